// round 2
// baseline (speedup 1.0000x reference)
#include <cuda_runtime.h>

// ---------------- problem constants ----------------
#define BATCH 4
#define NQ    4096
#define NK    1024
#define NH    16
#define HD    64
#define QD    1024   // QUERY_DIM
#define KD    768    // KEY_DIM
#define ATT_SCALE 0.125f  // 64^-0.5

// ---------------- scratch (device globals, no allocation) ----------------
__device__ float g_Qp[(size_t)BATCH * NQ * QD];  // projected Q  [B*Nq, 1024]
__device__ float g_Kp[(size_t)BATCH * NK * QD];  // projected K  [B*Nk, 1024]
__device__ float g_Vp[(size_t)BATCH * NK * QD];  // projected V  [B*Nk, 1024]
__device__ float g_AO[(size_t)BATCH * NQ * QD];  // attention out [B*Nq, 1024]

// ============================================================
// Tiled SGEMM with fused bias: C[M,N] = A[M,K] @ B[K,N] + bias
// BM=128, BN=128, BK=16, 256 threads, 8x8 per thread.
// Requires M%128==0, N%128==0, K%16==0 (true for all our shapes).
// ============================================================
#define GBM 128
#define GBN 128
#define GBK 16

__global__ __launch_bounds__(256) void sgemm_bias(
    const float* __restrict__ A, const float* __restrict__ B,
    const float* __restrict__ bias, float* __restrict__ C,
    int M, int N, int K)
{
    __shared__ float As[GBK][GBM];   // transposed A tile
    __shared__ float Bs[GBK][GBN];

    const int t   = threadIdx.x;
    const int tx  = t & 15;          // 0..15
    const int ty  = t >> 4;          // 0..15
    const int row0 = blockIdx.y * GBM;
    const int col0 = blockIdx.x * GBN;

    // A-load mapping: thread handles rows (t>>2) and (t>>2)+64, k-quad (t&3)*4
    const int arow = t >> 2;
    const int ak4  = (t & 3) * 4;
    // B-load mapping: row t>>5 (and +8), col quad (t&31)*4
    const int brow = t >> 5;
    const int bc4  = (t & 31) * 4;

    const float* Aptr = A + (size_t)row0 * K;
    const float* Bptr = B + col0;

    float acc[8][8];
#pragma unroll
    for (int i = 0; i < 8; i++)
#pragma unroll
        for (int j = 0; j < 8; j++) acc[i][j] = 0.f;

    for (int kt = 0; kt < K; kt += GBK) {
#pragma unroll
        for (int rr = 0; rr < 2; rr++) {
            int r = arow + rr * 64;
            float4 av = *(const float4*)(Aptr + (size_t)r * K + kt + ak4);
            As[ak4 + 0][r] = av.x;
            As[ak4 + 1][r] = av.y;
            As[ak4 + 2][r] = av.z;
            As[ak4 + 3][r] = av.w;
        }
#pragma unroll
        for (int rr = 0; rr < 2; rr++) {
            int r = brow + rr * 8;
            float4 bv = *(const float4*)(Bptr + (size_t)(kt + r) * N + bc4);
            *(float4*)&Bs[r][bc4] = bv;
        }
        __syncthreads();

#pragma unroll
        for (int kk = 0; kk < GBK; kk++) {
            float ar[8], br[8];
            *(float4*)&ar[0] = *(const float4*)&As[kk][ty * 8];
            *(float4*)&ar[4] = *(const float4*)&As[kk][ty * 8 + 4];
            *(float4*)&br[0] = *(const float4*)&Bs[kk][tx * 8];
            *(float4*)&br[4] = *(const float4*)&Bs[kk][tx * 8 + 4];
#pragma unroll
            for (int i = 0; i < 8; i++)
#pragma unroll
                for (int j = 0; j < 8; j++)
                    acc[i][j] += ar[i] * br[j];
        }
        __syncthreads();
    }

#pragma unroll
    for (int i = 0; i < 8; i++) {
        int r = row0 + ty * 8 + i;
#pragma unroll
        for (int j = 0; j < 8; j += 4) {
            int c = col0 + tx * 8 + j;
            float4 o;
            o.x = acc[i][j + 0] + bias[c + 0];
            o.y = acc[i][j + 1] + bias[c + 1];
            o.z = acc[i][j + 2] + bias[c + 2];
            o.w = acc[i][j + 3] + bias[c + 3];
            *(float4*)&C[(size_t)r * N + c] = o;
        }
    }
}

// ============================================================
// Flash attention, fp32. One block = 64 q rows of one (b,h).
// 256 threads: thread t -> row r=t>>2, col-group cg=t&3 (16 cols).
// smem (dynamic): Qs[64][65], KP[64][68] (K^T, reused as P), Vs[64][64]
// ============================================================
#define QS_STRIDE 65
#define KP_STRIDE 68
#define VS_STRIDE 64
#define ATTN_SMEM_FLOATS (64 * QS_STRIDE + 64 * KP_STRIDE + 64 * VS_STRIDE)
#define ATTN_SMEM_BYTES  (ATTN_SMEM_FLOATS * 4)

__global__ __launch_bounds__(256) void attn_kernel(
    const float* __restrict__ Qp, const float* __restrict__ Kp,
    const float* __restrict__ Vp, float* __restrict__ AO)
{
    extern __shared__ float sm[];
    float* Qs = sm;                        // 64 x 65
    float* KP = sm + 64 * QS_STRIDE;       // 64 x 68  (K transposed, then P)
    float* Vs = KP + 64 * KP_STRIDE;       // 64 x 64

    const int t  = threadIdx.x;
    const int r  = t >> 2;                 // 0..63  (q row within tile)
    const int cg = t & 3;                  // col group: 16 cols each
    const int q0 = blockIdx.x * 64;
    const int h  = blockIdx.y;
    const int b  = blockIdx.z;

    const float* Qg = Qp + ((size_t)(b * NQ + q0)) * QD + h * HD;
    const float* Kg = Kp + ((size_t)(b * NK)) * QD + h * HD;
    const float* Vg = Vp + ((size_t)(b * NK)) * QD + h * HD;

    // ---- load Q tile (pre-scaled) ----
    {
        const int rr = t >> 2, dg = t & 3;
#pragma unroll
        for (int w = 0; w < 4; w++) {
            float4 qv = *(const float4*)(Qg + (size_t)rr * QD + dg * 16 + w * 4);
            float* q = &Qs[rr * QS_STRIDE + dg * 16 + w * 4];
            q[0] = qv.x * ATT_SCALE;
            q[1] = qv.y * ATT_SCALE;
            q[2] = qv.z * ATT_SCALE;
            q[3] = qv.w * ATT_SCALE;
        }
    }

    float m = -1e30f, l = 0.f;
    float acc[16];
#pragma unroll
    for (int j = 0; j < 16; j++) acc[j] = 0.f;

    for (int n0 = 0; n0 < NK; n0 += 64) {
        __syncthreads();   // previous iteration finished reading KP/Vs

        // ---- load K chunk (transposed) and V chunk ----
        {
            const int i = t >> 2, dg = t & 3;
#pragma unroll
            for (int w = 0; w < 4; w++) {
                int d = dg * 16 + w * 4;
                float4 kv = *(const float4*)(Kg + (size_t)(n0 + i) * QD + d);
                KP[(d + 0) * KP_STRIDE + i] = kv.x;
                KP[(d + 1) * KP_STRIDE + i] = kv.y;
                KP[(d + 2) * KP_STRIDE + i] = kv.z;
                KP[(d + 3) * KP_STRIDE + i] = kv.w;
                float4 vv = *(const float4*)(Vg + (size_t)(n0 + i) * QD + d);
                *(float4*)&Vs[i * VS_STRIDE + d] = vv;
            }
        }
        __syncthreads();

        // ---- S = Q K^T : 16 columns per thread ----
        float s[16];
#pragma unroll
        for (int j = 0; j < 16; j++) s[j] = 0.f;
#pragma unroll 8
        for (int d = 0; d < 64; d++) {
            float q = Qs[r * QS_STRIDE + d];
            float kv[16];
            *(float4*)&kv[0]  = *(const float4*)&KP[d * KP_STRIDE + cg * 16 + 0];
            *(float4*)&kv[4]  = *(const float4*)&KP[d * KP_STRIDE + cg * 16 + 4];
            *(float4*)&kv[8]  = *(const float4*)&KP[d * KP_STRIDE + cg * 16 + 8];
            *(float4*)&kv[12] = *(const float4*)&KP[d * KP_STRIDE + cg * 16 + 12];
#pragma unroll
            for (int j = 0; j < 16; j++) s[j] += q * kv[j];
        }

        // ---- online softmax update (4 threads per row, same warp quad) ----
        float cmax = s[0];
#pragma unroll
        for (int j = 1; j < 16; j++) cmax = fmaxf(cmax, s[j]);
        cmax = fmaxf(cmax, __shfl_xor_sync(0xffffffffu, cmax, 1));
        cmax = fmaxf(cmax, __shfl_xor_sync(0xffffffffu, cmax, 2));
        float mnew = fmaxf(m, cmax);
        float psum = 0.f;
#pragma unroll
        for (int j = 0; j < 16; j++) {
            s[j] = __expf(s[j] - mnew);
            psum += s[j];
        }
        psum += __shfl_xor_sync(0xffffffffu, psum, 1);
        psum += __shfl_xor_sync(0xffffffffu, psum, 2);
        float alpha = __expf(m - mnew);
        l = l * alpha + psum;
#pragma unroll
        for (int j = 0; j < 16; j++) acc[j] *= alpha;
        m = mnew;

        __syncthreads();   // everyone done reading KP as K^T

        // ---- stage P into KP ----
        *(float4*)&KP[r * KP_STRIDE + cg * 16 + 0]  = make_float4(s[0],  s[1],  s[2],  s[3]);
        *(float4*)&KP[r * KP_STRIDE + cg * 16 + 4]  = make_float4(s[4],  s[5],  s[6],  s[7]);
        *(float4*)&KP[r * KP_STRIDE + cg * 16 + 8]  = make_float4(s[8],  s[9],  s[10], s[11]);
        *(float4*)&KP[r * KP_STRIDE + cg * 16 + 12] = make_float4(s[12], s[13], s[14], s[15]);
        __syncthreads();

        // ---- O += P @ V : 16 output dims per thread ----
#pragma unroll 8
        for (int kk = 0; kk < 64; kk++) {
            float p = KP[r * KP_STRIDE + kk];
            float vv[16];
            *(float4*)&vv[0]  = *(const float4*)&Vs[kk * VS_STRIDE + cg * 16 + 0];
            *(float4*)&vv[4]  = *(const float4*)&Vs[kk * VS_STRIDE + cg * 16 + 4];
            *(float4*)&vv[8]  = *(const float4*)&Vs[kk * VS_STRIDE + cg * 16 + 8];
            *(float4*)&vv[12] = *(const float4*)&Vs[kk * VS_STRIDE + cg * 16 + 12];
#pragma unroll
            for (int j = 0; j < 16; j++) acc[j] += p * vv[j];
        }
    }

    const float inv = 1.0f / l;
    float* Og = AO + ((size_t)(b * NQ + q0 + r)) * QD + h * HD + cg * 16;
    *(float4*)&Og[0]  = make_float4(acc[0]*inv,  acc[1]*inv,  acc[2]*inv,  acc[3]*inv);
    *(float4*)&Og[4]  = make_float4(acc[4]*inv,  acc[5]*inv,  acc[6]*inv,  acc[7]*inv);
    *(float4*)&Og[8]  = make_float4(acc[8]*inv,  acc[9]*inv,  acc[10]*inv, acc[11]*inv);
    *(float4*)&Og[12] = make_float4(acc[12]*inv, acc[13]*inv, acc[14]*inv, acc[15]*inv);
}

// ============================================================
// kernel_launch: 5 kernels on the default stream.
// ============================================================
extern "C" void kernel_launch(void* const* d_in, const int* in_sizes, int n_in,
                              void* d_out, int out_size)
{
    const float* query = (const float*)d_in[0];
    const float* key   = (const float*)d_in[1];
    const float* value = (const float*)d_in[2];
    const float* Wq    = (const float*)d_in[3];
    const float* bq    = (const float*)d_in[4];
    const float* Wk    = (const float*)d_in[5];
    const float* bk    = (const float*)d_in[6];
    const float* Wv    = (const float*)d_in[7];
    const float* bv    = (const float*)d_in[8];
    const float* Wo    = (const float*)d_in[9];
    const float* bo    = (const float*)d_in[10];
    float* out = (float*)d_out;

    float *Qp, *Kp, *Vp, *AO;
    cudaGetSymbolAddress((void**)&Qp, g_Qp);
    cudaGetSymbolAddress((void**)&Kp, g_Kp);
    cudaGetSymbolAddress((void**)&Vp, g_Vp);
    cudaGetSymbolAddress((void**)&AO, g_AO);

    cudaFuncSetAttribute(attn_kernel,
                         cudaFuncAttributeMaxDynamicSharedMemorySize,
                         ATTN_SMEM_BYTES);

    dim3 blk(256);

    // Q projection: [16384,1024] x [1024,1024]
    sgemm_bias<<<dim3(QD / GBN, (BATCH * NQ) / GBM), blk>>>(
        query, Wq, bq, Qp, BATCH * NQ, QD, QD);
    // K projection: [4096,768] x [768,1024]
    sgemm_bias<<<dim3(QD / GBN, (BATCH * NK) / GBM), blk>>>(
        key, Wk, bk, Kp, BATCH * NK, QD, KD);
    // V projection
    sgemm_bias<<<dim3(QD / GBN, (BATCH * NK) / GBM), blk>>>(
        value, Wv, bv, Vp, BATCH * NK, QD, KD);

    // attention: grid (Nq/64, heads, batch)
    attn_kernel<<<dim3(NQ / 64, NH, BATCH), blk, ATTN_SMEM_BYTES>>>(Qp, Kp, Vp, AO);

    // output projection: [16384,1024] x [1024,1024] -> d_out
    sgemm_bias<<<dim3(QD / GBN, (BATCH * NQ) / GBM), blk>>>(
        AO, Wo, bo, out, BATCH * NQ, QD, QD);
}

// round 4
// speedup vs baseline: 3.6622x; 3.6622x over previous
#include <cuda_runtime.h>
#include <cuda_bf16.h>
#include <cstdint>

#define BATCH 4
#define NQ    4096
#define NK    1024
#define NH    16
#define HD    64
#define QD    1024
#define KD    768
#define ATT_SCALE 0.125f

// ---------------- helpers ----------------
__device__ __forceinline__ uint32_t smem_u32(const void* p) {
    uint32_t a;
    asm("{ .reg .u64 t; cvta.to.shared.u64 t, %1; cvt.u32.u64 %0, t; }" : "=r"(a) : "l"(p));
    return a;
}
__device__ __forceinline__ void cpa16(uint32_t s, const void* g) {
    asm volatile("cp.async.cg.shared.global [%0], [%1], 16;" :: "r"(s), "l"(g));
}
__device__ __forceinline__ void ldsm4(uint32_t* r, uint32_t a) {
    asm volatile("ldmatrix.sync.aligned.m8n8.x4.shared.b16 {%0,%1,%2,%3}, [%4];"
        : "=r"(r[0]), "=r"(r[1]), "=r"(r[2]), "=r"(r[3]) : "r"(a));
}
__device__ __forceinline__ void mma16816(float* d, const uint32_t* a, const uint32_t* b) {
    asm volatile("mma.sync.aligned.m16n8k16.row.col.f32.bf16.bf16.f32 "
        "{%0,%1,%2,%3}, {%4,%5,%6,%7}, {%8,%9}, {%0,%1,%2,%3};"
        : "+f"(d[0]), "+f"(d[1]), "+f"(d[2]), "+f"(d[3])
        : "r"(a[0]), "r"(a[1]), "r"(a[2]), "r"(a[3]), "r"(b[0]), "r"(b[1]));
}
// swizzled byte offset within a [128][32]bf16 tile (64B rows): conflict-free ldmatrix
__device__ __forceinline__ uint32_t soff(int row, int chunk) {
    return (uint32_t)(row * 64 + ((chunk ^ ((row >> 1) & 3)) << 4));
}

// ---------------- scratch ----------------
#define AL16 __align__(16)
__device__ AL16 __nv_bfloat16 g_qh[(size_t)BATCH*NQ*QD], g_ql[(size_t)BATCH*NQ*QD];
__device__ AL16 __nv_bfloat16 g_kh[(size_t)BATCH*NK*KD], g_kl[(size_t)BATCH*NK*KD];
__device__ AL16 __nv_bfloat16 g_vh[(size_t)BATCH*NK*KD], g_vl[(size_t)BATCH*NK*KD];
__device__ AL16 __nv_bfloat16 g_aoh[(size_t)BATCH*NQ*QD], g_aol[(size_t)BATCH*NQ*QD];
__device__ AL16 __nv_bfloat16 g_wqh[(size_t)QD*QD], g_wql[(size_t)QD*QD];
__device__ AL16 __nv_bfloat16 g_wkh[(size_t)QD*KD], g_wkl[(size_t)QD*KD];
__device__ AL16 __nv_bfloat16 g_wvh[(size_t)QD*KD], g_wvl[(size_t)QD*KD];
__device__ AL16 __nv_bfloat16 g_woh[(size_t)QD*QD], g_wol[(size_t)QD*QD];
__device__ AL16 float g_Qp[(size_t)BATCH*NQ*QD];
__device__ AL16 float g_Kp[(size_t)BATCH*NK*QD];
__device__ AL16 float g_Vp[(size_t)BATCH*NK*QD];
__device__ AL16 float g_AO[(size_t)BATCH*NQ*QD];

// ============ split fp32 -> bf16 hi/lo ============
__global__ __launch_bounds__(256) void split_f32(
    const float* __restrict__ x, __nv_bfloat16* __restrict__ hi,
    __nv_bfloat16* __restrict__ lo, int n4)
{
    int i = blockIdx.x * 256 + threadIdx.x;
    if (i >= n4) return;
    float4 v = ((const float4*)x)[i];
    __nv_bfloat16 h0 = __float2bfloat16_rn(v.x), h1 = __float2bfloat16_rn(v.y);
    __nv_bfloat16 h2 = __float2bfloat16_rn(v.z), h3 = __float2bfloat16_rn(v.w);
    __nv_bfloat162 a, b, c, d;
    a.x = h0; a.y = h1; b.x = h2; b.y = h3;
    c.x = __float2bfloat16_rn(v.x - __bfloat162float(h0));
    c.y = __float2bfloat16_rn(v.y - __bfloat162float(h1));
    d.x = __float2bfloat16_rn(v.z - __bfloat162float(h2));
    d.y = __float2bfloat16_rn(v.w - __bfloat162float(h3));
    ((__nv_bfloat162*)hi)[2*i] = a; ((__nv_bfloat162*)hi)[2*i+1] = b;
    ((__nv_bfloat162*)lo)[2*i] = c; ((__nv_bfloat162*)lo)[2*i+1] = d;
}

// ============ transpose + split: W[K,N] -> [N,K] hi/lo ============
__global__ __launch_bounds__(256) void wsplit_t(
    const float* __restrict__ W, __nv_bfloat16* __restrict__ Th,
    __nv_bfloat16* __restrict__ Tl, int K, int N)
{
    __shared__ float tile[32][33];
    const int nb = blockIdx.x * 32, kb = blockIdx.y * 32;
    const int tx = threadIdx.x & 31, tg = threadIdx.x >> 5;
#pragma unroll
    for (int r = 0; r < 4; r++) {
        int k = tg + r * 8;
        tile[k][tx] = W[(size_t)(kb + k) * N + nb + tx];
    }
    __syncthreads();
#pragma unroll
    for (int r = 0; r < 4; r++) {
        int n = tg + r * 8;
        float v = tile[tx][n];
        __nv_bfloat16 h = __float2bfloat16_rn(v);
        Th[(size_t)(nb + n) * K + kb + tx] = h;
        Tl[(size_t)(nb + n) * K + kb + tx] = __float2bfloat16_rn(v - __bfloat162float(h));
    }
}

// ============ mma.sync GEMM: C[M,N] = (Ah+Al)[M,K] @ (Bh+Bl)[N,K]^T + bias ============
// CTA 128x128, K-chunk 32, 8 warps (64x32 each), 2-stage cp.async pipeline.
#define TA_H 0
#define TA_L 8192
#define TB_H 16384
#define TB_L 24576
#define STG  32768
#define GEMM_SMEM (2 * STG)

__global__ __launch_bounds__(256, 1) void gemm_mma(
    const __nv_bfloat16* __restrict__ Ah, const __nv_bfloat16* __restrict__ Al,
    const __nv_bfloat16* __restrict__ Bh, const __nv_bfloat16* __restrict__ Bl,
    const float* __restrict__ bias, float* __restrict__ C, int M, int N, int K)
{
    extern __shared__ char sm[];
    const uint32_t smb = smem_u32(sm);
    const int t = threadIdx.x, wid = t >> 5, lane = t & 31;
    const int m0 = blockIdx.y * 128, n0 = blockIdx.x * 128;
    const int NC = K >> 5;
    const int wm = (wid & 1) * 64, wn = (wid >> 1) * 32;

    const int lrow = t >> 1;            // 0..127
    const int lch0 = (t & 1) * 2;       // 0 or 2

    auto load_stage = [&](int c, int s) {
        const int kt = c << 5;
        const uint32_t sb = smb + s * STG;
#pragma unroll
        for (int j = 0; j < 2; j++) {
            int ch = lch0 + j;
            uint32_t so = soff(lrow, ch);
            size_t ga = (size_t)(m0 + lrow) * K + kt + ch * 8;
            size_t gb = (size_t)(n0 + lrow) * K + kt + ch * 8;
            cpa16(sb + TA_H + so, Ah + ga);
            cpa16(sb + TA_L + so, Al + ga);
            cpa16(sb + TB_H + so, Bh + gb);
            cpa16(sb + TB_L + so, Bl + gb);
        }
        asm volatile("cp.async.commit_group;" ::: "memory");
    };

    float d[4][4][4];
#pragma unroll
    for (int i = 0; i < 4; i++)
#pragma unroll
        for (int j = 0; j < 4; j++)
#pragma unroll
            for (int k = 0; k < 4; k++) d[i][j][k] = 0.f;

    load_stage(0, 0);

    for (int c = 0; c < NC; c++) {
        const int s = c & 1;
        if (c + 1 < NC) {
            load_stage(c + 1, s ^ 1);
            asm volatile("cp.async.wait_group 1;" ::: "memory");
        } else {
            asm volatile("cp.async.wait_group 0;" ::: "memory");
        }
        __syncthreads();

        const uint32_t sb = smb + s * STG;
#pragma unroll
        for (int ks = 0; ks < 2; ks++) {
            const int kc = ks * 2;  // base k-chunk (8 bf16 per chunk)
            uint32_t ahf[4][4], alf[4][4];
#pragma unroll
            for (int mt = 0; mt < 4; mt++) {
                int row = wm + mt * 16 + (lane & 15);
                int ch = kc + (lane >> 4);
                uint32_t so = soff(row, ch);
                ldsm4(ahf[mt], sb + TA_H + so);
                ldsm4(alf[mt], sb + TA_L + so);
            }
            uint32_t bhf[4][2], blf[4][2];
#pragma unroll
            for (int p = 0; p < 2; p++) {
                int nrow = wn + p * 16 + ((lane >> 4) & 1) * 8 + (lane & 7);
                int ch = kc + ((lane >> 3) & 1);
                uint32_t so = soff(nrow, ch);
                uint32_t r[4];
                ldsm4(r, sb + TB_H + so);
                bhf[p*2][0] = r[0]; bhf[p*2][1] = r[1];
                bhf[p*2+1][0] = r[2]; bhf[p*2+1][1] = r[3];
                ldsm4(r, sb + TB_L + so);
                blf[p*2][0] = r[0]; blf[p*2][1] = r[1];
                blf[p*2+1][0] = r[2]; blf[p*2+1][1] = r[3];
            }
#pragma unroll
            for (int mt = 0; mt < 4; mt++)
#pragma unroll
                for (int nt = 0; nt < 4; nt++) {
                    mma16816(d[mt][nt], ahf[mt], bhf[nt]);
                    mma16816(d[mt][nt], alf[mt], bhf[nt]);
                    mma16816(d[mt][nt], ahf[mt], blf[nt]);
                }
        }
        __syncthreads();
    }

    // epilogue
    const int lr = lane >> 2, lc = (lane & 3) * 2;
#pragma unroll
    for (int mt = 0; mt < 4; mt++) {
        int row = m0 + wm + mt * 16 + lr;
#pragma unroll
        for (int nt = 0; nt < 4; nt++) {
            int col = n0 + wn + nt * 8 + lc;
            float b0 = __ldg(bias + col), b1 = __ldg(bias + col + 1);
            float2 v0 = make_float2(d[mt][nt][0] + b0, d[mt][nt][1] + b1);
            float2 v1 = make_float2(d[mt][nt][2] + b0, d[mt][nt][3] + b1);
            *(float2*)&C[(size_t)row * N + col] = v0;
            *(float2*)&C[(size_t)(row + 8) * N + col] = v1;
        }
    }
}

// ============ flash attention fp32, 8x8 microkernel ============
#define QT_S 132
#define ATTN_SMEM ((64*QT_S + 64*QT_S + 128*QT_S + 128*64) * 4)

__global__ __launch_bounds__(256, 1) void attn2(
    const float* __restrict__ Qp, const float* __restrict__ Kp,
    const float* __restrict__ Vp, float* __restrict__ AO)
{
    extern __shared__ float smf[];
    float* Qt = smf;                 // [64 d][132] q-cols
    float* Kt = Qt + 64 * QT_S;      // [64 d][132] kv-cols
    float* Ps = Kt + 64 * QT_S;      // [128 q][132] kv-cols
    float* Vs = Ps + 128 * QT_S;     // [128 kv][64 d]

    const int t = threadIdx.x, tx = t & 15, ty = t >> 4;
    const int q0 = blockIdx.x * 128, h = blockIdx.y, b = blockIdx.z;

    const float* Qg = Qp + ((size_t)(b * NQ + q0)) * QD + h * HD;
    const float* Kg = Kp + ((size_t)b * NK) * QD + h * HD;
    const float* Vg = Vp + ((size_t)b * NK) * QD + h * HD;

#pragma unroll
    for (int i = 0; i < 8; i++) {
        int u = t + i * 256;
        int q = u >> 4, d4 = (u & 15) * 4;
        float4 v = *(const float4*)(Qg + (size_t)q * QD + d4);
        Qt[(d4+0)*QT_S + q] = v.x * ATT_SCALE;
        Qt[(d4+1)*QT_S + q] = v.y * ATT_SCALE;
        Qt[(d4+2)*QT_S + q] = v.z * ATT_SCALE;
        Qt[(d4+3)*QT_S + q] = v.w * ATT_SCALE;
    }

    float m[8], l[8], acc[8][4];
#pragma unroll
    for (int i = 0; i < 8; i++) {
        m[i] = -1e30f; l[i] = 0.f;
        acc[i][0] = acc[i][1] = acc[i][2] = acc[i][3] = 0.f;
    }

    for (int n0 = 0; n0 < NK; n0 += 128) {
        __syncthreads();
#pragma unroll
        for (int i = 0; i < 8; i++) {
            int u = t + i * 256;
            int kv = u >> 4, d4 = (u & 15) * 4;
            float4 kvec = *(const float4*)(Kg + (size_t)(n0 + kv) * QD + d4);
            Kt[(d4+0)*QT_S + kv] = kvec.x;
            Kt[(d4+1)*QT_S + kv] = kvec.y;
            Kt[(d4+2)*QT_S + kv] = kvec.z;
            Kt[(d4+3)*QT_S + kv] = kvec.w;
            *(float4*)&Vs[kv * 64 + d4] = *(const float4*)(Vg + (size_t)(n0 + kv) * QD + d4);
        }
        __syncthreads();

        float s[8][8];
#pragma unroll
        for (int i = 0; i < 8; i++)
#pragma unroll
            for (int j = 0; j < 8; j++) s[i][j] = 0.f;
#pragma unroll 4
        for (int k = 0; k < 64; k++) {
            float a[8], bb[8];
            *(float4*)&a[0]  = *(const float4*)&Qt[k*QT_S + ty*8];
            *(float4*)&a[4]  = *(const float4*)&Qt[k*QT_S + ty*8 + 4];
            *(float4*)&bb[0] = *(const float4*)&Kt[k*QT_S + tx*8];
            *(float4*)&bb[4] = *(const float4*)&Kt[k*QT_S + tx*8 + 4];
#pragma unroll
            for (int i = 0; i < 8; i++)
#pragma unroll
                for (int j = 0; j < 8; j++) s[i][j] += a[i] * bb[j];
        }

#pragma unroll
        for (int i = 0; i < 8; i++) {
            float cm = s[i][0];
#pragma unroll
            for (int j = 1; j < 8; j++) cm = fmaxf(cm, s[i][j]);
            cm = fmaxf(cm, __shfl_xor_sync(0xffffffffu, cm, 1));
            cm = fmaxf(cm, __shfl_xor_sync(0xffffffffu, cm, 2));
            cm = fmaxf(cm, __shfl_xor_sync(0xffffffffu, cm, 4));
            cm = fmaxf(cm, __shfl_xor_sync(0xffffffffu, cm, 8));
            float mn = fmaxf(m[i], cm), ps = 0.f;
#pragma unroll
            for (int j = 0; j < 8; j++) { s[i][j] = __expf(s[i][j] - mn); ps += s[i][j]; }
            ps += __shfl_xor_sync(0xffffffffu, ps, 1);
            ps += __shfl_xor_sync(0xffffffffu, ps, 2);
            ps += __shfl_xor_sync(0xffffffffu, ps, 4);
            ps += __shfl_xor_sync(0xffffffffu, ps, 8);
            float al = __expf(m[i] - mn);
            l[i] = l[i] * al + ps;
            acc[i][0] *= al; acc[i][1] *= al; acc[i][2] *= al; acc[i][3] *= al;
            m[i] = mn;
            *(float4*)&Ps[(ty*8+i)*QT_S + tx*8]     = make_float4(s[i][0], s[i][1], s[i][2], s[i][3]);
            *(float4*)&Ps[(ty*8+i)*QT_S + tx*8 + 4] = make_float4(s[i][4], s[i][5], s[i][6], s[i][7]);
        }
        __syncthreads();

#pragma unroll 2
        for (int kk4 = 0; kk4 < 32; kk4++) {
            float4 vv[4];
#pragma unroll
            for (int j = 0; j < 4; j++)
                vv[j] = *(const float4*)&Vs[(kk4*4+j)*64 + tx*4];
#pragma unroll
            for (int i = 0; i < 8; i++) {
                float4 p = *(const float4*)&Ps[(ty*8+i)*QT_S + kk4*4];
                acc[i][0] += p.x*vv[0].x + p.y*vv[1].x + p.z*vv[2].x + p.w*vv[3].x;
                acc[i][1] += p.x*vv[0].y + p.y*vv[1].y + p.z*vv[2].y + p.w*vv[3].y;
                acc[i][2] += p.x*vv[0].z + p.y*vv[1].z + p.z*vv[2].z + p.w*vv[3].z;
                acc[i][3] += p.x*vv[0].w + p.y*vv[1].w + p.z*vv[2].w + p.w*vv[3].w;
            }
        }
    }

#pragma unroll
    for (int i = 0; i < 8; i++) {
        float inv = 1.0f / l[i];
        float* Og = AO + ((size_t)(b * NQ + q0 + ty*8 + i)) * QD + h * HD + tx * 4;
        *(float4*)Og = make_float4(acc[i][0]*inv, acc[i][1]*inv, acc[i][2]*inv, acc[i][3]*inv);
    }
}

// ============ kernel_launch ============
extern "C" void kernel_launch(void* const* d_in, const int* in_sizes, int n_in,
                              void* d_out, int out_size)
{
    const float* query = (const float*)d_in[0];
    const float* key   = (const float*)d_in[1];
    const float* value = (const float*)d_in[2];
    const float* Wq = (const float*)d_in[3];  const float* bq = (const float*)d_in[4];
    const float* Wk = (const float*)d_in[5];  const float* bk = (const float*)d_in[6];
    const float* Wv = (const float*)d_in[7];  const float* bv = (const float*)d_in[8];
    const float* Wo = (const float*)d_in[9];  const float* bo = (const float*)d_in[10];
    float* out = (float*)d_out;

    __nv_bfloat16 *qh,*ql,*kh,*kl,*vh,*vl,*aoh,*aol;
    __nv_bfloat16 *wqh,*wql,*wkh,*wkl,*wvh,*wvl,*woh,*wol;
    float *Qp,*Kp,*Vp,*AO;
    cudaGetSymbolAddress((void**)&qh, g_qh);   cudaGetSymbolAddress((void**)&ql, g_ql);
    cudaGetSymbolAddress((void**)&kh, g_kh);   cudaGetSymbolAddress((void**)&kl, g_kl);
    cudaGetSymbolAddress((void**)&vh, g_vh);   cudaGetSymbolAddress((void**)&vl, g_vl);
    cudaGetSymbolAddress((void**)&aoh, g_aoh); cudaGetSymbolAddress((void**)&aol, g_aol);
    cudaGetSymbolAddress((void**)&wqh, g_wqh); cudaGetSymbolAddress((void**)&wql, g_wql);
    cudaGetSymbolAddress((void**)&wkh, g_wkh); cudaGetSymbolAddress((void**)&wkl, g_wkl);
    cudaGetSymbolAddress((void**)&wvh, g_wvh); cudaGetSymbolAddress((void**)&wvl, g_wvl);
    cudaGetSymbolAddress((void**)&woh, g_woh); cudaGetSymbolAddress((void**)&wol, g_wol);
    cudaGetSymbolAddress((void**)&Qp, g_Qp);   cudaGetSymbolAddress((void**)&Kp, g_Kp);
    cudaGetSymbolAddress((void**)&Vp, g_Vp);   cudaGetSymbolAddress((void**)&AO, g_AO);

    cudaFuncSetAttribute(gemm_mma, cudaFuncAttributeMaxDynamicSharedMemorySize, GEMM_SMEM);
    cudaFuncSetAttribute(attn2,    cudaFuncAttributeMaxDynamicSharedMemorySize, ATTN_SMEM);

    const int MQ = BATCH * NQ;   // 16384
    const int MK = BATCH * NK;   // 4096

    split_f32<<<(MQ*QD/4 + 255)/256, 256>>>(query, qh, ql, MQ*QD/4);
    split_f32<<<(MK*KD/4 + 255)/256, 256>>>(key,   kh, kl, MK*KD/4);
    split_f32<<<(MK*KD/4 + 255)/256, 256>>>(value, vh, vl, MK*KD/4);
    wsplit_t<<<dim3(QD/32, QD/32), 256>>>(Wq, wqh, wql, QD, QD);
    wsplit_t<<<dim3(QD/32, KD/32), 256>>>(Wk, wkh, wkl, KD, QD);
    wsplit_t<<<dim3(QD/32, KD/32), 256>>>(Wv, wvh, wvl, KD, QD);
    wsplit_t<<<dim3(QD/32, QD/32), 256>>>(Wo, woh, wol, QD, QD);

    gemm_mma<<<dim3(QD/128, MQ/128), 256, GEMM_SMEM>>>(qh, ql, wqh, wql, bq, Qp, MQ, QD, QD);
    gemm_mma<<<dim3(QD/128, MK/128), 256, GEMM_SMEM>>>(kh, kl, wkh, wkl, bk, Kp, MK, QD, KD);
    gemm_mma<<<dim3(QD/128, MK/128), 256, GEMM_SMEM>>>(vh, vl, wvh, wvl, bv, Vp, MK, QD, KD);

    attn2<<<dim3(NQ/128, NH, BATCH), 256, ATTN_SMEM>>>(Qp, Kp, Vp, AO);

    split_f32<<<(MQ*QD/4 + 255)/256, 256>>>(AO, aoh, aol, MQ*QD/4);
    gemm_mma<<<dim3(QD/128, MQ/128), 256, GEMM_SMEM>>>(aoh, aol, woh, wol, bo, out, MQ, QD, QD);
}

// round 5
// speedup vs baseline: 6.7250x; 1.8363x over previous
#include <cuda_runtime.h>
#include <cuda_bf16.h>
#include <cstdint>

#define BATCH 4
#define NQ    4096
#define NK    1024
#define NH    16
#define HD    64
#define QD    1024
#define KD    768
// scale folded into Q projection: 0.125 * log2(e)
#define QSCALE 0.1803368801f

// ---------------- helpers ----------------
__device__ __forceinline__ uint32_t smem_u32(const void* p) {
    uint32_t a;
    asm("{ .reg .u64 t; cvta.to.shared.u64 t, %1; cvt.u32.u64 %0, t; }" : "=r"(a) : "l"(p));
    return a;
}
__device__ __forceinline__ void cpa16(uint32_t s, const void* g) {
    asm volatile("cp.async.cg.shared.global [%0], [%1], 16;" :: "r"(s), "l"(g));
}
#define CP_COMMIT() asm volatile("cp.async.commit_group;" ::: "memory")
#define CP_WAIT(n)  asm volatile("cp.async.wait_group %0;" :: "n"(n) : "memory")
__device__ __forceinline__ void ldsm4(uint32_t* r, uint32_t a) {
    asm volatile("ldmatrix.sync.aligned.m8n8.x4.shared.b16 {%0,%1,%2,%3}, [%4];"
        : "=r"(r[0]), "=r"(r[1]), "=r"(r[2]), "=r"(r[3]) : "r"(a));
}
__device__ __forceinline__ void ldsm4t(uint32_t* r, uint32_t a) {
    asm volatile("ldmatrix.sync.aligned.m8n8.x4.trans.shared.b16 {%0,%1,%2,%3}, [%4];"
        : "=r"(r[0]), "=r"(r[1]), "=r"(r[2]), "=r"(r[3]) : "r"(a));
}
__device__ __forceinline__ void mma16816(float* d, const uint32_t* a, const uint32_t* b) {
    asm volatile("mma.sync.aligned.m16n8k16.row.col.f32.bf16.bf16.f32 "
        "{%0,%1,%2,%3}, {%4,%5,%6,%7}, {%8,%9}, {%0,%1,%2,%3};"
        : "+f"(d[0]), "+f"(d[1]), "+f"(d[2]), "+f"(d[3])
        : "r"(a[0]), "r"(a[1]), "r"(a[2]), "r"(a[3]), "r"(b[0]), "r"(b[1]));
}
__device__ __forceinline__ uint32_t packbf(float hi, float lo) {
    uint32_t r;
    asm("cvt.rn.bf16x2.f32 %0, %1, %2;" : "=r"(r) : "f"(hi), "f"(lo));
    return r;
}
// swizzled offset in [rows][32]bf16 (64B rows, 4 chunks)
__device__ __forceinline__ uint32_t soff(int row, int chunk) {
    return (uint32_t)(row * 64 + ((chunk ^ ((row >> 1) & 3)) << 4));
}
// swizzled offset in [rows][64]bf16 (128B rows, 8 chunks)
__device__ __forceinline__ uint32_t soff64(int row, int ch) {
    return (uint32_t)(row * 128 + ((ch ^ (row & 7)) << 4));
}
// 2^z via deg-6 poly + exponent injection (no MUFU)
__device__ __forceinline__ float fexp2(float z) {
    z = fmaxf(z, -60.f);
    float fi = floorf(z);
    float f = z - fi;
    float p = 1.54035e-4f;
    p = fmaf(p, f, 1.33336e-3f);
    p = fmaf(p, f, 9.61813e-3f);
    p = fmaf(p, f, 5.55041e-2f);
    p = fmaf(p, f, 2.40227e-1f);
    p = fmaf(p, f, 6.9314718e-1f);
    p = fmaf(p, f, 1.0f);
    int i = (int)fi;
    return __int_as_float(__float_as_int(p) + (i << 23));
}

// ---------------- scratch ----------------
#define AL16 __align__(16)
// input splits
__device__ AL16 __nv_bfloat16 g_qh[(size_t)BATCH*NQ*QD], g_ql[(size_t)BATCH*NQ*QD];
__device__ AL16 __nv_bfloat16 g_kh[(size_t)BATCH*NK*KD], g_kl[(size_t)BATCH*NK*KD];
__device__ AL16 __nv_bfloat16 g_vh[(size_t)BATCH*NK*KD], g_vl[(size_t)BATCH*NK*KD];
// weight splits (transposed [N,K])
__device__ AL16 __nv_bfloat16 g_wqh[(size_t)QD*QD], g_wql[(size_t)QD*QD];
__device__ AL16 __nv_bfloat16 g_wkh[(size_t)QD*KD], g_wkl[(size_t)QD*KD];
__device__ AL16 __nv_bfloat16 g_wvh[(size_t)QD*KD], g_wvl[(size_t)QD*KD];
__device__ AL16 __nv_bfloat16 g_woh[(size_t)QD*QD], g_wol[(size_t)QD*QD];
// projected hi/lo
__device__ AL16 __nv_bfloat16 g_Qh[(size_t)BATCH*NQ*QD], g_Ql[(size_t)BATCH*NQ*QD];
__device__ AL16 __nv_bfloat16 g_Kh[(size_t)BATCH*NK*QD], g_Kl[(size_t)BATCH*NK*QD];
__device__ AL16 __nv_bfloat16 g_Vh[(size_t)BATCH*NK*QD], g_Vl[(size_t)BATCH*NK*QD];
// attention out hi/lo
__device__ AL16 __nv_bfloat16 g_aoh[(size_t)BATCH*NQ*QD], g_aol[(size_t)BATCH*NQ*QD];

// ============ split fp32 -> bf16 hi/lo ============
__global__ __launch_bounds__(256) void split_f32(
    const float* __restrict__ x, __nv_bfloat16* __restrict__ hi,
    __nv_bfloat16* __restrict__ lo, int n4)
{
    int i = blockIdx.x * 256 + threadIdx.x;
    if (i >= n4) return;
    float4 v = ((const float4*)x)[i];
    uint32_t h01 = packbf(v.y, v.x), h23 = packbf(v.w, v.z);
    ((uint32_t*)hi)[2*i] = h01; ((uint32_t*)hi)[2*i+1] = h23;
    float l0 = v.x - __uint_as_float(h01 << 16);
    float l1 = v.y - __uint_as_float(h01 & 0xFFFF0000u);
    float l2 = v.z - __uint_as_float(h23 << 16);
    float l3 = v.w - __uint_as_float(h23 & 0xFFFF0000u);
    ((uint32_t*)lo)[2*i] = packbf(l1, l0); ((uint32_t*)lo)[2*i+1] = packbf(l3, l2);
}

// ============ transpose + split: W[K,N] -> [N,K] hi/lo ============
__global__ __launch_bounds__(256) void wsplit_t(
    const float* __restrict__ W, __nv_bfloat16* __restrict__ Th,
    __nv_bfloat16* __restrict__ Tl, int K, int N)
{
    __shared__ float tile[32][33];
    const int nb = blockIdx.x * 32, kb = blockIdx.y * 32;
    const int tx = threadIdx.x & 31, tg = threadIdx.x >> 5;
#pragma unroll
    for (int r = 0; r < 4; r++) {
        int k = tg + r * 8;
        tile[k][tx] = W[(size_t)(kb + k) * N + nb + tx];
    }
    __syncthreads();
#pragma unroll
    for (int r = 0; r < 4; r++) {
        int n = tg + r * 8;
        float v = tile[tx][n];
        __nv_bfloat16 h = __float2bfloat16_rn(v);
        Th[(size_t)(nb + n) * K + kb + tx] = h;
        Tl[(size_t)(nb + n) * K + kb + tx] = __float2bfloat16_rn(v - __bfloat162float(h));
    }
}

// ============ mma.sync GEMM: (Ah+Al)[M,K] @ (Bh+Bl)[N,K]^T + bias, then *scale ============
// Output: fp32 (Cf) OR bf16 hi/lo (Ch, Cl). CTA 128x128, K-chunk 32, 8 warps.
#define TA_H 0
#define TA_L 8192
#define TB_H 16384
#define TB_L 24576
#define STG  32768
#define GEMM_SMEM (2 * STG)

__global__ __launch_bounds__(256, 1) void gemm_mma(
    const __nv_bfloat16* __restrict__ Ah, const __nv_bfloat16* __restrict__ Al,
    const __nv_bfloat16* __restrict__ Bh, const __nv_bfloat16* __restrict__ Bl,
    const float* __restrict__ bias, float* __restrict__ Cf,
    __nv_bfloat16* __restrict__ Ch, __nv_bfloat16* __restrict__ Cl,
    float scale, int M, int N, int K)
{
    extern __shared__ char sm[];
    const uint32_t smb = smem_u32(sm);
    const int t = threadIdx.x, wid = t >> 5, lane = t & 31;
    const int m0 = blockIdx.y * 128, n0 = blockIdx.x * 128;
    const int NC = K >> 5;
    const int wm = (wid & 1) * 64, wn = (wid >> 1) * 32;
    const int lrow = t >> 1;
    const int lch0 = (t & 1) * 2;

    auto load_stage = [&](int c, int s) {
        const int kt = c << 5;
        const uint32_t sb = smb + s * STG;
#pragma unroll
        for (int j = 0; j < 2; j++) {
            int ch = lch0 + j;
            uint32_t so = soff(lrow, ch);
            size_t ga = (size_t)(m0 + lrow) * K + kt + ch * 8;
            size_t gb = (size_t)(n0 + lrow) * K + kt + ch * 8;
            cpa16(sb + TA_H + so, Ah + ga);
            cpa16(sb + TA_L + so, Al + ga);
            cpa16(sb + TB_H + so, Bh + gb);
            cpa16(sb + TB_L + so, Bl + gb);
        }
        CP_COMMIT();
    };

    float d[4][4][4];
#pragma unroll
    for (int i = 0; i < 4; i++)
#pragma unroll
        for (int j = 0; j < 4; j++)
#pragma unroll
            for (int k = 0; k < 4; k++) d[i][j][k] = 0.f;

    load_stage(0, 0);

    for (int c = 0; c < NC; c++) {
        const int s = c & 1;
        if (c + 1 < NC) { load_stage(c + 1, s ^ 1); CP_WAIT(1); }
        else CP_WAIT(0);
        __syncthreads();

        const uint32_t sb = smb + s * STG;
#pragma unroll
        for (int ks = 0; ks < 2; ks++) {
            const int kc = ks * 2;
            uint32_t ahf[4][4], alf[4][4];
#pragma unroll
            for (int mt = 0; mt < 4; mt++) {
                int row = wm + mt * 16 + (lane & 15);
                int ch = kc + (lane >> 4);
                uint32_t so = soff(row, ch);
                ldsm4(ahf[mt], sb + TA_H + so);
                ldsm4(alf[mt], sb + TA_L + so);
            }
            uint32_t bhf[4][2], blf[4][2];
#pragma unroll
            for (int p = 0; p < 2; p++) {
                int nrow = wn + p * 16 + ((lane >> 4) & 1) * 8 + (lane & 7);
                int ch = kc + ((lane >> 3) & 1);
                uint32_t so = soff(nrow, ch);
                uint32_t r[4];
                ldsm4(r, sb + TB_H + so);
                bhf[p*2][0] = r[0]; bhf[p*2][1] = r[1];
                bhf[p*2+1][0] = r[2]; bhf[p*2+1][1] = r[3];
                ldsm4(r, sb + TB_L + so);
                blf[p*2][0] = r[0]; blf[p*2][1] = r[1];
                blf[p*2+1][0] = r[2]; blf[p*2+1][1] = r[3];
            }
#pragma unroll
            for (int mt = 0; mt < 4; mt++)
#pragma unroll
                for (int nt = 0; nt < 4; nt++) {
                    mma16816(d[mt][nt], ahf[mt], bhf[nt]);
                    mma16816(d[mt][nt], alf[mt], bhf[nt]);
                    mma16816(d[mt][nt], ahf[mt], blf[nt]);
                }
        }
        __syncthreads();
    }

    const int lr = lane >> 2, lc = (lane & 3) * 2;
#pragma unroll
    for (int mt = 0; mt < 4; mt++) {
        int row = m0 + wm + mt * 16 + lr;
#pragma unroll
        for (int nt = 0; nt < 4; nt++) {
            int col = n0 + wn + nt * 8 + lc;
            float b0 = __ldg(bias + col), b1 = __ldg(bias + col + 1);
            float v0 = (d[mt][nt][0] + b0) * scale, v1 = (d[mt][nt][1] + b1) * scale;
            float v2 = (d[mt][nt][2] + b0) * scale, v3 = (d[mt][nt][3] + b1) * scale;
            if (Cf) {
                *(float2*)&Cf[(size_t)row * N + col] = make_float2(v0, v1);
                *(float2*)&Cf[(size_t)(row + 8) * N + col] = make_float2(v2, v3);
            } else {
                uint32_t hA = packbf(v1, v0), hB = packbf(v3, v2);
                *(uint32_t*)&Ch[(size_t)row * N + col] = hA;
                *(uint32_t*)&Ch[(size_t)(row + 8) * N + col] = hB;
                float l0 = v0 - __uint_as_float(hA << 16);
                float l1 = v1 - __uint_as_float(hA & 0xFFFF0000u);
                float l2 = v2 - __uint_as_float(hB << 16);
                float l3 = v3 - __uint_as_float(hB & 0xFFFF0000u);
                *(uint32_t*)&Cl[(size_t)row * N + col] = packbf(l1, l0);
                *(uint32_t*)&Cl[(size_t)(row + 8) * N + col] = packbf(l3, l2);
            }
        }
    }
}

// ============ tensor-core flash attention ============
// CTA: 128 q rows of one (b,h); 8 warps x 16 rows. kv chunks of 128, 2-stage cp.async.
// stage layout: Kh[16K] Kl[16K] Vh[16K] Vl[16K]; Q hi/lo after both stages.
#define ATS 65536
#define AT_Q (2 * ATS)
#define ATTN_SMEM (2 * ATS + 32768)

__global__ __launch_bounds__(256, 1) void attn_tc(
    const __nv_bfloat16* __restrict__ Qh, const __nv_bfloat16* __restrict__ Ql,
    const __nv_bfloat16* __restrict__ Kh, const __nv_bfloat16* __restrict__ Kl,
    const __nv_bfloat16* __restrict__ Vh, const __nv_bfloat16* __restrict__ Vl,
    __nv_bfloat16* __restrict__ AOh, __nv_bfloat16* __restrict__ AOl)
{
    extern __shared__ char sm[];
    const uint32_t smb = smem_u32(sm);
    const int t = threadIdx.x, w = t >> 5, lane = t & 31;
    const int q0 = blockIdx.x * 128, h = blockIdx.y, b = blockIdx.z;
    const size_t qbase = ((size_t)(b * NQ + q0)) * QD + h * HD;
    const size_t kbase = ((size_t)(b * NK)) * QD + h * HD;

    auto ld_stage = [&](int c, int s) {
        const uint32_t sb = smb + s * ATS;
        const int n0 = c << 7;
#pragma unroll
        for (int j = 0; j < 4; j++) {
            int u = t + j * 256;
            int row = u >> 3, ch = u & 7;
            uint32_t so = soff64(row, ch);
            size_t g = kbase + (size_t)(n0 + row) * QD + ch * 8;
            cpa16(sb + so, Kh + g);
            cpa16(sb + 16384 + so, Kl + g);
            cpa16(sb + 32768 + so, Vh + g);
            cpa16(sb + 49152 + so, Vl + g);
        }
        CP_COMMIT();
    };

    // Q load (goes into group 0 together with stage 0)
#pragma unroll
    for (int j = 0; j < 4; j++) {
        int u = t + j * 256;
        int row = u >> 3, ch = u & 7;
        uint32_t so = soff64(row, ch);
        size_t g = qbase + (size_t)row * QD + ch * 8;
        cpa16(smb + AT_Q + so, Qh + g);
        cpa16(smb + AT_Q + 16384 + so, Ql + g);
    }
    ld_stage(0, 0);

    uint32_t qhf[4][4], qlf[4][4];
    float s[16][4];
    float o[8][4];
    float lsum0 = 0.f, lsum1 = 0.f;
#pragma unroll
    for (int i = 0; i < 8; i++)
#pragma unroll
        for (int j = 0; j < 4; j++) o[i][j] = 0.f;

    for (int c = 0; c < 8; c++) {
        const int st = c & 1;
        if (c < 7) { ld_stage(c + 1, st ^ 1); CP_WAIT(1); }
        else CP_WAIT(0);
        __syncthreads();

        if (c == 0) {
#pragma unroll
            for (int ks = 0; ks < 4; ks++) {
                int row = w * 16 + (lane & 15);
                uint32_t so = soff64(row, ks * 2 + (lane >> 4));
                ldsm4(qhf[ks], smb + AT_Q + so);
                ldsm4(qlf[ks], smb + AT_Q + 16384 + so);
            }
        }
        const uint32_t sb = smb + st * ATS;

        // ---- S = Q K^T (logits in log2 domain; scale folded into Q) ----
#pragma unroll
        for (int sn = 0; sn < 16; sn++) {
            s[sn][0] = 0.f; s[sn][1] = 0.f; s[sn][2] = 0.f; s[sn][3] = 0.f;
        }
#pragma unroll
        for (int ks = 0; ks < 4; ks++) {
#pragma unroll
            for (int p = 0; p < 8; p++) {
                int nrow = p * 16 + ((lane >> 4) & 1) * 8 + (lane & 7);
                int ch = ks * 2 + ((lane >> 3) & 1);
                uint32_t so = soff64(nrow, ch);
                uint32_t kf[4], kfl[4];
                ldsm4(kf, sb + so);
                ldsm4(kfl, sb + 16384 + so);
                uint32_t b0[2] = {kf[0], kf[1]},  b1[2] = {kf[2], kf[3]};
                uint32_t c0[2] = {kfl[0], kfl[1]}, c1[2] = {kfl[2], kfl[3]};
                mma16816(s[2*p],   qhf[ks], b0);
                mma16816(s[2*p],   qlf[ks], b0);
                mma16816(s[2*p],   qhf[ks], c0);
                mma16816(s[2*p+1], qhf[ks], b1);
                mma16816(s[2*p+1], qlf[ks], b1);
                mma16816(s[2*p+1], qhf[ks], c1);
            }
        }

        // ---- exp (poly, FMA pipe), pack P hi/lo, PV mma ----
#pragma unroll
        for (int kk = 0; kk < 8; kk++) {
            float* e0 = s[2*kk];
            float* e1 = s[2*kk+1];
#pragma unroll
            for (int j = 0; j < 4; j++) { e0[j] = fexp2(e0[j]); e1[j] = fexp2(e1[j]); }
            lsum0 += e0[0] + e0[1] + e1[0] + e1[1];
            lsum1 += e0[2] + e0[3] + e1[2] + e1[3];
            uint32_t ph[4], pl[4];
            ph[0] = packbf(e0[1], e0[0]); ph[1] = packbf(e0[3], e0[2]);
            ph[2] = packbf(e1[1], e1[0]); ph[3] = packbf(e1[3], e1[2]);
            pl[0] = packbf(e0[1] - __uint_as_float(ph[0] & 0xFFFF0000u),
                           e0[0] - __uint_as_float(ph[0] << 16));
            pl[1] = packbf(e0[3] - __uint_as_float(ph[1] & 0xFFFF0000u),
                           e0[2] - __uint_as_float(ph[1] << 16));
            pl[2] = packbf(e1[1] - __uint_as_float(ph[2] & 0xFFFF0000u),
                           e1[0] - __uint_as_float(ph[2] << 16));
            pl[3] = packbf(e1[3] - __uint_as_float(ph[3] & 0xFFFF0000u),
                           e1[2] - __uint_as_float(ph[3] << 16));
#pragma unroll
            for (int q = 0; q < 4; q++) {
                int row = kk * 16 + (lane & 15);
                int ch = q * 2 + (lane >> 4);
                uint32_t so = soff64(row, ch);
                uint32_t vf[4], vfl[4];
                ldsm4t(vf, sb + 32768 + so);
                ldsm4t(vfl, sb + 49152 + so);
                uint32_t b0[2] = {vf[0], vf[1]},  b1[2] = {vf[2], vf[3]};
                uint32_t c0[2] = {vfl[0], vfl[1]}, c1[2] = {vfl[2], vfl[3]};
                mma16816(o[2*q],   ph, b0);
                mma16816(o[2*q],   pl, b0);
                mma16816(o[2*q],   ph, c0);
                mma16816(o[2*q+1], ph, b1);
                mma16816(o[2*q+1], pl, b1);
                mma16816(o[2*q+1], ph, c1);
            }
        }
        __syncthreads();
    }

    // row sums across the 4-lane quad
    lsum0 += __shfl_xor_sync(0xffffffffu, lsum0, 1);
    lsum0 += __shfl_xor_sync(0xffffffffu, lsum0, 2);
    lsum1 += __shfl_xor_sync(0xffffffffu, lsum1, 1);
    lsum1 += __shfl_xor_sync(0xffffffffu, lsum1, 2);
    const float inv0 = 1.f / lsum0, inv1 = 1.f / lsum1;

    const int row0 = q0 + w * 16 + (lane >> 2);
#pragma unroll
    for (int nt = 0; nt < 8; nt++) {
        int col = h * HD + nt * 8 + (lane & 3) * 2;
        float v0 = o[nt][0] * inv0, v1 = o[nt][1] * inv0;
        float v2 = o[nt][2] * inv1, v3 = o[nt][3] * inv1;
        uint32_t hA = packbf(v1, v0), hB = packbf(v3, v2);
        *(uint32_t*)&AOh[((size_t)(b * NQ + row0)) * QD + col] = hA;
        *(uint32_t*)&AOh[((size_t)(b * NQ + row0 + 8)) * QD + col] = hB;
        float l0 = v0 - __uint_as_float(hA << 16);
        float l1 = v1 - __uint_as_float(hA & 0xFFFF0000u);
        float l2 = v2 - __uint_as_float(hB << 16);
        float l3 = v3 - __uint_as_float(hB & 0xFFFF0000u);
        *(uint32_t*)&AOl[((size_t)(b * NQ + row0)) * QD + col] = packbf(l1, l0);
        *(uint32_t*)&AOl[((size_t)(b * NQ + row0 + 8)) * QD + col] = packbf(l3, l2);
    }
}

// ============ kernel_launch ============
extern "C" void kernel_launch(void* const* d_in, const int* in_sizes, int n_in,
                              void* d_out, int out_size)
{
    const float* query = (const float*)d_in[0];
    const float* key   = (const float*)d_in[1];
    const float* value = (const float*)d_in[2];
    const float* Wq = (const float*)d_in[3];  const float* bq = (const float*)d_in[4];
    const float* Wk = (const float*)d_in[5];  const float* bk = (const float*)d_in[6];
    const float* Wv = (const float*)d_in[7];  const float* bv = (const float*)d_in[8];
    const float* Wo = (const float*)d_in[9];  const float* bo = (const float*)d_in[10];
    float* out = (float*)d_out;

    __nv_bfloat16 *qh,*ql,*kh,*kl,*vh,*vl;
    __nv_bfloat16 *wqh,*wql,*wkh,*wkl,*wvh,*wvl,*woh,*wol;
    __nv_bfloat16 *Qh,*Ql,*Kh,*Kl,*Vh,*Vl,*aoh,*aol;
    cudaGetSymbolAddress((void**)&qh, g_qh);   cudaGetSymbolAddress((void**)&ql, g_ql);
    cudaGetSymbolAddress((void**)&kh, g_kh);   cudaGetSymbolAddress((void**)&kl, g_kl);
    cudaGetSymbolAddress((void**)&vh, g_vh);   cudaGetSymbolAddress((void**)&vl, g_vl);
    cudaGetSymbolAddress((void**)&wqh, g_wqh); cudaGetSymbolAddress((void**)&wql, g_wql);
    cudaGetSymbolAddress((void**)&wkh, g_wkh); cudaGetSymbolAddress((void**)&wkl, g_wkl);
    cudaGetSymbolAddress((void**)&wvh, g_wvh); cudaGetSymbolAddress((void**)&wvl, g_wvl);
    cudaGetSymbolAddress((void**)&woh, g_woh); cudaGetSymbolAddress((void**)&wol, g_wol);
    cudaGetSymbolAddress((void**)&Qh, g_Qh);   cudaGetSymbolAddress((void**)&Ql, g_Ql);
    cudaGetSymbolAddress((void**)&Kh, g_Kh);   cudaGetSymbolAddress((void**)&Kl, g_Kl);
    cudaGetSymbolAddress((void**)&Vh, g_Vh);   cudaGetSymbolAddress((void**)&Vl, g_Vl);
    cudaGetSymbolAddress((void**)&aoh, g_aoh); cudaGetSymbolAddress((void**)&aol, g_aol);

    cudaFuncSetAttribute(gemm_mma, cudaFuncAttributeMaxDynamicSharedMemorySize, GEMM_SMEM);
    cudaFuncSetAttribute(attn_tc,  cudaFuncAttributeMaxDynamicSharedMemorySize, ATTN_SMEM);

    const int MQ = BATCH * NQ;   // 16384
    const int MK = BATCH * NK;   // 4096

    split_f32<<<(MQ*QD/4 + 255)/256, 256>>>(query, qh, ql, MQ*QD/4);
    split_f32<<<(MK*KD/4 + 255)/256, 256>>>(key,   kh, kl, MK*KD/4);
    split_f32<<<(MK*KD/4 + 255)/256, 256>>>(value, vh, vl, MK*KD/4);
    wsplit_t<<<dim3(QD/32, QD/32), 256>>>(Wq, wqh, wql, QD, QD);
    wsplit_t<<<dim3(QD/32, KD/32), 256>>>(Wk, wkh, wkl, KD, QD);
    wsplit_t<<<dim3(QD/32, KD/32), 256>>>(Wv, wvh, wvl, KD, QD);
    wsplit_t<<<dim3(QD/32, QD/32), 256>>>(Wo, woh, wol, QD, QD);

    // projections (Q scaled by SCALE*log2e; outputs bf16 hi/lo)
    gemm_mma<<<dim3(QD/128, MQ/128), 256, GEMM_SMEM>>>(
        qh, ql, wqh, wql, bq, nullptr, Qh, Ql, QSCALE, MQ, QD, QD);
    gemm_mma<<<dim3(QD/128, MK/128), 256, GEMM_SMEM>>>(
        kh, kl, wkh, wkl, bk, nullptr, Kh, Kl, 1.0f, MK, QD, KD);
    gemm_mma<<<dim3(QD/128, MK/128), 256, GEMM_SMEM>>>(
        vh, vl, wvh, wvl, bv, nullptr, Vh, Vl, 1.0f, MK, QD, KD);

    attn_tc<<<dim3(NQ/128, NH, BATCH), 256, ATTN_SMEM>>>(
        Qh, Ql, Kh, Kl, Vh, Vl, aoh, aol);

    // output projection -> fp32 d_out
    gemm_mma<<<dim3(QD/128, MQ/128), 256, GEMM_SMEM>>>(
        aoh, aol, woh, wol, bo, out, nullptr, nullptr, 1.0f, MQ, QD, QD);
}

// round 6
// speedup vs baseline: 8.2155x; 1.2216x over previous
#include <cuda_runtime.h>
#include <cuda_bf16.h>
#include <cuda_fp16.h>
#include <cstdint>

#define BATCH 4
#define NQ    4096
#define NK    1024
#define NH    16
#define HD    64
#define QD    1024
#define KD    768
// scale folded into Q projection: 0.125 * log2(e)
#define QSCALE 0.1803368801f

// ---------------- helpers ----------------
__device__ __forceinline__ uint32_t smem_u32(const void* p) {
    uint32_t a;
    asm("{ .reg .u64 t; cvta.to.shared.u64 t, %1; cvt.u32.u64 %0, t; }" : "=r"(a) : "l"(p));
    return a;
}
__device__ __forceinline__ void cpa16(uint32_t s, const void* g) {
    asm volatile("cp.async.cg.shared.global [%0], [%1], 16;" :: "r"(s), "l"(g));
}
#define CP_COMMIT() asm volatile("cp.async.commit_group;" ::: "memory")
#define CP_WAIT(n)  asm volatile("cp.async.wait_group %0;" :: "n"(n) : "memory")
__device__ __forceinline__ void ldsm4(uint32_t* r, uint32_t a) {
    asm volatile("ldmatrix.sync.aligned.m8n8.x4.shared.b16 {%0,%1,%2,%3}, [%4];"
        : "=r"(r[0]), "=r"(r[1]), "=r"(r[2]), "=r"(r[3]) : "r"(a));
}
__device__ __forceinline__ void ldsm4t(uint32_t* r, uint32_t a) {
    asm volatile("ldmatrix.sync.aligned.m8n8.x4.trans.shared.b16 {%0,%1,%2,%3}, [%4];"
        : "=r"(r[0]), "=r"(r[1]), "=r"(r[2]), "=r"(r[3]) : "r"(a));
}
__device__ __forceinline__ void mma_bf(float* d, const uint32_t* a, const uint32_t* b) {
    asm volatile("mma.sync.aligned.m16n8k16.row.col.f32.bf16.bf16.f32 "
        "{%0,%1,%2,%3}, {%4,%5,%6,%7}, {%8,%9}, {%0,%1,%2,%3};"
        : "+f"(d[0]), "+f"(d[1]), "+f"(d[2]), "+f"(d[3])
        : "r"(a[0]), "r"(a[1]), "r"(a[2]), "r"(a[3]), "r"(b[0]), "r"(b[1]));
}
__device__ __forceinline__ void mma_fp(float* d, const uint32_t* a, const uint32_t* b) {
    asm volatile("mma.sync.aligned.m16n8k16.row.col.f32.f16.f16.f32 "
        "{%0,%1,%2,%3}, {%4,%5,%6,%7}, {%8,%9}, {%0,%1,%2,%3};"
        : "+f"(d[0]), "+f"(d[1]), "+f"(d[2]), "+f"(d[3])
        : "r"(a[0]), "r"(a[1]), "r"(a[2]), "r"(a[3]), "r"(b[0]), "r"(b[1]));
}
__device__ __forceinline__ uint32_t packbf(float hi, float lo) {
    uint32_t r;
    asm("cvt.rn.bf16x2.f32 %0, %1, %2;" : "=r"(r) : "f"(hi), "f"(lo));
    return r;
}
__device__ __forceinline__ uint32_t packh(float hi, float lo) {
    uint32_t r;
    asm("cvt.rn.f16x2.f32 %0, %1, %2;" : "=r"(r) : "f"(hi), "f"(lo));
    return r;
}
// swizzled offset in [rows][32]bf16 (64B rows, 4 chunks)
__device__ __forceinline__ uint32_t soff(int row, int chunk) {
    return (uint32_t)(row * 64 + ((chunk ^ ((row >> 1) & 3)) << 4));
}
// swizzled offset in [rows][64]halfwords (128B rows, 8 chunks)
__device__ __forceinline__ uint32_t soff64(int row, int ch) {
    return (uint32_t)(row * 128 + ((ch ^ (row & 7)) << 4));
}
// 2^z via deg-6 poly + exponent injection (no MUFU)
__device__ __forceinline__ float fexp2(float z) {
    z = fmaxf(z, -60.f);
    float fi = floorf(z);
    float f = z - fi;
    float p = 1.54035e-4f;
    p = fmaf(p, f, 1.33336e-3f);
    p = fmaf(p, f, 9.61813e-3f);
    p = fmaf(p, f, 5.55041e-2f);
    p = fmaf(p, f, 2.40227e-1f);
    p = fmaf(p, f, 6.9314718e-1f);
    p = fmaf(p, f, 1.0f);
    int i = (int)fi;
    return __int_as_float(__float_as_int(p) + (i << 23));
}

// ---------------- scratch ----------------
#define AL16 __align__(16)
// input splits (bf16 hi/lo for 3-product projection GEMMs)
__device__ AL16 __nv_bfloat16 g_qh[(size_t)BATCH*NQ*QD], g_ql[(size_t)BATCH*NQ*QD];
__device__ AL16 __nv_bfloat16 g_kh[(size_t)BATCH*NK*KD], g_kl[(size_t)BATCH*NK*KD];
__device__ AL16 __nv_bfloat16 g_vh[(size_t)BATCH*NK*KD], g_vl[(size_t)BATCH*NK*KD];
// weight splits (transposed [N,K])
__device__ AL16 __nv_bfloat16 g_wqh[(size_t)QD*QD], g_wql[(size_t)QD*QD];
__device__ AL16 __nv_bfloat16 g_wkh[(size_t)QD*KD], g_wkl[(size_t)QD*KD];
__device__ AL16 __nv_bfloat16 g_wvh[(size_t)QD*KD], g_wvl[(size_t)QD*KD];
__device__ AL16 __nv_bfloat16 g_woh[(size_t)QD*QD], g_wol[(size_t)QD*QD];
// projected Q/K/V: single fp16
__device__ AL16 __half g_Qp[(size_t)BATCH*NQ*QD];
__device__ AL16 __half g_Kp[(size_t)BATCH*NK*QD];
__device__ AL16 __half g_Vp[(size_t)BATCH*NK*QD];
// attention out hi/lo (bf16, for 3-product Oproj)
__device__ AL16 __nv_bfloat16 g_aoh[(size_t)BATCH*NQ*QD], g_aol[(size_t)BATCH*NQ*QD];

// ============ fused input split: q/k/v fp32 -> bf16 hi/lo ============
__global__ __launch_bounds__(256) void split_in(
    const float* __restrict__ q, const float* __restrict__ k, const float* __restrict__ v)
{
    const float* x; __nv_bfloat16 *hi, *lo; int n4;
    if (blockIdx.z == 0) { x = q; hi = g_qh; lo = g_ql; n4 = BATCH*NQ*QD/4; }
    else if (blockIdx.z == 1) { x = k; hi = g_kh; lo = g_kl; n4 = BATCH*NK*KD/4; }
    else { x = v; hi = g_vh; lo = g_vl; n4 = BATCH*NK*KD/4; }
    int i = blockIdx.x * 256 + threadIdx.x;
    if (i >= n4) return;
    float4 val = ((const float4*)x)[i];
    uint32_t h01 = packbf(val.y, val.x), h23 = packbf(val.w, val.z);
    ((uint32_t*)hi)[2*i] = h01; ((uint32_t*)hi)[2*i+1] = h23;
    float l0 = val.x - __uint_as_float(h01 << 16);
    float l1 = val.y - __uint_as_float(h01 & 0xFFFF0000u);
    float l2 = val.z - __uint_as_float(h23 << 16);
    float l3 = val.w - __uint_as_float(h23 & 0xFFFF0000u);
    ((uint32_t*)lo)[2*i] = packbf(l1, l0); ((uint32_t*)lo)[2*i+1] = packbf(l3, l2);
}

// ============ fused weight transpose+split: W[K,N] -> [N,K] hi/lo ============
__global__ __launch_bounds__(256) void wsplit_all(
    const float* __restrict__ Wq, const float* __restrict__ Wk,
    const float* __restrict__ Wv, const float* __restrict__ Wo)
{
    const float* W; __nv_bfloat16 *Th, *Tl; int K;
    if (blockIdx.z == 0) { W = Wq; Th = g_wqh; Tl = g_wql; K = QD; }
    else if (blockIdx.z == 1) { W = Wk; Th = g_wkh; Tl = g_wkl; K = KD; }
    else if (blockIdx.z == 2) { W = Wv; Th = g_wvh; Tl = g_wvl; K = KD; }
    else { W = Wo; Th = g_woh; Tl = g_wol; K = QD; }
    const int N = QD;
    const int nb = blockIdx.x * 32, kb = blockIdx.y * 32;
    if (kb >= K) return;
    __shared__ float tile[32][33];
    const int tx = threadIdx.x & 31, tg = threadIdx.x >> 5;
#pragma unroll
    for (int r = 0; r < 4; r++) {
        int kk = tg + r * 8;
        tile[kk][tx] = W[(size_t)(kb + kk) * N + nb + tx];
    }
    __syncthreads();
#pragma unroll
    for (int r = 0; r < 4; r++) {
        int n = tg + r * 8;
        float v = tile[tx][n];
        __nv_bfloat16 h = __float2bfloat16_rn(v);
        Th[(size_t)(nb + n) * K + kb + tx] = h;
        Tl[(size_t)(nb + n) * K + kb + tx] = __float2bfloat16_rn(v - __bfloat162float(h));
    }
}

// ============ mma.sync GEMM (bf16 3-product): (Ah+Al)@(Bh+Bl)^T + bias, *scale ============
// Output: fp32 (Cf) OR fp16 single (C16). CTA 128x128, K-chunk 32, 8 warps.
#define TA_H 0
#define TA_L 8192
#define TB_H 16384
#define TB_L 24576
#define STG  32768
#define GEMM_SMEM (2 * STG)

__global__ __launch_bounds__(256, 1) void gemm_mma(
    const __nv_bfloat16* __restrict__ Ah, const __nv_bfloat16* __restrict__ Al,
    const __nv_bfloat16* __restrict__ Bh, const __nv_bfloat16* __restrict__ Bl,
    const float* __restrict__ bias, float* __restrict__ Cf,
    __half* __restrict__ C16, float scale, int M, int N, int K)
{
    extern __shared__ char sm[];
    const uint32_t smb = smem_u32(sm);
    const int t = threadIdx.x, wid = t >> 5, lane = t & 31;
    const int m0 = blockIdx.y * 128, n0 = blockIdx.x * 128;
    const int NC = K >> 5;
    const int wm = (wid & 1) * 64, wn = (wid >> 1) * 32;
    const int lrow = t >> 1;
    const int lch0 = (t & 1) * 2;

    auto load_stage = [&](int c, int s) {
        const int kt = c << 5;
        const uint32_t sb = smb + s * STG;
#pragma unroll
        for (int j = 0; j < 2; j++) {
            int ch = lch0 + j;
            uint32_t so = soff(lrow, ch);
            size_t ga = (size_t)(m0 + lrow) * K + kt + ch * 8;
            size_t gb = (size_t)(n0 + lrow) * K + kt + ch * 8;
            cpa16(sb + TA_H + so, Ah + ga);
            cpa16(sb + TA_L + so, Al + ga);
            cpa16(sb + TB_H + so, Bh + gb);
            cpa16(sb + TB_L + so, Bl + gb);
        }
        CP_COMMIT();
    };

    float d[4][4][4];
#pragma unroll
    for (int i = 0; i < 4; i++)
#pragma unroll
        for (int j = 0; j < 4; j++)
#pragma unroll
            for (int k = 0; k < 4; k++) d[i][j][k] = 0.f;

    load_stage(0, 0);

    for (int c = 0; c < NC; c++) {
        const int s = c & 1;
        if (c + 1 < NC) { load_stage(c + 1, s ^ 1); CP_WAIT(1); }
        else CP_WAIT(0);
        __syncthreads();

        const uint32_t sb = smb + s * STG;
#pragma unroll
        for (int ks = 0; ks < 2; ks++) {
            const int kc = ks * 2;
            uint32_t ahf[4][4], alf[4][4];
#pragma unroll
            for (int mt = 0; mt < 4; mt++) {
                int row = wm + mt * 16 + (lane & 15);
                int ch = kc + (lane >> 4);
                uint32_t so = soff(row, ch);
                ldsm4(ahf[mt], sb + TA_H + so);
                ldsm4(alf[mt], sb + TA_L + so);
            }
            uint32_t bhf[4][2], blf[4][2];
#pragma unroll
            for (int p = 0; p < 2; p++) {
                int nrow = wn + p * 16 + ((lane >> 4) & 1) * 8 + (lane & 7);
                int ch = kc + ((lane >> 3) & 1);
                uint32_t so = soff(nrow, ch);
                uint32_t r[4];
                ldsm4(r, sb + TB_H + so);
                bhf[p*2][0] = r[0]; bhf[p*2][1] = r[1];
                bhf[p*2+1][0] = r[2]; bhf[p*2+1][1] = r[3];
                ldsm4(r, sb + TB_L + so);
                blf[p*2][0] = r[0]; blf[p*2][1] = r[1];
                blf[p*2+1][0] = r[2]; blf[p*2+1][1] = r[3];
            }
#pragma unroll
            for (int mt = 0; mt < 4; mt++)
#pragma unroll
                for (int nt = 0; nt < 4; nt++) {
                    mma_bf(d[mt][nt], ahf[mt], bhf[nt]);
                    mma_bf(d[mt][nt], alf[mt], bhf[nt]);
                    mma_bf(d[mt][nt], ahf[mt], blf[nt]);
                }
        }
        __syncthreads();
    }

    const int lr = lane >> 2, lc = (lane & 3) * 2;
#pragma unroll
    for (int mt = 0; mt < 4; mt++) {
        int row = m0 + wm + mt * 16 + lr;
#pragma unroll
        for (int nt = 0; nt < 4; nt++) {
            int col = n0 + wn + nt * 8 + lc;
            float b0 = __ldg(bias + col), b1 = __ldg(bias + col + 1);
            float v0 = (d[mt][nt][0] + b0) * scale, v1 = (d[mt][nt][1] + b1) * scale;
            float v2 = (d[mt][nt][2] + b0) * scale, v3 = (d[mt][nt][3] + b1) * scale;
            if (Cf) {
                *(float2*)&Cf[(size_t)row * N + col] = make_float2(v0, v1);
                *(float2*)&Cf[(size_t)(row + 8) * N + col] = make_float2(v2, v3);
            } else {
                *(uint32_t*)&C16[(size_t)row * N + col] = packh(v1, v0);
                *(uint32_t*)&C16[(size_t)(row + 8) * N + col] = packh(v3, v2);
            }
        }
    }
}

// ============ tensor-core flash attention, single-product fp16 ============
// CTA: 128 q rows of one (b,h); 8 warps x 16 rows. kv chunks of 128, 3-stage cp.async.
// stage (32KB): K[16K] V[16K]; Q fp16 (16KB) after the 3 stages.
#define ATS 32768
#define AT_Q (3 * ATS)
#define ATTN_SMEM (3 * ATS + 16384)

__global__ __launch_bounds__(256, 1) void attn_tc(
    const __half* __restrict__ Qp, const __half* __restrict__ Kp,
    const __half* __restrict__ Vp,
    __nv_bfloat16* __restrict__ AOh, __nv_bfloat16* __restrict__ AOl)
{
    extern __shared__ char sm[];
    const uint32_t smb = smem_u32(sm);
    const int t = threadIdx.x, w = t >> 5, lane = t & 31;
    const int q0 = blockIdx.x * 128, h = blockIdx.y, b = blockIdx.z;
    const size_t qbase = ((size_t)(b * NQ + q0)) * QD + h * HD;
    const size_t kbase = ((size_t)(b * NK)) * QD + h * HD;

    auto ld_stage = [&](int c, int s) {
        const uint32_t sb = smb + s * ATS;
        const int n0 = c << 7;
#pragma unroll
        for (int j = 0; j < 4; j++) {
            int u = t + j * 256;
            int row = u >> 3, ch = u & 7;
            uint32_t so = soff64(row, ch);
            size_t g = kbase + (size_t)(n0 + row) * QD + ch * 8;
            cpa16(sb + so, Kp + g);
            cpa16(sb + 16384 + so, Vp + g);
        }
        CP_COMMIT();
    };

    // Q load rides in cp group 0
#pragma unroll
    for (int j = 0; j < 4; j++) {
        int u = t + j * 256;
        int row = u >> 3, ch = u & 7;
        uint32_t so = soff64(row, ch);
        cpa16(smb + AT_Q + so, Qp + qbase + (size_t)row * QD + ch * 8);
    }
    ld_stage(0, 0);
    ld_stage(1, 1);

    uint32_t qf[4][4];
    float s[16][4];
    float o[8][4];
    float lsum0 = 0.f, lsum1 = 0.f;
#pragma unroll
    for (int i = 0; i < 8; i++)
#pragma unroll
        for (int j = 0; j < 4; j++) o[i][j] = 0.f;

    for (int c = 0; c < 8; c++) {
        const int st = c % 3;
        if (c + 2 < 8) { ld_stage(c + 2, (c + 2) % 3); CP_WAIT(2); }
        else if (c + 1 < 8) CP_WAIT(1);
        else CP_WAIT(0);
        __syncthreads();

        if (c == 0) {
#pragma unroll
            for (int ks = 0; ks < 4; ks++) {
                int row = w * 16 + (lane & 15);
                uint32_t so = soff64(row, ks * 2 + (lane >> 4));
                ldsm4(qf[ks], smb + AT_Q + so);
            }
        }
        const uint32_t sb = smb + st * ATS;

        // ---- S = Q K^T (logits in log2 domain; scale folded into Q) ----
#pragma unroll
        for (int sn = 0; sn < 16; sn++) {
            s[sn][0] = 0.f; s[sn][1] = 0.f; s[sn][2] = 0.f; s[sn][3] = 0.f;
        }
#pragma unroll
        for (int ks = 0; ks < 4; ks++) {
#pragma unroll
            for (int p = 0; p < 8; p++) {
                int nrow = p * 16 + ((lane >> 4) & 1) * 8 + (lane & 7);
                int ch = ks * 2 + ((lane >> 3) & 1);
                uint32_t so = soff64(nrow, ch);
                uint32_t kf[4];
                ldsm4(kf, sb + so);
                uint32_t b0[2] = {kf[0], kf[1]}, b1[2] = {kf[2], kf[3]};
                mma_fp(s[2*p],   qf[ks], b0);
                mma_fp(s[2*p+1], qf[ks], b1);
            }
        }

        // ---- exp2 (poly), pack P fp16, PV mma ----
#pragma unroll
        for (int kk = 0; kk < 8; kk++) {
            float* e0 = s[2*kk];
            float* e1 = s[2*kk+1];
#pragma unroll
            for (int j = 0; j < 4; j++) { e0[j] = fexp2(e0[j]); e1[j] = fexp2(e1[j]); }
            lsum0 += e0[0] + e0[1] + e1[0] + e1[1];
            lsum1 += e0[2] + e0[3] + e1[2] + e1[3];
            uint32_t ph[4];
            ph[0] = packh(e0[1], e0[0]); ph[1] = packh(e0[3], e0[2]);
            ph[2] = packh(e1[1], e1[0]); ph[3] = packh(e1[3], e1[2]);
#pragma unroll
            for (int q = 0; q < 4; q++) {
                int row = kk * 16 + (lane & 15);
                int ch = q * 2 + (lane >> 4);
                uint32_t so = soff64(row, ch);
                uint32_t vf[4];
                ldsm4t(vf, sb + 16384 + so);
                uint32_t b0[2] = {vf[0], vf[1]}, b1[2] = {vf[2], vf[3]};
                mma_fp(o[2*q],   ph, b0);
                mma_fp(o[2*q+1], ph, b1);
            }
        }
        __syncthreads();
    }

    // row sums across the 4-lane quad
    lsum0 += __shfl_xor_sync(0xffffffffu, lsum0, 1);
    lsum0 += __shfl_xor_sync(0xffffffffu, lsum0, 2);
    lsum1 += __shfl_xor_sync(0xffffffffu, lsum1, 1);
    lsum1 += __shfl_xor_sync(0xffffffffu, lsum1, 2);
    const float inv0 = 1.f / lsum0, inv1 = 1.f / lsum1;

    const int row0 = q0 + w * 16 + (lane >> 2);
#pragma unroll
    for (int nt = 0; nt < 8; nt++) {
        int col = h * HD + nt * 8 + (lane & 3) * 2;
        float v0 = o[nt][0] * inv0, v1 = o[nt][1] * inv0;
        float v2 = o[nt][2] * inv1, v3 = o[nt][3] * inv1;
        uint32_t hA = packbf(v1, v0), hB = packbf(v3, v2);
        *(uint32_t*)&AOh[((size_t)(b * NQ + row0)) * QD + col] = hA;
        *(uint32_t*)&AOh[((size_t)(b * NQ + row0 + 8)) * QD + col] = hB;
        float l0 = v0 - __uint_as_float(hA << 16);
        float l1 = v1 - __uint_as_float(hA & 0xFFFF0000u);
        float l2 = v2 - __uint_as_float(hB << 16);
        float l3 = v3 - __uint_as_float(hB & 0xFFFF0000u);
        *(uint32_t*)&AOl[((size_t)(b * NQ + row0)) * QD + col] = packbf(l1, l0);
        *(uint32_t*)&AOl[((size_t)(b * NQ + row0 + 8)) * QD + col] = packbf(l3, l2);
    }
}

// ============ kernel_launch ============
extern "C" void kernel_launch(void* const* d_in, const int* in_sizes, int n_in,
                              void* d_out, int out_size)
{
    const float* query = (const float*)d_in[0];
    const float* key   = (const float*)d_in[1];
    const float* value = (const float*)d_in[2];
    const float* Wq = (const float*)d_in[3];  const float* bq = (const float*)d_in[4];
    const float* Wk = (const float*)d_in[5];  const float* bk = (const float*)d_in[6];
    const float* Wv = (const float*)d_in[7];  const float* bv = (const float*)d_in[8];
    const float* Wo = (const float*)d_in[9];  const float* bo = (const float*)d_in[10];
    float* out = (float*)d_out;

    __nv_bfloat16 *qh,*ql,*kh,*kl,*vh,*vl;
    __nv_bfloat16 *wqh,*wql,*wkh,*wkl,*wvh,*wvl,*woh,*wol,*aoh,*aol;
    __half *Qp,*Kp,*Vp;
    cudaGetSymbolAddress((void**)&qh, g_qh);   cudaGetSymbolAddress((void**)&ql, g_ql);
    cudaGetSymbolAddress((void**)&kh, g_kh);   cudaGetSymbolAddress((void**)&kl, g_kl);
    cudaGetSymbolAddress((void**)&vh, g_vh);   cudaGetSymbolAddress((void**)&vl, g_vl);
    cudaGetSymbolAddress((void**)&wqh, g_wqh); cudaGetSymbolAddress((void**)&wql, g_wql);
    cudaGetSymbolAddress((void**)&wkh, g_wkh); cudaGetSymbolAddress((void**)&wkl, g_wkl);
    cudaGetSymbolAddress((void**)&wvh, g_wvh); cudaGetSymbolAddress((void**)&wvl, g_wvl);
    cudaGetSymbolAddress((void**)&woh, g_woh); cudaGetSymbolAddress((void**)&wol, g_wol);
    cudaGetSymbolAddress((void**)&Qp, g_Qp);   cudaGetSymbolAddress((void**)&Kp, g_Kp);
    cudaGetSymbolAddress((void**)&Vp, g_Vp);
    cudaGetSymbolAddress((void**)&aoh, g_aoh); cudaGetSymbolAddress((void**)&aol, g_aol);

    cudaFuncSetAttribute(gemm_mma, cudaFuncAttributeMaxDynamicSharedMemorySize, GEMM_SMEM);
    cudaFuncSetAttribute(attn_tc,  cudaFuncAttributeMaxDynamicSharedMemorySize, ATTN_SMEM);

    const int MQ = BATCH * NQ;   // 16384
    const int MK = BATCH * NK;   // 4096

    // launch 0: fused input split
    split_in<<<dim3(MQ*QD/4/256, 1, 3), 256>>>(query, key, value);
    // launch 1: fused weight transpose+split
    wsplit_all<<<dim3(QD/32, QD/32, 4), 256>>>(Wq, Wk, Wv, Wo);
    // launches 2-4: projections (Q scaled by SCALE*log2e; outputs fp16)
    gemm_mma<<<dim3(QD/128, MQ/128), 256, GEMM_SMEM>>>(
        qh, ql, wqh, wql, bq, nullptr, Qp, QSCALE, MQ, QD, QD);
    gemm_mma<<<dim3(QD/128, MK/128), 256, GEMM_SMEM>>>(
        kh, kl, wkh, wkl, bk, nullptr, Kp, 1.0f, MK, QD, KD);
    gemm_mma<<<dim3(QD/128, MK/128), 256, GEMM_SMEM>>>(
        vh, vl, wvh, wvl, bv, nullptr, Vp, 1.0f, MK, QD, KD);
    // launch 5 (ncu -s 5 -c 1 captures this): attention
    attn_tc<<<dim3(NQ/128, NH, BATCH), 256, ATTN_SMEM>>>(Qp, Kp, Vp, aoh, aol);
    // launch 6: output projection -> fp32 d_out
    gemm_mma<<<dim3(QD/128, MQ/128), 256, GEMM_SMEM>>>(
        aoh, aol, woh, wol, bo, out, nullptr, 1.0f, MQ, QD, QD);
}

// round 7
// speedup vs baseline: 9.6181x; 1.1707x over previous
#include <cuda_runtime.h>
#include <cuda_bf16.h>
#include <cuda_fp16.h>
#include <cstdint>

#define BATCH 4
#define NQ    4096
#define NK    1024
#define NH    16
#define HD    64
#define QD    1024
#define KD    768
// scale folded into Q projection: 0.125 * log2(e)
#define QSCALE 0.1803368801f

// ---------------- helpers ----------------
__device__ __forceinline__ uint32_t smem_u32(const void* p) {
    uint32_t a;
    asm("{ .reg .u64 t; cvta.to.shared.u64 t, %1; cvt.u32.u64 %0, t; }" : "=r"(a) : "l"(p));
    return a;
}
__device__ __forceinline__ void cpa16(uint32_t s, const void* g) {
    asm volatile("cp.async.cg.shared.global [%0], [%1], 16;" :: "r"(s), "l"(g));
}
#define CP_COMMIT() asm volatile("cp.async.commit_group;" ::: "memory")
#define CP_WAIT(n)  asm volatile("cp.async.wait_group %0;" :: "n"(n) : "memory")
__device__ __forceinline__ void ldsm4(uint32_t* r, uint32_t a) {
    asm volatile("ldmatrix.sync.aligned.m8n8.x4.shared.b16 {%0,%1,%2,%3}, [%4];"
        : "=r"(r[0]), "=r"(r[1]), "=r"(r[2]), "=r"(r[3]) : "r"(a));
}
__device__ __forceinline__ void ldsm4t(uint32_t* r, uint32_t a) {
    asm volatile("ldmatrix.sync.aligned.m8n8.x4.trans.shared.b16 {%0,%1,%2,%3}, [%4];"
        : "=r"(r[0]), "=r"(r[1]), "=r"(r[2]), "=r"(r[3]) : "r"(a));
}
__device__ __forceinline__ void mma_bf(float* d, const uint32_t* a, const uint32_t* b) {
    asm volatile("mma.sync.aligned.m16n8k16.row.col.f32.bf16.bf16.f32 "
        "{%0,%1,%2,%3}, {%4,%5,%6,%7}, {%8,%9}, {%0,%1,%2,%3};"
        : "+f"(d[0]), "+f"(d[1]), "+f"(d[2]), "+f"(d[3])
        : "r"(a[0]), "r"(a[1]), "r"(a[2]), "r"(a[3]), "r"(b[0]), "r"(b[1]));
}
__device__ __forceinline__ void mma_fp(float* d, const uint32_t* a, const uint32_t* b) {
    asm volatile("mma.sync.aligned.m16n8k16.row.col.f32.f16.f16.f32 "
        "{%0,%1,%2,%3}, {%4,%5,%6,%7}, {%8,%9}, {%0,%1,%2,%3};"
        : "+f"(d[0]), "+f"(d[1]), "+f"(d[2]), "+f"(d[3])
        : "r"(a[0]), "r"(a[1]), "r"(a[2]), "r"(a[3]), "r"(b[0]), "r"(b[1]));
}
__device__ __forceinline__ uint32_t packbf(float hi, float lo) {
    uint32_t r;
    asm("cvt.rn.bf16x2.f32 %0, %1, %2;" : "=r"(r) : "f"(hi), "f"(lo));
    return r;
}
__device__ __forceinline__ uint32_t packh(float hi, float lo) {
    uint32_t r;
    asm("cvt.rn.f16x2.f32 %0, %1, %2;" : "=r"(r) : "f"(hi), "f"(lo));
    return r;
}
// swizzled offset in [rows][32]halfwords (64B rows, 4 chunks)
__device__ __forceinline__ uint32_t soff(int row, int chunk) {
    return (uint32_t)(row * 64 + ((chunk ^ ((row >> 1) & 3)) << 4));
}
// swizzled offset in [rows][64]halfwords (128B rows, 8 chunks)
__device__ __forceinline__ uint32_t soff64(int row, int ch) {
    return (uint32_t)(row * 128 + ((ch ^ (row & 7)) << 4));
}
// 2^z via deg-6 poly + exponent injection (no MUFU)
__device__ __forceinline__ float fexp2(float z) {
    z = fmaxf(z, -60.f);
    float fi = floorf(z);
    float f = z - fi;
    float p = 1.54035e-4f;
    p = fmaf(p, f, 1.33336e-3f);
    p = fmaf(p, f, 9.61813e-3f);
    p = fmaf(p, f, 5.55041e-2f);
    p = fmaf(p, f, 2.40227e-1f);
    p = fmaf(p, f, 6.9314718e-1f);
    p = fmaf(p, f, 1.0f);
    int i = (int)fi;
    return __int_as_float(__float_as_int(p) + (i << 23));
}

// ---------------- scratch ----------------
#define AL16 __align__(16)
__device__ AL16 __nv_bfloat16 g_qh[(size_t)BATCH*NQ*QD], g_ql[(size_t)BATCH*NQ*QD];
__device__ AL16 __nv_bfloat16 g_kh[(size_t)BATCH*NK*KD], g_kl[(size_t)BATCH*NK*KD];
__device__ AL16 __nv_bfloat16 g_vh[(size_t)BATCH*NK*KD], g_vl[(size_t)BATCH*NK*KD];
__device__ AL16 __nv_bfloat16 g_wqh[(size_t)QD*QD], g_wql[(size_t)QD*QD];
__device__ AL16 __nv_bfloat16 g_wkh[(size_t)QD*KD], g_wkl[(size_t)QD*KD];
__device__ AL16 __nv_bfloat16 g_wvh[(size_t)QD*KD], g_wvl[(size_t)QD*KD];
__device__ AL16 __nv_bfloat16 g_woh[(size_t)QD*QD], g_wol[(size_t)QD*QD];
__device__ AL16 __half g_Qp[(size_t)BATCH*NQ*QD];
__device__ AL16 __half g_Kp[(size_t)BATCH*NK*QD];
__device__ AL16 __half g_Vp[(size_t)BATCH*NK*QD];
__device__ AL16 __nv_bfloat16 g_aoh[(size_t)BATCH*NQ*QD], g_aol[(size_t)BATCH*NQ*QD];

// ============ fused input split: q/k/v fp32 -> bf16 hi/lo ============
__global__ __launch_bounds__(256) void split_in(
    const float* __restrict__ q, const float* __restrict__ k, const float* __restrict__ v)
{
    const float* x; __nv_bfloat16 *hi, *lo; int n4;
    if (blockIdx.z == 0) { x = q; hi = g_qh; lo = g_ql; n4 = BATCH*NQ*QD/4; }
    else if (blockIdx.z == 1) { x = k; hi = g_kh; lo = g_kl; n4 = BATCH*NK*KD/4; }
    else { x = v; hi = g_vh; lo = g_vl; n4 = BATCH*NK*KD/4; }
    int i = blockIdx.x * 256 + threadIdx.x;
    if (i >= n4) return;
    float4 val = ((const float4*)x)[i];
    uint32_t h01 = packbf(val.y, val.x), h23 = packbf(val.w, val.z);
    ((uint32_t*)hi)[2*i] = h01; ((uint32_t*)hi)[2*i+1] = h23;
    float l0 = val.x - __uint_as_float(h01 << 16);
    float l1 = val.y - __uint_as_float(h01 & 0xFFFF0000u);
    float l2 = val.z - __uint_as_float(h23 << 16);
    float l3 = val.w - __uint_as_float(h23 & 0xFFFF0000u);
    ((uint32_t*)lo)[2*i] = packbf(l1, l0); ((uint32_t*)lo)[2*i+1] = packbf(l3, l2);
}

// ============ fused weight transpose+split ============
__global__ __launch_bounds__(256) void wsplit_all(
    const float* __restrict__ Wq, const float* __restrict__ Wk,
    const float* __restrict__ Wv, const float* __restrict__ Wo)
{
    const float* W; __nv_bfloat16 *Th, *Tl; int K;
    if (blockIdx.z == 0) { W = Wq; Th = g_wqh; Tl = g_wql; K = QD; }
    else if (blockIdx.z == 1) { W = Wk; Th = g_wkh; Tl = g_wkl; K = KD; }
    else if (blockIdx.z == 2) { W = Wv; Th = g_wvh; Tl = g_wvl; K = KD; }
    else { W = Wo; Th = g_woh; Tl = g_wol; K = QD; }
    const int N = QD;
    const int nb = blockIdx.x * 32, kb = blockIdx.y * 32;
    if (kb >= K) return;
    __shared__ float tile[32][33];
    const int tx = threadIdx.x & 31, tg = threadIdx.x >> 5;
#pragma unroll
    for (int r = 0; r < 4; r++) {
        int kk = tg + r * 8;
        tile[kk][tx] = W[(size_t)(kb + kk) * N + nb + tx];
    }
    __syncthreads();
#pragma unroll
    for (int r = 0; r < 4; r++) {
        int n = tg + r * 8;
        float v = tile[tx][n];
        __nv_bfloat16 h = __float2bfloat16_rn(v);
        Th[(size_t)(nb + n) * K + kb + tx] = h;
        Tl[(size_t)(nb + n) * K + kb + tx] = __float2bfloat16_rn(v - __bfloat162float(h));
    }
}

// ============ mma.sync GEMM (bf16 3-product), 2 CTAs/SM ============
#define TA_H 0
#define TA_L 8192
#define TB_H 16384
#define TB_L 24576
#define STG  32768
#define GEMM_SMEM (2 * STG)

__global__ __launch_bounds__(256, 2) void gemm_mma(
    const __nv_bfloat16* __restrict__ Ah, const __nv_bfloat16* __restrict__ Al,
    const __nv_bfloat16* __restrict__ Bh, const __nv_bfloat16* __restrict__ Bl,
    const float* __restrict__ bias, float* __restrict__ Cf,
    __half* __restrict__ C16, float scale, int M, int N, int K)
{
    extern __shared__ char sm[];
    const uint32_t smb = smem_u32(sm);
    const int t = threadIdx.x, wid = t >> 5, lane = t & 31;
    const int m0 = blockIdx.y * 128, n0 = blockIdx.x * 128;
    const int NC = K >> 5;
    const int wm = (wid & 1) * 64, wn = (wid >> 1) * 32;
    const int lrow = t >> 1;
    const int lch0 = (t & 1) * 2;

    auto load_stage = [&](int c, int s) {
        const int kt = c << 5;
        const uint32_t sb = smb + s * STG;
#pragma unroll
        for (int j = 0; j < 2; j++) {
            int ch = lch0 + j;
            uint32_t so = soff(lrow, ch);
            size_t ga = (size_t)(m0 + lrow) * K + kt + ch * 8;
            size_t gb = (size_t)(n0 + lrow) * K + kt + ch * 8;
            cpa16(sb + TA_H + so, Ah + ga);
            cpa16(sb + TA_L + so, Al + ga);
            cpa16(sb + TB_H + so, Bh + gb);
            cpa16(sb + TB_L + so, Bl + gb);
        }
        CP_COMMIT();
    };

    float d[4][4][4];
#pragma unroll
    for (int i = 0; i < 4; i++)
#pragma unroll
        for (int j = 0; j < 4; j++)
#pragma unroll
            for (int k = 0; k < 4; k++) d[i][j][k] = 0.f;

    load_stage(0, 0);

    for (int c = 0; c < NC; c++) {
        const int s = c & 1;
        if (c + 1 < NC) { load_stage(c + 1, s ^ 1); CP_WAIT(1); }
        else CP_WAIT(0);
        __syncthreads();

        const uint32_t sb = smb + s * STG;
#pragma unroll
        for (int ks = 0; ks < 2; ks++) {
            const int kc = ks * 2;
            uint32_t ahf[4][4], alf[4][4];
#pragma unroll
            for (int mt = 0; mt < 4; mt++) {
                int row = wm + mt * 16 + (lane & 15);
                int ch = kc + (lane >> 4);
                uint32_t so = soff(row, ch);
                ldsm4(ahf[mt], sb + TA_H + so);
                ldsm4(alf[mt], sb + TA_L + so);
            }
            uint32_t bhf[4][2], blf[4][2];
#pragma unroll
            for (int p = 0; p < 2; p++) {
                int nrow = wn + p * 16 + ((lane >> 4) & 1) * 8 + (lane & 7);
                int ch = kc + ((lane >> 3) & 1);
                uint32_t so = soff(nrow, ch);
                uint32_t r[4];
                ldsm4(r, sb + TB_H + so);
                bhf[p*2][0] = r[0]; bhf[p*2][1] = r[1];
                bhf[p*2+1][0] = r[2]; bhf[p*2+1][1] = r[3];
                ldsm4(r, sb + TB_L + so);
                blf[p*2][0] = r[0]; blf[p*2][1] = r[1];
                blf[p*2+1][0] = r[2]; blf[p*2+1][1] = r[3];
            }
#pragma unroll
            for (int mt = 0; mt < 4; mt++)
#pragma unroll
                for (int nt = 0; nt < 4; nt++) {
                    mma_bf(d[mt][nt], ahf[mt], bhf[nt]);
                    mma_bf(d[mt][nt], alf[mt], bhf[nt]);
                    mma_bf(d[mt][nt], ahf[mt], blf[nt]);
                }
        }
        __syncthreads();
    }

    const int lr = lane >> 2, lc = (lane & 3) * 2;
#pragma unroll
    for (int mt = 0; mt < 4; mt++) {
        int row = m0 + wm + mt * 16 + lr;
#pragma unroll
        for (int nt = 0; nt < 4; nt++) {
            int col = n0 + wn + nt * 8 + lc;
            float b0 = __ldg(bias + col), b1 = __ldg(bias + col + 1);
            float v0 = (d[mt][nt][0] + b0) * scale, v1 = (d[mt][nt][1] + b1) * scale;
            float v2 = (d[mt][nt][2] + b0) * scale, v3 = (d[mt][nt][3] + b1) * scale;
            if (Cf) {
                *(float2*)&Cf[(size_t)row * N + col] = make_float2(v0, v1);
                *(float2*)&Cf[(size_t)(row + 8) * N + col] = make_float2(v2, v3);
            } else {
                *(uint32_t*)&C16[(size_t)row * N + col] = packh(v1, v0);
                *(uint32_t*)&C16[(size_t)(row + 8) * N + col] = packh(v3, v2);
            }
        }
    }
}

// ============ tensor-core flash attention, fp16, kv-chunk 64, 4-stage, 2 CTAs/SM ============
// CTA: 128 q rows of one (b,h); 8 warps x 16 rows. smem: 4 stages x 16KB (K 8K + V 8K) + Q 16KB.
#define ATS 16384
#define AT_Q (4 * ATS)
#define ATTN_SMEM (4 * ATS + 16384)
#define NCH (NK / 64)   // 16 chunks

__global__ __launch_bounds__(256, 2) void attn_tc(
    const __half* __restrict__ Qp, const __half* __restrict__ Kp,
    const __half* __restrict__ Vp,
    __nv_bfloat16* __restrict__ AOh, __nv_bfloat16* __restrict__ AOl)
{
    extern __shared__ char sm[];
    const uint32_t smb = smem_u32(sm);
    const int t = threadIdx.x, w = t >> 5, lane = t & 31;
    const int q0 = blockIdx.x * 128, h = blockIdx.y, b = blockIdx.z;
    const size_t qbase = ((size_t)(b * NQ + q0)) * QD + h * HD;
    const size_t kbase = ((size_t)(b * NK)) * QD + h * HD;

    auto ld_stage = [&](int c) {
        const uint32_t sb = smb + (c & 3) * ATS;
        const int n0 = c << 6;
#pragma unroll
        for (int j = 0; j < 2; j++) {
            int u = t + j * 256;
            int row = u >> 3, ch = u & 7;
            uint32_t so = soff64(row, ch);
            size_t g = kbase + (size_t)(n0 + row) * QD + ch * 8;
            cpa16(sb + so, Kp + g);
            cpa16(sb + 8192 + so, Vp + g);
        }
        CP_COMMIT();
    };

    // Q load rides in cp group 0
#pragma unroll
    for (int j = 0; j < 4; j++) {
        int u = t + j * 256;
        int row = u >> 3, ch = u & 7;
        uint32_t so = soff64(row, ch);
        cpa16(smb + AT_Q + so, Qp + qbase + (size_t)row * QD + ch * 8);
    }
    ld_stage(0);
    ld_stage(1);
    ld_stage(2);

    uint32_t qf[4][4];
    float s[8][4];
    float o[8][4];
    float lsum0 = 0.f, lsum1 = 0.f;
#pragma unroll
    for (int i = 0; i < 8; i++)
#pragma unroll
        for (int j = 0; j < 4; j++) o[i][j] = 0.f;

    for (int c = 0; c < NCH; c++) {
        if (c + 3 < NCH) { ld_stage(c + 3); CP_WAIT(3); }
        else if (c == NCH - 3) CP_WAIT(2);
        else if (c == NCH - 2) CP_WAIT(1);
        else CP_WAIT(0);
        __syncthreads();

        if (c == 0) {
#pragma unroll
            for (int ks = 0; ks < 4; ks++) {
                int row = w * 16 + (lane & 15);
                uint32_t so = soff64(row, ks * 2 + (lane >> 4));
                ldsm4(qf[ks], smb + AT_Q + so);
            }
        }
        const uint32_t sb = smb + (c & 3) * ATS;

        // ---- S = Q K^T over 64 kv (logits in log2 domain) ----
#pragma unroll
        for (int sn = 0; sn < 8; sn++) {
            s[sn][0] = 0.f; s[sn][1] = 0.f; s[sn][2] = 0.f; s[sn][3] = 0.f;
        }
#pragma unroll
        for (int ks = 0; ks < 4; ks++) {
#pragma unroll
            for (int p = 0; p < 4; p++) {
                int nrow = p * 16 + ((lane >> 4) & 1) * 8 + (lane & 7);
                int ch = ks * 2 + ((lane >> 3) & 1);
                uint32_t so = soff64(nrow, ch);
                uint32_t kf[4];
                ldsm4(kf, sb + so);
                uint32_t b0[2] = {kf[0], kf[1]}, b1[2] = {kf[2], kf[3]};
                mma_fp(s[2*p],   qf[ks], b0);
                mma_fp(s[2*p+1], qf[ks], b1);
            }
        }

        // ---- exp2 (poly), pack P fp16, PV mma ----
#pragma unroll
        for (int kk = 0; kk < 4; kk++) {
            float* e0 = s[2*kk];
            float* e1 = s[2*kk+1];
#pragma unroll
            for (int j = 0; j < 4; j++) { e0[j] = fexp2(e0[j]); e1[j] = fexp2(e1[j]); }
            lsum0 += e0[0] + e0[1] + e1[0] + e1[1];
            lsum1 += e0[2] + e0[3] + e1[2] + e1[3];
            uint32_t ph[4];
            ph[0] = packh(e0[1], e0[0]); ph[1] = packh(e0[3], e0[2]);
            ph[2] = packh(e1[1], e1[0]); ph[3] = packh(e1[3], e1[2]);
#pragma unroll
            for (int q = 0; q < 4; q++) {
                int row = kk * 16 + (lane & 15);
                int ch = q * 2 + (lane >> 4);
                uint32_t so = soff64(row, ch);
                uint32_t vf[4];
                ldsm4t(vf, sb + 8192 + so);
                uint32_t b0[2] = {vf[0], vf[1]}, b1[2] = {vf[2], vf[3]};
                mma_fp(o[2*q],   ph, b0);
                mma_fp(o[2*q+1], ph, b1);
            }
        }
        __syncthreads();
    }

    lsum0 += __shfl_xor_sync(0xffffffffu, lsum0, 1);
    lsum0 += __shfl_xor_sync(0xffffffffu, lsum0, 2);
    lsum1 += __shfl_xor_sync(0xffffffffu, lsum1, 1);
    lsum1 += __shfl_xor_sync(0xffffffffu, lsum1, 2);
    const float inv0 = 1.f / lsum0, inv1 = 1.f / lsum1;

    const int row0 = q0 + w * 16 + (lane >> 2);
#pragma unroll
    for (int nt = 0; nt < 8; nt++) {
        int col = h * HD + nt * 8 + (lane & 3) * 2;
        float v0 = o[nt][0] * inv0, v1 = o[nt][1] * inv0;
        float v2 = o[nt][2] * inv1, v3 = o[nt][3] * inv1;
        uint32_t hA = packbf(v1, v0), hB = packbf(v3, v2);
        *(uint32_t*)&AOh[((size_t)(b * NQ + row0)) * QD + col] = hA;
        *(uint32_t*)&AOh[((size_t)(b * NQ + row0 + 8)) * QD + col] = hB;
        float l0 = v0 - __uint_as_float(hA << 16);
        float l1 = v1 - __uint_as_float(hA & 0xFFFF0000u);
        float l2 = v2 - __uint_as_float(hB << 16);
        float l3 = v3 - __uint_as_float(hB & 0xFFFF0000u);
        *(uint32_t*)&AOl[((size_t)(b * NQ + row0)) * QD + col] = packbf(l1, l0);
        *(uint32_t*)&AOl[((size_t)(b * NQ + row0 + 8)) * QD + col] = packbf(l3, l2);
    }
}

// ============ kernel_launch ============
extern "C" void kernel_launch(void* const* d_in, const int* in_sizes, int n_in,
                              void* d_out, int out_size)
{
    const float* query = (const float*)d_in[0];
    const float* key   = (const float*)d_in[1];
    const float* value = (const float*)d_in[2];
    const float* Wq = (const float*)d_in[3];  const float* bq = (const float*)d_in[4];
    const float* Wk = (const float*)d_in[5];  const float* bk = (const float*)d_in[6];
    const float* Wv = (const float*)d_in[7];  const float* bv = (const float*)d_in[8];
    const float* Wo = (const float*)d_in[9];  const float* bo = (const float*)d_in[10];
    float* out = (float*)d_out;

    __nv_bfloat16 *qh,*ql,*kh,*kl,*vh,*vl;
    __nv_bfloat16 *wqh,*wql,*wkh,*wkl,*wvh,*wvl,*woh,*wol,*aoh,*aol;
    __half *Qp,*Kp,*Vp;
    cudaGetSymbolAddress((void**)&qh, g_qh);   cudaGetSymbolAddress((void**)&ql, g_ql);
    cudaGetSymbolAddress((void**)&kh, g_kh);   cudaGetSymbolAddress((void**)&kl, g_kl);
    cudaGetSymbolAddress((void**)&vh, g_vh);   cudaGetSymbolAddress((void**)&vl, g_vl);
    cudaGetSymbolAddress((void**)&wqh, g_wqh); cudaGetSymbolAddress((void**)&wql, g_wql);
    cudaGetSymbolAddress((void**)&wkh, g_wkh); cudaGetSymbolAddress((void**)&wkl, g_wkl);
    cudaGetSymbolAddress((void**)&wvh, g_wvh); cudaGetSymbolAddress((void**)&wvl, g_wvl);
    cudaGetSymbolAddress((void**)&woh, g_woh); cudaGetSymbolAddress((void**)&wol, g_wol);
    cudaGetSymbolAddress((void**)&Qp, g_Qp);   cudaGetSymbolAddress((void**)&Kp, g_Kp);
    cudaGetSymbolAddress((void**)&Vp, g_Vp);
    cudaGetSymbolAddress((void**)&aoh, g_aoh); cudaGetSymbolAddress((void**)&aol, g_aol);

    cudaFuncSetAttribute(gemm_mma, cudaFuncAttributeMaxDynamicSharedMemorySize, GEMM_SMEM);
    cudaFuncSetAttribute(attn_tc,  cudaFuncAttributeMaxDynamicSharedMemorySize, ATTN_SMEM);

    const int MQ = BATCH * NQ;   // 16384
    const int MK = BATCH * NK;   // 4096

    split_in<<<dim3(MQ*QD/4/256, 1, 3), 256>>>(query, key, value);
    wsplit_all<<<dim3(QD/32, QD/32, 4), 256>>>(Wq, Wk, Wv, Wo);
    gemm_mma<<<dim3(QD/128, MQ/128), 256, GEMM_SMEM>>>(
        qh, ql, wqh, wql, bq, nullptr, Qp, QSCALE, MQ, QD, QD);
    gemm_mma<<<dim3(QD/128, MK/128), 256, GEMM_SMEM>>>(
        kh, kl, wkh, wkl, bk, nullptr, Kp, 1.0f, MK, QD, KD);
    gemm_mma<<<dim3(QD/128, MK/128), 256, GEMM_SMEM>>>(
        vh, vl, wvh, wvl, bv, nullptr, Vp, 1.0f, MK, QD, KD);
    attn_tc<<<dim3(NQ/128, NH, BATCH), 256, ATTN_SMEM>>>(Qp, Kp, Vp, aoh, aol);
    gemm_mma<<<dim3(QD/128, MQ/128), 256, GEMM_SMEM>>>(
        aoh, aol, woh, wol, bo, out, nullptr, 1.0f, MQ, QD, QD);
}

// round 8
// speedup vs baseline: 11.2897x; 1.1738x over previous
#include <cuda_runtime.h>
#include <cuda_bf16.h>
#include <cuda_fp16.h>
#include <cstdint>

#define BATCH 4
#define NQ    4096
#define NK    1024
#define NH    16
#define HD    64
#define QD    1024
#define KD    768
#define QSCALE 0.1803368801f   // 0.125 * log2(e), folded into Q proj

// ---------------- helpers ----------------
__device__ __forceinline__ uint32_t smem_u32(const void* p) {
    uint32_t a;
    asm("{ .reg .u64 t; cvta.to.shared.u64 t, %1; cvt.u32.u64 %0, t; }" : "=r"(a) : "l"(p));
    return a;
}
__device__ __forceinline__ void cpa16(uint32_t s, const void* g) {
    asm volatile("cp.async.cg.shared.global [%0], [%1], 16;" :: "r"(s), "l"(g));
}
#define CP_COMMIT() asm volatile("cp.async.commit_group;" ::: "memory")
#define CP_WAIT(n)  asm volatile("cp.async.wait_group %0;" :: "n"(n) : "memory")
__device__ __forceinline__ void ldsm4(uint32_t* r, uint32_t a) {
    asm volatile("ldmatrix.sync.aligned.m8n8.x4.shared.b16 {%0,%1,%2,%3}, [%4];"
        : "=r"(r[0]), "=r"(r[1]), "=r"(r[2]), "=r"(r[3]) : "r"(a));
}
__device__ __forceinline__ void ldsm4t(uint32_t* r, uint32_t a) {
    asm volatile("ldmatrix.sync.aligned.m8n8.x4.trans.shared.b16 {%0,%1,%2,%3}, [%4];"
        : "=r"(r[0]), "=r"(r[1]), "=r"(r[2]), "=r"(r[3]) : "r"(a));
}
__device__ __forceinline__ void mma_bf(float* d, const uint32_t* a, const uint32_t* b) {
    asm volatile("mma.sync.aligned.m16n8k16.row.col.f32.bf16.bf16.f32 "
        "{%0,%1,%2,%3}, {%4,%5,%6,%7}, {%8,%9}, {%0,%1,%2,%3};"
        : "+f"(d[0]), "+f"(d[1]), "+f"(d[2]), "+f"(d[3])
        : "r"(a[0]), "r"(a[1]), "r"(a[2]), "r"(a[3]), "r"(b[0]), "r"(b[1]));
}
__device__ __forceinline__ void mma_fp(float* d, const uint32_t* a, const uint32_t* b) {
    asm volatile("mma.sync.aligned.m16n8k16.row.col.f32.f16.f16.f32 "
        "{%0,%1,%2,%3}, {%4,%5,%6,%7}, {%8,%9}, {%0,%1,%2,%3};"
        : "+f"(d[0]), "+f"(d[1]), "+f"(d[2]), "+f"(d[3])
        : "r"(a[0]), "r"(a[1]), "r"(a[2]), "r"(a[3]), "r"(b[0]), "r"(b[1]));
}
__device__ __forceinline__ uint32_t packbf(float hi, float lo) {
    uint32_t r;
    asm("cvt.rn.bf16x2.f32 %0, %1, %2;" : "=r"(r) : "f"(hi), "f"(lo));
    return r;
}
__device__ __forceinline__ uint32_t packh(float hi, float lo) {
    uint32_t r;
    asm("cvt.rn.f16x2.f32 %0, %1, %2;" : "=r"(r) : "f"(hi), "f"(lo));
    return r;
}
// swizzled offset in [rows][32]halfwords (64B rows, 4 chunks)
__device__ __forceinline__ uint32_t soff(int row, int chunk) {
    return (uint32_t)(row * 64 + ((chunk ^ ((row >> 1) & 3)) << 4));
}
// swizzled offset in [rows][64]halfwords (128B rows, 8 chunks)
__device__ __forceinline__ uint32_t soff64(int row, int ch) {
    return (uint32_t)(row * 128 + ((ch ^ (row & 7)) << 4));
}
// 2^z via deg-6 poly + exponent injection (no MUFU)
__device__ __forceinline__ float fexp2(float z) {
    z = fmaxf(z, -60.f);
    float fi = floorf(z);
    float f = z - fi;
    float p = 1.54035e-4f;
    p = fmaf(p, f, 1.33336e-3f);
    p = fmaf(p, f, 9.61813e-3f);
    p = fmaf(p, f, 5.55041e-2f);
    p = fmaf(p, f, 2.40227e-1f);
    p = fmaf(p, f, 6.9314718e-1f);
    p = fmaf(p, f, 1.0f);
    int i = (int)fi;
    return __int_as_float(__float_as_int(p) + (i << 23));
}

// ---------------- scratch ----------------
#define AL16 __align__(16)
// q input split fp16 hi/lo (for fp16 2-product Q proj)
__device__ AL16 __half g_qh16[(size_t)BATCH*NQ*QD], g_ql16[(size_t)BATCH*NQ*QD];
// k/v input splits bf16 hi/lo (for bf16 3-product K/V proj)
__device__ AL16 __nv_bfloat16 g_kh[(size_t)BATCH*NK*KD], g_kl[(size_t)BATCH*NK*KD];
__device__ AL16 __nv_bfloat16 g_vh[(size_t)BATCH*NK*KD], g_vl[(size_t)BATCH*NK*KD];
// weights: Wq/Wo single fp16 transposed; Wk/Wv bf16 hi/lo transposed
__device__ AL16 __half g_wq16[(size_t)QD*QD], g_wo16[(size_t)QD*QD];
__device__ AL16 __nv_bfloat16 g_wkh[(size_t)QD*KD], g_wkl[(size_t)QD*KD];
__device__ AL16 __nv_bfloat16 g_wvh[(size_t)QD*KD], g_wvl[(size_t)QD*KD];
// projected Q/K/V fp16
__device__ AL16 __half g_Qp[(size_t)BATCH*NQ*QD];
__device__ AL16 __half g_Kp[(size_t)BATCH*NK*QD];
__device__ AL16 __half g_Vp[(size_t)BATCH*NK*QD];
// attention out fp16 hi/lo
__device__ AL16 __half g_aoh16[(size_t)BATCH*NQ*QD], g_aol16[(size_t)BATCH*NQ*QD];

// ============ fused input split ============
__global__ __launch_bounds__(256) void split_in(
    const float* __restrict__ q, const float* __restrict__ k, const float* __restrict__ v)
{
    int z = blockIdx.z;
    int i = blockIdx.x * 256 + threadIdx.x;
    if (z == 0) {
        if (i >= BATCH*NQ*QD/4) return;
        float4 val = ((const float4*)q)[i];
        __half h0 = __float2half_rn(val.x), h1 = __float2half_rn(val.y);
        __half h2 = __float2half_rn(val.z), h3 = __float2half_rn(val.w);
        uint32_t a = ((uint32_t)__half_as_ushort(h1) << 16) | __half_as_ushort(h0);
        uint32_t b = ((uint32_t)__half_as_ushort(h3) << 16) | __half_as_ushort(h2);
        ((uint32_t*)g_qh16)[2*i] = a; ((uint32_t*)g_qh16)[2*i+1] = b;
        ((uint32_t*)g_ql16)[2*i] = packh(val.y - __half2float(h1), val.x - __half2float(h0));
        ((uint32_t*)g_ql16)[2*i+1] = packh(val.w - __half2float(h3), val.z - __half2float(h2));
    } else {
        const float* x = (z == 1) ? k : v;
        __nv_bfloat16* hi = (z == 1) ? g_kh : g_vh;
        __nv_bfloat16* lo = (z == 1) ? g_kl : g_vl;
        if (i >= BATCH*NK*KD/4) return;
        float4 val = ((const float4*)x)[i];
        uint32_t h01 = packbf(val.y, val.x), h23 = packbf(val.w, val.z);
        ((uint32_t*)hi)[2*i] = h01; ((uint32_t*)hi)[2*i+1] = h23;
        float l0 = val.x - __uint_as_float(h01 << 16);
        float l1 = val.y - __uint_as_float(h01 & 0xFFFF0000u);
        float l2 = val.z - __uint_as_float(h23 << 16);
        float l3 = val.w - __uint_as_float(h23 & 0xFFFF0000u);
        ((uint32_t*)lo)[2*i] = packbf(l1, l0); ((uint32_t*)lo)[2*i+1] = packbf(l3, l2);
    }
}

// ============ fused weight transpose+split ============
__global__ __launch_bounds__(256) void wsplit_all(
    const float* __restrict__ Wq, const float* __restrict__ Wk,
    const float* __restrict__ Wv, const float* __restrict__ Wo)
{
    int z = blockIdx.z;
    const float* W; int K = QD;
    __half* T16 = nullptr; __nv_bfloat16 *Th = nullptr, *Tl = nullptr;
    if (z == 0)      { W = Wq; T16 = g_wq16; }
    else if (z == 1) { W = Wk; Th = g_wkh; Tl = g_wkl; K = KD; }
    else if (z == 2) { W = Wv; Th = g_wvh; Tl = g_wvl; K = KD; }
    else             { W = Wo; T16 = g_wo16; }
    const int N = QD;
    const int nb = blockIdx.x * 32, kb = blockIdx.y * 32;
    if (kb >= K) return;
    __shared__ float tile[32][33];
    const int tx = threadIdx.x & 31, tg = threadIdx.x >> 5;
#pragma unroll
    for (int r = 0; r < 4; r++) {
        int kk = tg + r * 8;
        tile[kk][tx] = W[(size_t)(kb + kk) * N + nb + tx];
    }
    __syncthreads();
#pragma unroll
    for (int r = 0; r < 4; r++) {
        int n = tg + r * 8;
        float v = tile[tx][n];
        if (T16) {
            T16[(size_t)(nb + n) * K + kb + tx] = __float2half_rn(v);
        } else {
            __nv_bfloat16 h = __float2bfloat16_rn(v);
            Th[(size_t)(nb + n) * K + kb + tx] = h;
            Tl[(size_t)(nb + n) * K + kb + tx] = __float2bfloat16_rn(v - __bfloat162float(h));
        }
    }
}

// ============ bf16 3-product GEMM (K/V proj), 3-stage pipeline ============
#define B3_AH 0
#define B3_AL 8192
#define B3_BH 16384
#define B3_BL 24576
#define B3_STG 32768
#define B3_SMEM (3 * B3_STG)

__global__ __launch_bounds__(256, 2) void gemm_bf3(
    const __nv_bfloat16* __restrict__ Ah, const __nv_bfloat16* __restrict__ Al,
    const __nv_bfloat16* __restrict__ Bh, const __nv_bfloat16* __restrict__ Bl,
    const float* __restrict__ bias, __half* __restrict__ C16,
    int M, int N, int K)
{
    extern __shared__ char sm[];
    const uint32_t smb = smem_u32(sm);
    const int t = threadIdx.x, wid = t >> 5, lane = t & 31;
    const int m0 = blockIdx.y * 128, n0 = blockIdx.x * 128;
    const int NC = K >> 5;
    const int wm = (wid & 1) * 64, wn = (wid >> 1) * 32;
    const int lrow = t >> 1, lch0 = (t & 1) * 2;

    auto load_stage = [&](int c) {
        const int kt = c << 5;
        const uint32_t sb = smb + (c % 3) * B3_STG;
#pragma unroll
        for (int j = 0; j < 2; j++) {
            int ch = lch0 + j;
            uint32_t so = soff(lrow, ch);
            size_t ga = (size_t)(m0 + lrow) * K + kt + ch * 8;
            size_t gb = (size_t)(n0 + lrow) * K + kt + ch * 8;
            cpa16(sb + B3_AH + so, Ah + ga);
            cpa16(sb + B3_AL + so, Al + ga);
            cpa16(sb + B3_BH + so, Bh + gb);
            cpa16(sb + B3_BL + so, Bl + gb);
        }
        CP_COMMIT();
    };

    float d[4][4][4];
#pragma unroll
    for (int i = 0; i < 4; i++)
#pragma unroll
        for (int j = 0; j < 4; j++)
#pragma unroll
            for (int k = 0; k < 4; k++) d[i][j][k] = 0.f;

    load_stage(0); load_stage(1);

    for (int c = 0; c < NC; c++) {
        if (c + 2 < NC) { load_stage(c + 2); CP_WAIT(2); }
        else if (c == NC - 2) CP_WAIT(1);
        else CP_WAIT(0);
        __syncthreads();

        const uint32_t sb = smb + (c % 3) * B3_STG;
#pragma unroll
        for (int ks = 0; ks < 2; ks++) {
            const int kc = ks * 2;
            uint32_t ahf[4][4], alf[4][4];
#pragma unroll
            for (int mt = 0; mt < 4; mt++) {
                int row = wm + mt * 16 + (lane & 15);
                int ch = kc + (lane >> 4);
                uint32_t so = soff(row, ch);
                ldsm4(ahf[mt], sb + B3_AH + so);
                ldsm4(alf[mt], sb + B3_AL + so);
            }
            uint32_t bhf[4][2], blf[4][2];
#pragma unroll
            for (int p = 0; p < 2; p++) {
                int nrow = wn + p * 16 + ((lane >> 4) & 1) * 8 + (lane & 7);
                int ch = kc + ((lane >> 3) & 1);
                uint32_t so = soff(nrow, ch);
                uint32_t r[4];
                ldsm4(r, sb + B3_BH + so);
                bhf[p*2][0] = r[0]; bhf[p*2][1] = r[1];
                bhf[p*2+1][0] = r[2]; bhf[p*2+1][1] = r[3];
                ldsm4(r, sb + B3_BL + so);
                blf[p*2][0] = r[0]; blf[p*2][1] = r[1];
                blf[p*2+1][0] = r[2]; blf[p*2+1][1] = r[3];
            }
#pragma unroll
            for (int mt = 0; mt < 4; mt++)
#pragma unroll
                for (int nt = 0; nt < 4; nt++) {
                    mma_bf(d[mt][nt], ahf[mt], bhf[nt]);
                    mma_bf(d[mt][nt], alf[mt], bhf[nt]);
                    mma_bf(d[mt][nt], ahf[mt], blf[nt]);
                }
        }
        __syncthreads();
    }

    const int lr = lane >> 2, lc = (lane & 3) * 2;
#pragma unroll
    for (int mt = 0; mt < 4; mt++) {
        int row = m0 + wm + mt * 16 + lr;
#pragma unroll
        for (int nt = 0; nt < 4; nt++) {
            int col = n0 + wn + nt * 8 + lc;
            float b0 = __ldg(bias + col), b1 = __ldg(bias + col + 1);
            *(uint32_t*)&C16[(size_t)row * N + col] = packh(d[mt][nt][1] + b1, d[mt][nt][0] + b0);
            *(uint32_t*)&C16[(size_t)(row + 8) * N + col] = packh(d[mt][nt][3] + b1, d[mt][nt][2] + b0);
        }
    }
}

// ============ fp16 2-product GEMM (Q/O proj), 4-stage pipeline ============
// C = (Ah+Al)[M,K] @ B[N,K]^T + bias, *scale.  A hi/lo fp16, B single fp16.
#define F2_AH 0
#define F2_AL 8192
#define F2_B  16384
#define F2_STG 24576
#define F2_SMEM (4 * F2_STG)

__global__ __launch_bounds__(256, 2) void gemm_fp2(
    const __half* __restrict__ Ah, const __half* __restrict__ Al,
    const __half* __restrict__ B,
    const float* __restrict__ bias, float* __restrict__ Cf,
    __half* __restrict__ C16, float scale, int M, int N, int K)
{
    extern __shared__ char sm[];
    const uint32_t smb = smem_u32(sm);
    const int t = threadIdx.x, wid = t >> 5, lane = t & 31;
    const int m0 = blockIdx.y * 128, n0 = blockIdx.x * 128;
    const int NC = K >> 5;
    const int wm = (wid & 1) * 64, wn = (wid >> 1) * 32;
    const int lrow = t >> 1, lch0 = (t & 1) * 2;

    auto load_stage = [&](int c) {
        const int kt = c << 5;
        const uint32_t sb = smb + (c & 3) * F2_STG;
#pragma unroll
        for (int j = 0; j < 2; j++) {
            int ch = lch0 + j;
            uint32_t so = soff(lrow, ch);
            size_t ga = (size_t)(m0 + lrow) * K + kt + ch * 8;
            size_t gb = (size_t)(n0 + lrow) * K + kt + ch * 8;
            cpa16(sb + F2_AH + so, Ah + ga);
            cpa16(sb + F2_AL + so, Al + ga);
            cpa16(sb + F2_B  + so, B + gb);
        }
        CP_COMMIT();
    };

    float d[4][4][4];
#pragma unroll
    for (int i = 0; i < 4; i++)
#pragma unroll
        for (int j = 0; j < 4; j++)
#pragma unroll
            for (int k = 0; k < 4; k++) d[i][j][k] = 0.f;

    load_stage(0); load_stage(1); load_stage(2);

    for (int c = 0; c < NC; c++) {
        if (c + 3 < NC) { load_stage(c + 3); CP_WAIT(3); }
        else if (c == NC - 3) CP_WAIT(2);
        else if (c == NC - 2) CP_WAIT(1);
        else CP_WAIT(0);
        __syncthreads();

        const uint32_t sb = smb + (c & 3) * F2_STG;
#pragma unroll
        for (int ks = 0; ks < 2; ks++) {
            const int kc = ks * 2;
            uint32_t ahf[4][4], alf[4][4];
#pragma unroll
            for (int mt = 0; mt < 4; mt++) {
                int row = wm + mt * 16 + (lane & 15);
                int ch = kc + (lane >> 4);
                uint32_t so = soff(row, ch);
                ldsm4(ahf[mt], sb + F2_AH + so);
                ldsm4(alf[mt], sb + F2_AL + so);
            }
            uint32_t bf[4][2];
#pragma unroll
            for (int p = 0; p < 2; p++) {
                int nrow = wn + p * 16 + ((lane >> 4) & 1) * 8 + (lane & 7);
                int ch = kc + ((lane >> 3) & 1);
                uint32_t so = soff(nrow, ch);
                uint32_t r[4];
                ldsm4(r, sb + F2_B + so);
                bf[p*2][0] = r[0]; bf[p*2][1] = r[1];
                bf[p*2+1][0] = r[2]; bf[p*2+1][1] = r[3];
            }
#pragma unroll
            for (int mt = 0; mt < 4; mt++)
#pragma unroll
                for (int nt = 0; nt < 4; nt++) {
                    mma_fp(d[mt][nt], ahf[mt], bf[nt]);
                    mma_fp(d[mt][nt], alf[mt], bf[nt]);
                }
        }
        __syncthreads();
    }

    const int lr = lane >> 2, lc = (lane & 3) * 2;
#pragma unroll
    for (int mt = 0; mt < 4; mt++) {
        int row = m0 + wm + mt * 16 + lr;
#pragma unroll
        for (int nt = 0; nt < 4; nt++) {
            int col = n0 + wn + nt * 8 + lc;
            float b0 = __ldg(bias + col), b1 = __ldg(bias + col + 1);
            float v0 = (d[mt][nt][0] + b0) * scale, v1 = (d[mt][nt][1] + b1) * scale;
            float v2 = (d[mt][nt][2] + b0) * scale, v3 = (d[mt][nt][3] + b1) * scale;
            if (Cf) {
                *(float2*)&Cf[(size_t)row * N + col] = make_float2(v0, v1);
                *(float2*)&Cf[(size_t)(row + 8) * N + col] = make_float2(v2, v3);
            } else {
                *(uint32_t*)&C16[(size_t)row * N + col] = packh(v1, v0);
                *(uint32_t*)&C16[(size_t)(row + 8) * N + col] = packh(v3, v2);
            }
        }
    }
}

// ============ tensor-core flash attention, fp16, kv-chunk 64, 4-stage ============
#define ATS 16384
#define AT_Q (4 * ATS)
#define ATTN_SMEM (4 * ATS + 16384)
#define NCH (NK / 64)   // 16 chunks

__global__ __launch_bounds__(256, 2) void attn_tc(
    const __half* __restrict__ Qp, const __half* __restrict__ Kp,
    const __half* __restrict__ Vp,
    __half* __restrict__ AOh, __half* __restrict__ AOl)
{
    extern __shared__ char sm[];
    const uint32_t smb = smem_u32(sm);
    const int t = threadIdx.x, w = t >> 5, lane = t & 31;
    const int q0 = blockIdx.x * 128, h = blockIdx.y, b = blockIdx.z;
    const size_t qbase = ((size_t)(b * NQ + q0)) * QD + h * HD;
    const size_t kbase = ((size_t)(b * NK)) * QD + h * HD;

    auto ld_stage = [&](int c) {
        const uint32_t sb = smb + (c & 3) * ATS;
        const int n0 = c << 6;
#pragma unroll
        for (int j = 0; j < 2; j++) {
            int u = t + j * 256;
            int row = u >> 3, ch = u & 7;
            uint32_t so = soff64(row, ch);
            size_t g = kbase + (size_t)(n0 + row) * QD + ch * 8;
            cpa16(sb + so, Kp + g);
            cpa16(sb + 8192 + so, Vp + g);
        }
        CP_COMMIT();
    };

#pragma unroll
    for (int j = 0; j < 4; j++) {
        int u = t + j * 256;
        int row = u >> 3, ch = u & 7;
        uint32_t so = soff64(row, ch);
        cpa16(smb + AT_Q + so, Qp + qbase + (size_t)row * QD + ch * 8);
    }
    ld_stage(0); ld_stage(1); ld_stage(2);

    uint32_t qf[4][4];
    float s[8][4];
    float o[8][4];
    float lsum0 = 0.f, lsum1 = 0.f;
#pragma unroll
    for (int i = 0; i < 8; i++)
#pragma unroll
        for (int j = 0; j < 4; j++) o[i][j] = 0.f;

    for (int c = 0; c < NCH; c++) {
        if (c + 3 < NCH) { ld_stage(c + 3); CP_WAIT(3); }
        else if (c == NCH - 3) CP_WAIT(2);
        else if (c == NCH - 2) CP_WAIT(1);
        else CP_WAIT(0);
        __syncthreads();

        if (c == 0) {
#pragma unroll
            for (int ks = 0; ks < 4; ks++) {
                int row = w * 16 + (lane & 15);
                uint32_t so = soff64(row, ks * 2 + (lane >> 4));
                ldsm4(qf[ks], smb + AT_Q + so);
            }
        }
        const uint32_t sb = smb + (c & 3) * ATS;

#pragma unroll
        for (int sn = 0; sn < 8; sn++) {
            s[sn][0] = 0.f; s[sn][1] = 0.f; s[sn][2] = 0.f; s[sn][3] = 0.f;
        }
#pragma unroll
        for (int ks = 0; ks < 4; ks++) {
#pragma unroll
            for (int p = 0; p < 4; p++) {
                int nrow = p * 16 + ((lane >> 4) & 1) * 8 + (lane & 7);
                int ch = ks * 2 + ((lane >> 3) & 1);
                uint32_t so = soff64(nrow, ch);
                uint32_t kf[4];
                ldsm4(kf, sb + so);
                uint32_t b0[2] = {kf[0], kf[1]}, b1[2] = {kf[2], kf[3]};
                mma_fp(s[2*p],   qf[ks], b0);
                mma_fp(s[2*p+1], qf[ks], b1);
            }
        }

#pragma unroll
        for (int kk = 0; kk < 4; kk++) {
            float* e0 = s[2*kk];
            float* e1 = s[2*kk+1];
#pragma unroll
            for (int j = 0; j < 4; j++) { e0[j] = fexp2(e0[j]); e1[j] = fexp2(e1[j]); }
            lsum0 += e0[0] + e0[1] + e1[0] + e1[1];
            lsum1 += e0[2] + e0[3] + e1[2] + e1[3];
            uint32_t ph[4];
            ph[0] = packh(e0[1], e0[0]); ph[1] = packh(e0[3], e0[2]);
            ph[2] = packh(e1[1], e1[0]); ph[3] = packh(e1[3], e1[2]);
#pragma unroll
            for (int q = 0; q < 4; q++) {
                int row = kk * 16 + (lane & 15);
                int ch = q * 2 + (lane >> 4);
                uint32_t so = soff64(row, ch);
                uint32_t vf[4];
                ldsm4t(vf, sb + 8192 + so);
                uint32_t b0[2] = {vf[0], vf[1]}, b1[2] = {vf[2], vf[3]};
                mma_fp(o[2*q],   ph, b0);
                mma_fp(o[2*q+1], ph, b1);
            }
        }
        __syncthreads();
    }

    lsum0 += __shfl_xor_sync(0xffffffffu, lsum0, 1);
    lsum0 += __shfl_xor_sync(0xffffffffu, lsum0, 2);
    lsum1 += __shfl_xor_sync(0xffffffffu, lsum1, 1);
    lsum1 += __shfl_xor_sync(0xffffffffu, lsum1, 2);
    const float inv0 = 1.f / lsum0, inv1 = 1.f / lsum1;

    const int row0 = q0 + w * 16 + (lane >> 2);
#pragma unroll
    for (int nt = 0; nt < 8; nt++) {
        int col = h * HD + nt * 8 + (lane & 3) * 2;
        float v0 = o[nt][0] * inv0, v1 = o[nt][1] * inv0;
        float v2 = o[nt][2] * inv1, v3 = o[nt][3] * inv1;
        __half h0 = __float2half_rn(v0), h1 = __float2half_rn(v1);
        __half h2 = __float2half_rn(v2), h3 = __float2half_rn(v3);
        uint32_t hA = ((uint32_t)__half_as_ushort(h1) << 16) | __half_as_ushort(h0);
        uint32_t hB = ((uint32_t)__half_as_ushort(h3) << 16) | __half_as_ushort(h2);
        *(uint32_t*)&AOh[((size_t)(b * NQ + row0)) * QD + col] = hA;
        *(uint32_t*)&AOh[((size_t)(b * NQ + row0 + 8)) * QD + col] = hB;
        *(uint32_t*)&AOl[((size_t)(b * NQ + row0)) * QD + col] =
            packh(v1 - __half2float(h1), v0 - __half2float(h0));
        *(uint32_t*)&AOl[((size_t)(b * NQ + row0 + 8)) * QD + col] =
            packh(v3 - __half2float(h3), v2 - __half2float(h2));
    }
}

// ============ kernel_launch ============
extern "C" void kernel_launch(void* const* d_in, const int* in_sizes, int n_in,
                              void* d_out, int out_size)
{
    const float* query = (const float*)d_in[0];
    const float* key   = (const float*)d_in[1];
    const float* value = (const float*)d_in[2];
    const float* Wq = (const float*)d_in[3];  const float* bq = (const float*)d_in[4];
    const float* Wk = (const float*)d_in[5];  const float* bk = (const float*)d_in[6];
    const float* Wv = (const float*)d_in[7];  const float* bv = (const float*)d_in[8];
    const float* Wo = (const float*)d_in[9];  const float* bo = (const float*)d_in[10];
    float* out = (float*)d_out;

    __half *qh16,*ql16,*wq16,*wo16,*Qp,*Kp,*Vp,*aoh16,*aol16;
    __nv_bfloat16 *kh,*kl,*vh,*vl,*wkh,*wkl,*wvh,*wvl;
    cudaGetSymbolAddress((void**)&qh16, g_qh16); cudaGetSymbolAddress((void**)&ql16, g_ql16);
    cudaGetSymbolAddress((void**)&kh, g_kh);     cudaGetSymbolAddress((void**)&kl, g_kl);
    cudaGetSymbolAddress((void**)&vh, g_vh);     cudaGetSymbolAddress((void**)&vl, g_vl);
    cudaGetSymbolAddress((void**)&wq16, g_wq16); cudaGetSymbolAddress((void**)&wo16, g_wo16);
    cudaGetSymbolAddress((void**)&wkh, g_wkh);   cudaGetSymbolAddress((void**)&wkl, g_wkl);
    cudaGetSymbolAddress((void**)&wvh, g_wvh);   cudaGetSymbolAddress((void**)&wvl, g_wvl);
    cudaGetSymbolAddress((void**)&Qp, g_Qp);     cudaGetSymbolAddress((void**)&Kp, g_Kp);
    cudaGetSymbolAddress((void**)&Vp, g_Vp);
    cudaGetSymbolAddress((void**)&aoh16, g_aoh16); cudaGetSymbolAddress((void**)&aol16, g_aol16);

    cudaFuncSetAttribute(gemm_bf3, cudaFuncAttributeMaxDynamicSharedMemorySize, B3_SMEM);
    cudaFuncSetAttribute(gemm_fp2, cudaFuncAttributeMaxDynamicSharedMemorySize, F2_SMEM);
    cudaFuncSetAttribute(attn_tc,  cudaFuncAttributeMaxDynamicSharedMemorySize, ATTN_SMEM);

    const int MQ = BATCH * NQ;   // 16384
    const int MK = BATCH * NK;   // 4096

    // launch 0-1: splits
    split_in<<<dim3(MQ*QD/4/256, 1, 3), 256>>>(query, key, value);
    wsplit_all<<<dim3(QD/32, QD/32, 4), 256>>>(Wq, Wk, Wv, Wo);
    // launch 2: Q proj (fp16 2-product, QSCALE folded)
    gemm_fp2<<<dim3(QD/128, MQ/128), 256, F2_SMEM>>>(
        qh16, ql16, wq16, bq, nullptr, Qp, QSCALE, MQ, QD, QD);
    // launches 3-4: K/V proj (bf16 3-product)
    gemm_bf3<<<dim3(QD/128, MK/128), 256, B3_SMEM>>>(
        kh, kl, wkh, wkl, bk, Kp, MK, QD, KD);
    gemm_bf3<<<dim3(QD/128, MK/128), 256, B3_SMEM>>>(
        vh, vl, wvh, wvl, bv, Vp, MK, QD, KD);
    // launch 5: attention (ncu -s 5 -c 1 captures this)
    attn_tc<<<dim3(NQ/128, NH, BATCH), 256, ATTN_SMEM>>>(Qp, Kp, Vp, aoh16, aol16);
    // launch 6: O proj (fp16 2-product) -> fp32 d_out
    gemm_fp2<<<dim3(QD/128, MQ/128), 256, F2_SMEM>>>(
        aoh16, aol16, wo16, bo, out, nullptr, 1.0f, MQ, QD, QD);
}

// round 9
// speedup vs baseline: 16.2460x; 1.4390x over previous
#include <cuda_runtime.h>
#include <cuda_fp16.h>
#include <cstdint>

#define BATCH 4
#define NQ    4096
#define NK    1024
#define NH    16
#define HD    64
#define QD    1024
#define KD    768
#define QSCALE 0.1803368801f   // 0.125 * log2(e), folded into Q proj epilogue

// ---------------- helpers ----------------
__device__ __forceinline__ uint32_t smem_u32(const void* p) {
    uint32_t a;
    asm("{ .reg .u64 t; cvta.to.shared.u64 t, %1; cvt.u32.u64 %0, t; }" : "=r"(a) : "l"(p));
    return a;
}
__device__ __forceinline__ void cpa16(uint32_t s, const void* g) {
    asm volatile("cp.async.cg.shared.global [%0], [%1], 16;" :: "r"(s), "l"(g));
}
#define CP_COMMIT() asm volatile("cp.async.commit_group;" ::: "memory")
#define CP_WAIT(n)  asm volatile("cp.async.wait_group %0;" :: "n"(n) : "memory")
__device__ __forceinline__ void ldsm4(uint32_t* r, uint32_t a) {
    asm volatile("ldmatrix.sync.aligned.m8n8.x4.shared.b16 {%0,%1,%2,%3}, [%4];"
        : "=r"(r[0]), "=r"(r[1]), "=r"(r[2]), "=r"(r[3]) : "r"(a));
}
__device__ __forceinline__ void ldsm4t(uint32_t* r, uint32_t a) {
    asm volatile("ldmatrix.sync.aligned.m8n8.x4.trans.shared.b16 {%0,%1,%2,%3}, [%4];"
        : "=r"(r[0]), "=r"(r[1]), "=r"(r[2]), "=r"(r[3]) : "r"(a));
}
__device__ __forceinline__ void mma_fp(float* d, const uint32_t* a, const uint32_t* b) {
    asm volatile("mma.sync.aligned.m16n8k16.row.col.f32.f16.f16.f32 "
        "{%0,%1,%2,%3}, {%4,%5,%6,%7}, {%8,%9}, {%0,%1,%2,%3};"
        : "+f"(d[0]), "+f"(d[1]), "+f"(d[2]), "+f"(d[3])
        : "r"(a[0]), "r"(a[1]), "r"(a[2]), "r"(a[3]), "r"(b[0]), "r"(b[1]));
}
__device__ __forceinline__ uint32_t packh(float hi, float lo) {
    uint32_t r;
    asm("cvt.rn.f16x2.f32 %0, %1, %2;" : "=r"(r) : "f"(hi), "f"(lo));
    return r;
}
// swizzled offset in [rows][32]halfwords (64B rows, 4 chunks)
__device__ __forceinline__ uint32_t soff(int row, int chunk) {
    return (uint32_t)(row * 64 + ((chunk ^ ((row >> 1) & 3)) << 4));
}
// swizzled offset in [rows][64]halfwords (128B rows, 8 chunks)
__device__ __forceinline__ uint32_t soff64(int row, int ch) {
    return (uint32_t)(row * 128 + ((ch ^ (row & 7)) << 4));
}
// 2^z via deg-6 poly + exponent injection (no MUFU)
__device__ __forceinline__ float fexp2(float z) {
    z = fmaxf(z, -60.f);
    float fi = floorf(z);
    float f = z - fi;
    float p = 1.54035e-4f;
    p = fmaf(p, f, 1.33336e-3f);
    p = fmaf(p, f, 9.61813e-3f);
    p = fmaf(p, f, 5.55041e-2f);
    p = fmaf(p, f, 2.40227e-1f);
    p = fmaf(p, f, 6.9314718e-1f);
    p = fmaf(p, f, 1.0f);
    int i = (int)fi;
    return __int_as_float(__float_as_int(p) + (i << 23));
}

// ---------------- scratch (all fp16 single) ----------------
#define AL16 __align__(16)
__device__ AL16 __half g_q16[(size_t)BATCH*NQ*QD];
__device__ AL16 __half g_k16[(size_t)BATCH*NK*KD];
__device__ AL16 __half g_v16[(size_t)BATCH*NK*KD];
__device__ AL16 __half g_wq16[(size_t)QD*QD], g_wo16[(size_t)QD*QD];
__device__ AL16 __half g_wk16[(size_t)QD*KD], g_wv16[(size_t)QD*KD];
__device__ AL16 __half g_Qp[(size_t)BATCH*NQ*QD];
__device__ AL16 __half g_Kp[(size_t)BATCH*NK*QD];
__device__ AL16 __half g_Vp[(size_t)BATCH*NK*QD];
__device__ AL16 __half g_AO16[(size_t)BATCH*NQ*QD];

// ============ fused input convert: q/k/v fp32 -> fp16 ============
__global__ __launch_bounds__(256) void conv_in(
    const float* __restrict__ q, const float* __restrict__ k, const float* __restrict__ v)
{
    int z = blockIdx.z;
    const float* x = (z == 0) ? q : (z == 1) ? k : v;
    __half* dst = (z == 0) ? g_q16 : (z == 1) ? g_k16 : g_v16;
    int n4 = (z == 0) ? BATCH*NQ*QD/4 : BATCH*NK*KD/4;
    int i = blockIdx.x * 256 + threadIdx.x;
    if (i >= n4) return;
    float4 val = ((const float4*)x)[i];
    ((uint32_t*)dst)[2*i]   = packh(val.y, val.x);
    ((uint32_t*)dst)[2*i+1] = packh(val.w, val.z);
}

// ============ fused weight transpose+convert: W[K,N] -> [N,K] fp16 ============
__global__ __launch_bounds__(256) void wconv_all(
    const float* __restrict__ Wq, const float* __restrict__ Wk,
    const float* __restrict__ Wv, const float* __restrict__ Wo)
{
    int z = blockIdx.z;
    const float* W; __half* T; int K = QD;
    if (z == 0)      { W = Wq; T = g_wq16; }
    else if (z == 1) { W = Wk; T = g_wk16; K = KD; }
    else if (z == 2) { W = Wv; T = g_wv16; K = KD; }
    else             { W = Wo; T = g_wo16; }
    const int N = QD;
    const int nb = blockIdx.x * 32, kb = blockIdx.y * 32;
    if (kb >= K) return;
    __shared__ float tile[32][33];
    const int tx = threadIdx.x & 31, tg = threadIdx.x >> 5;
#pragma unroll
    for (int r = 0; r < 4; r++) {
        int kk = tg + r * 8;
        tile[kk][tx] = W[(size_t)(kb + kk) * N + nb + tx];
    }
    __syncthreads();
#pragma unroll
    for (int r = 0; r < 4; r++) {
        int n = tg + r * 8;
        T[(size_t)(nb + n) * K + kb + tx] = __float2half_rn(tile[tx][n]);
    }
}

// ============ fp16 single-product GEMM, 5-stage pipeline, 1 bar/iter ============
// C[M,N] = A[M,K] @ B[N,K]^T + bias, *scale. CTA 128x128, K-chunk 32, 8 warps.
#define F1_A 0
#define F1_B 8192
#define F1_STG 16384
#define F1_SMEM (5 * F1_STG)

__global__ __launch_bounds__(256, 2) void gemm_f16(
    const __half* __restrict__ A, const __half* __restrict__ B,
    const float* __restrict__ bias, float* __restrict__ Cf,
    __half* __restrict__ C16, float scale, int M, int N, int K)
{
    extern __shared__ char sm[];
    const uint32_t smb = smem_u32(sm);
    const int t = threadIdx.x, wid = t >> 5, lane = t & 31;
    const int m0 = blockIdx.y * 128, n0 = blockIdx.x * 128;
    const int NC = K >> 5;
    const int wm = (wid & 1) * 64, wn = (wid >> 1) * 32;
    const int lrow = t >> 1, lch0 = (t & 1) * 2;

    auto load_stage = [&](int c) {
        const int kt = c << 5;
        const uint32_t sb = smb + (c % 5) * F1_STG;
#pragma unroll
        for (int j = 0; j < 2; j++) {
            int ch = lch0 + j;
            uint32_t so = soff(lrow, ch);
            cpa16(sb + F1_A + so, A + (size_t)(m0 + lrow) * K + kt + ch * 8);
            cpa16(sb + F1_B + so, B + (size_t)(n0 + lrow) * K + kt + ch * 8);
        }
        CP_COMMIT();
    };

    float d[4][4][4];
#pragma unroll
    for (int i = 0; i < 4; i++)
#pragma unroll
        for (int j = 0; j < 4; j++)
#pragma unroll
            for (int k = 0; k < 4; k++) d[i][j][k] = 0.f;

    load_stage(0); load_stage(1); load_stage(2); load_stage(3);

    for (int c = 0; c < NC; c++) {
        if (c <= NC - 4) CP_WAIT(3);
        else if (c == NC - 3) CP_WAIT(2);
        else if (c == NC - 2) CP_WAIT(1);
        else CP_WAIT(0);
        __syncthreads();
        if (c + 4 < NC) load_stage(c + 4);

        const uint32_t sb = smb + (c % 5) * F1_STG;
#pragma unroll
        for (int ks = 0; ks < 2; ks++) {
            const int kc = ks * 2;
            uint32_t af[4][4];
#pragma unroll
            for (int mt = 0; mt < 4; mt++) {
                int row = wm + mt * 16 + (lane & 15);
                int ch = kc + (lane >> 4);
                ldsm4(af[mt], sb + F1_A + soff(row, ch));
            }
            uint32_t bf[4][2];
#pragma unroll
            for (int p = 0; p < 2; p++) {
                int nrow = wn + p * 16 + ((lane >> 4) & 1) * 8 + (lane & 7);
                int ch = kc + ((lane >> 3) & 1);
                uint32_t r[4];
                ldsm4(r, sb + F1_B + soff(nrow, ch));
                bf[p*2][0] = r[0]; bf[p*2][1] = r[1];
                bf[p*2+1][0] = r[2]; bf[p*2+1][1] = r[3];
            }
#pragma unroll
            for (int mt = 0; mt < 4; mt++)
#pragma unroll
                for (int nt = 0; nt < 4; nt++)
                    mma_fp(d[mt][nt], af[mt], bf[nt]);
        }
    }

    const int lr = lane >> 2, lc = (lane & 3) * 2;
#pragma unroll
    for (int mt = 0; mt < 4; mt++) {
        int row = m0 + wm + mt * 16 + lr;
#pragma unroll
        for (int nt = 0; nt < 4; nt++) {
            int col = n0 + wn + nt * 8 + lc;
            float b0 = __ldg(bias + col), b1 = __ldg(bias + col + 1);
            float v0 = (d[mt][nt][0] + b0) * scale, v1 = (d[mt][nt][1] + b1) * scale;
            float v2 = (d[mt][nt][2] + b0) * scale, v3 = (d[mt][nt][3] + b1) * scale;
            if (Cf) {
                *(float2*)&Cf[(size_t)row * N + col] = make_float2(v0, v1);
                *(float2*)&Cf[(size_t)(row + 8) * N + col] = make_float2(v2, v3);
            } else {
                *(uint32_t*)&C16[(size_t)row * N + col] = packh(v1, v0);
                *(uint32_t*)&C16[(size_t)(row + 8) * N + col] = packh(v3, v2);
            }
        }
    }
}

// ============ tensor-core flash attention, fp16, kv-chunk 64, 4-stage, 1 bar/iter ============
#define ATS 16384
#define AT_Q (4 * ATS)
#define ATTN_SMEM (4 * ATS + 16384)
#define NCH (NK / 64)   // 16 chunks

__global__ __launch_bounds__(256, 2) void attn_tc(
    const __half* __restrict__ Qp, const __half* __restrict__ Kp,
    const __half* __restrict__ Vp, __half* __restrict__ AO)
{
    extern __shared__ char sm[];
    const uint32_t smb = smem_u32(sm);
    const int t = threadIdx.x, w = t >> 5, lane = t & 31;
    const int q0 = blockIdx.x * 128, h = blockIdx.y, b = blockIdx.z;
    const size_t qbase = ((size_t)(b * NQ + q0)) * QD + h * HD;
    const size_t kbase = ((size_t)(b * NK)) * QD + h * HD;

    auto ld_stage = [&](int c) {
        const uint32_t sb = smb + (c & 3) * ATS;
        const int n0 = c << 6;
#pragma unroll
        for (int j = 0; j < 2; j++) {
            int u = t + j * 256;
            int row = u >> 3, ch = u & 7;
            uint32_t so = soff64(row, ch);
            size_t g = kbase + (size_t)(n0 + row) * QD + ch * 8;
            cpa16(sb + so, Kp + g);
            cpa16(sb + 8192 + so, Vp + g);
        }
        CP_COMMIT();
    };

    // Q load rides in cp group 0
#pragma unroll
    for (int j = 0; j < 4; j++) {
        int u = t + j * 256;
        int row = u >> 3, ch = u & 7;
        cpa16(smb + AT_Q + soff64(row, ch), Qp + qbase + (size_t)row * QD + ch * 8);
    }
    ld_stage(0); ld_stage(1); ld_stage(2);

    uint32_t qf[4][4];
    float s[8][4];
    float o[8][4];
    float lsum0 = 0.f, lsum1 = 0.f;
#pragma unroll
    for (int i = 0; i < 8; i++)
#pragma unroll
        for (int j = 0; j < 4; j++) o[i][j] = 0.f;

    for (int c = 0; c < NCH; c++) {
        if (c <= NCH - 3) CP_WAIT(2);
        else if (c == NCH - 2) CP_WAIT(1);
        else CP_WAIT(0);
        __syncthreads();
        if (c + 3 < NCH) ld_stage(c + 3);

        if (c == 0) {
#pragma unroll
            for (int ks = 0; ks < 4; ks++) {
                int row = w * 16 + (lane & 15);
                ldsm4(qf[ks], smb + AT_Q + soff64(row, ks * 2 + (lane >> 4)));
            }
        }
        const uint32_t sb = smb + (c & 3) * ATS;

        // ---- S = Q K^T over 64 kv (logits in log2 domain) ----
#pragma unroll
        for (int sn = 0; sn < 8; sn++) {
            s[sn][0] = 0.f; s[sn][1] = 0.f; s[sn][2] = 0.f; s[sn][3] = 0.f;
        }
#pragma unroll
        for (int ks = 0; ks < 4; ks++) {
#pragma unroll
            for (int p = 0; p < 4; p++) {
                int nrow = p * 16 + ((lane >> 4) & 1) * 8 + (lane & 7);
                int ch = ks * 2 + ((lane >> 3) & 1);
                uint32_t kf[4];
                ldsm4(kf, sb + soff64(nrow, ch));
                uint32_t b0[2] = {kf[0], kf[1]}, b1[2] = {kf[2], kf[3]};
                mma_fp(s[2*p],   qf[ks], b0);
                mma_fp(s[2*p+1], qf[ks], b1);
            }
        }

        // ---- exp2 (poly), pack P fp16, PV mma ----
#pragma unroll
        for (int kk = 0; kk < 4; kk++) {
            float* e0 = s[2*kk];
            float* e1 = s[2*kk+1];
#pragma unroll
            for (int j = 0; j < 4; j++) { e0[j] = fexp2(e0[j]); e1[j] = fexp2(e1[j]); }
            lsum0 += e0[0] + e0[1] + e1[0] + e1[1];
            lsum1 += e0[2] + e0[3] + e1[2] + e1[3];
            uint32_t ph[4];
            ph[0] = packh(e0[1], e0[0]); ph[1] = packh(e0[3], e0[2]);
            ph[2] = packh(e1[1], e1[0]); ph[3] = packh(e1[3], e1[2]);
#pragma unroll
            for (int q = 0; q < 4; q++) {
                int row = kk * 16 + (lane & 15);
                int ch = q * 2 + (lane >> 4);
                uint32_t vf[4];
                ldsm4t(vf, sb + 8192 + soff64(row, ch));
                uint32_t b0[2] = {vf[0], vf[1]}, b1[2] = {vf[2], vf[3]};
                mma_fp(o[2*q],   ph, b0);
                mma_fp(o[2*q+1], ph, b1);
            }
        }
    }

    lsum0 += __shfl_xor_sync(0xffffffffu, lsum0, 1);
    lsum0 += __shfl_xor_sync(0xffffffffu, lsum0, 2);
    lsum1 += __shfl_xor_sync(0xffffffffu, lsum1, 1);
    lsum1 += __shfl_xor_sync(0xffffffffu, lsum1, 2);
    const float inv0 = 1.f / lsum0, inv1 = 1.f / lsum1;

    const int row0 = q0 + w * 16 + (lane >> 2);
#pragma unroll
    for (int nt = 0; nt < 8; nt++) {
        int col = h * HD + nt * 8 + (lane & 3) * 2;
        *(uint32_t*)&AO[((size_t)(b * NQ + row0)) * QD + col] =
            packh(o[nt][1] * inv0, o[nt][0] * inv0);
        *(uint32_t*)&AO[((size_t)(b * NQ + row0 + 8)) * QD + col] =
            packh(o[nt][3] * inv1, o[nt][2] * inv1);
    }
}

// ============ kernel_launch ============
extern "C" void kernel_launch(void* const* d_in, const int* in_sizes, int n_in,
                              void* d_out, int out_size)
{
    const float* query = (const float*)d_in[0];
    const float* key   = (const float*)d_in[1];
    const float* value = (const float*)d_in[2];
    const float* Wq = (const float*)d_in[3];  const float* bq = (const float*)d_in[4];
    const float* Wk = (const float*)d_in[5];  const float* bk = (const float*)d_in[6];
    const float* Wv = (const float*)d_in[7];  const float* bv = (const float*)d_in[8];
    const float* Wo = (const float*)d_in[9];  const float* bo = (const float*)d_in[10];
    float* out = (float*)d_out;

    __half *q16,*k16,*v16,*wq16,*wk16,*wv16,*wo16,*Qp,*Kp,*Vp,*ao16;
    cudaGetSymbolAddress((void**)&q16, g_q16);   cudaGetSymbolAddress((void**)&k16, g_k16);
    cudaGetSymbolAddress((void**)&v16, g_v16);
    cudaGetSymbolAddress((void**)&wq16, g_wq16); cudaGetSymbolAddress((void**)&wk16, g_wk16);
    cudaGetSymbolAddress((void**)&wv16, g_wv16); cudaGetSymbolAddress((void**)&wo16, g_wo16);
    cudaGetSymbolAddress((void**)&Qp, g_Qp);     cudaGetSymbolAddress((void**)&Kp, g_Kp);
    cudaGetSymbolAddress((void**)&Vp, g_Vp);     cudaGetSymbolAddress((void**)&ao16, g_AO16);

    cudaFuncSetAttribute(gemm_f16, cudaFuncAttributeMaxDynamicSharedMemorySize, F1_SMEM);
    cudaFuncSetAttribute(attn_tc,  cudaFuncAttributeMaxDynamicSharedMemorySize, ATTN_SMEM);

    const int MQ = BATCH * NQ;   // 16384
    const int MK = BATCH * NK;   // 4096

    // launch 0-1: converts
    conv_in<<<dim3(MQ*QD/4/256, 1, 3), 256>>>(query, key, value);
    wconv_all<<<dim3(QD/32, QD/32, 4), 256>>>(Wq, Wk, Wv, Wo);
    // launches 2-4: projections (fp16 single product; Q scaled by SCALE*log2e)
    gemm_f16<<<dim3(QD/128, MQ/128), 256, F1_SMEM>>>(
        q16, wq16, bq, nullptr, Qp, QSCALE, MQ, QD, QD);
    gemm_f16<<<dim3(QD/128, MK/128), 256, F1_SMEM>>>(
        k16, wk16, bk, nullptr, Kp, 1.0f, MK, QD, KD);
    gemm_f16<<<dim3(QD/128, MK/128), 256, F1_SMEM>>>(
        v16, wv16, bv, nullptr, Vp, 1.0f, MK, QD, KD);
    // launch 5: attention (ncu -s 5 -c 1 captures this)
    attn_tc<<<dim3(NQ/128, NH, BATCH), 256, ATTN_SMEM>>>(Qp, Kp, Vp, ao16);
    // launch 6: O proj -> fp32 d_out
    gemm_f16<<<dim3(QD/128, MQ/128), 256, F1_SMEM>>>(
        ao16, wo16, bo, out, nullptr, 1.0f, MQ, QD, QD);
}

// round 10
// speedup vs baseline: 18.1202x; 1.1154x over previous
#include <cuda_runtime.h>
#include <cuda_fp16.h>
#include <cstdint>

#define BATCH 4
#define NQ    4096
#define NK    1024
#define NH    16
#define HD    64
#define QD    1024
#define KD    768
#define QSCALE 0.1803368801f   // 0.125 * log2(e), folded into Q proj epilogue

// ---------------- helpers ----------------
__device__ __forceinline__ uint32_t smem_u32(const void* p) {
    uint32_t a;
    asm("{ .reg .u64 t; cvta.to.shared.u64 t, %1; cvt.u32.u64 %0, t; }" : "=r"(a) : "l"(p));
    return a;
}
__device__ __forceinline__ void cpa16(uint32_t s, const void* g) {
    asm volatile("cp.async.cg.shared.global [%0], [%1], 16;" :: "r"(s), "l"(g));
}
#define CP_COMMIT() asm volatile("cp.async.commit_group;" ::: "memory")
#define CP_WAIT(n)  asm volatile("cp.async.wait_group %0;" :: "n"(n) : "memory")
__device__ __forceinline__ void ldsm4(uint32_t* r, uint32_t a) {
    asm volatile("ldmatrix.sync.aligned.m8n8.x4.shared.b16 {%0,%1,%2,%3}, [%4];"
        : "=r"(r[0]), "=r"(r[1]), "=r"(r[2]), "=r"(r[3]) : "r"(a));
}
__device__ __forceinline__ void ldsm4t(uint32_t* r, uint32_t a) {
    asm volatile("ldmatrix.sync.aligned.m8n8.x4.trans.shared.b16 {%0,%1,%2,%3}, [%4];"
        : "=r"(r[0]), "=r"(r[1]), "=r"(r[2]), "=r"(r[3]) : "r"(a));
}
__device__ __forceinline__ void mma_fp(float* d, const uint32_t* a, const uint32_t* b) {
    asm volatile("mma.sync.aligned.m16n8k16.row.col.f32.f16.f16.f32 "
        "{%0,%1,%2,%3}, {%4,%5,%6,%7}, {%8,%9}, {%0,%1,%2,%3};"
        : "+f"(d[0]), "+f"(d[1]), "+f"(d[2]), "+f"(d[3])
        : "r"(a[0]), "r"(a[1]), "r"(a[2]), "r"(a[3]), "r"(b[0]), "r"(b[1]));
}
__device__ __forceinline__ uint32_t packh(float hi, float lo) {
    uint32_t r;
    asm("cvt.rn.f16x2.f32 %0, %1, %2;" : "=r"(r) : "f"(hi), "f"(lo));
    return r;
}
// swizzled offset in [rows][64]halfwords (128B rows, 8 chunks of 16B)
__device__ __forceinline__ uint32_t soff64(int row, int ch) {
    return (uint32_t)(row * 128 + ((ch ^ (row & 7)) << 4));
}
// 2^z via deg-6 poly + exponent injection (no MUFU)
__device__ __forceinline__ float fexp2(float z) {
    z = fmaxf(z, -60.f);
    float fi = floorf(z);
    float f = z - fi;
    float p = 1.54035e-4f;
    p = fmaf(p, f, 1.33336e-3f);
    p = fmaf(p, f, 9.61813e-3f);
    p = fmaf(p, f, 5.55041e-2f);
    p = fmaf(p, f, 2.40227e-1f);
    p = fmaf(p, f, 6.9314718e-1f);
    p = fmaf(p, f, 1.0f);
    int i = (int)fi;
    return __int_as_float(__float_as_int(p) + (i << 23));
}

// ---------------- scratch (all fp16 single) ----------------
#define AL16 __align__(16)
__device__ AL16 __half g_q16[(size_t)BATCH*NQ*QD];
__device__ AL16 __half g_k16[(size_t)BATCH*NK*KD];
__device__ AL16 __half g_v16[(size_t)BATCH*NK*KD];
__device__ AL16 __half g_wq16[(size_t)QD*QD], g_wo16[(size_t)QD*QD];
__device__ AL16 __half g_wk16[(size_t)QD*KD], g_wv16[(size_t)QD*KD];
__device__ AL16 __half g_Qp[(size_t)BATCH*NQ*QD];
__device__ AL16 __half g_Kp[(size_t)BATCH*NK*QD];
__device__ AL16 __half g_Vp[(size_t)BATCH*NK*QD];
__device__ AL16 __half g_AO16[(size_t)BATCH*NQ*QD];

// ============ fused input convert: q/k/v fp32 -> fp16 ============
__global__ __launch_bounds__(256) void conv_in(
    const float* __restrict__ q, const float* __restrict__ k, const float* __restrict__ v)
{
    int z = blockIdx.z;
    const float* x = (z == 0) ? q : (z == 1) ? k : v;
    __half* dst = (z == 0) ? g_q16 : (z == 1) ? g_k16 : g_v16;
    int n4 = (z == 0) ? BATCH*NQ*QD/4 : BATCH*NK*KD/4;
    int i = blockIdx.x * 256 + threadIdx.x;
    if (i >= n4) return;
    float4 val = ((const float4*)x)[i];
    ((uint32_t*)dst)[2*i]   = packh(val.y, val.x);
    ((uint32_t*)dst)[2*i+1] = packh(val.w, val.z);
}

// ============ fused weight transpose+convert: W[K,N] -> [N,K] fp16 ============
__global__ __launch_bounds__(256) void wconv_all(
    const float* __restrict__ Wq, const float* __restrict__ Wk,
    const float* __restrict__ Wv, const float* __restrict__ Wo)
{
    int z = blockIdx.z;
    const float* W; __half* T; int K = QD;
    if (z == 0)      { W = Wq; T = g_wq16; }
    else if (z == 1) { W = Wk; T = g_wk16; K = KD; }
    else if (z == 2) { W = Wv; T = g_wv16; K = KD; }
    else             { W = Wo; T = g_wo16; }
    const int N = QD;
    const int nb = blockIdx.x * 32, kb = blockIdx.y * 32;
    if (kb >= K) return;
    __shared__ float tile[32][33];
    const int tx = threadIdx.x & 31, tg = threadIdx.x >> 5;
#pragma unroll
    for (int r = 0; r < 4; r++) {
        int kk = tg + r * 8;
        tile[kk][tx] = W[(size_t)(kb + kk) * N + nb + tx];
    }
    __syncthreads();
#pragma unroll
    for (int r = 0; r < 4; r++) {
        int n = tg + r * 8;
        T[(size_t)(nb + n) * K + kb + tx] = __float2half_rn(tile[tx][n]);
    }
}

// ============ fp16 GEMM, K-chunk 64, 3-stage pipeline, 1 bar/chunk ============
// C[M,N] = A[M,K] @ B[N,K]^T + bias, *scale. CTA 128x128, 8 warps (64x32 each).
#define F1_A 0
#define F1_B 16384
#define F1_STG 32768
#define F1_SMEM (3 * F1_STG)   // 96 KB

__global__ __launch_bounds__(256, 2) void gemm_f16(
    const __half* __restrict__ A, const __half* __restrict__ B,
    const float* __restrict__ bias, float* __restrict__ Cf,
    __half* __restrict__ C16, float scale, int M, int N, int K)
{
    extern __shared__ char sm[];
    const uint32_t smb = smem_u32(sm);
    const int t = threadIdx.x, wid = t >> 5, lane = t & 31;
    const int m0 = blockIdx.y * 128, n0 = blockIdx.x * 128;
    const int NC = K >> 6;
    const int wm = (wid & 1) * 64, wn = (wid >> 1) * 32;

    auto load_stage = [&](int c) {
        const int kt = c << 6;
        const uint32_t sb = smb + (c % 3) * F1_STG;
#pragma unroll
        for (int j = 0; j < 4; j++) {
            int u = t + j * 256;
            int row = u >> 3, ch = u & 7;
            uint32_t so = soff64(row, ch);
            cpa16(sb + F1_A + so, A + (size_t)(m0 + row) * K + kt + ch * 8);
            cpa16(sb + F1_B + so, B + (size_t)(n0 + row) * K + kt + ch * 8);
        }
        CP_COMMIT();
    };

    float d[4][4][4];
#pragma unroll
    for (int i = 0; i < 4; i++)
#pragma unroll
        for (int j = 0; j < 4; j++)
#pragma unroll
            for (int k = 0; k < 4; k++) d[i][j][k] = 0.f;

    load_stage(0); load_stage(1);

    for (int c = 0; c < NC; c++) {
        if (c < NC - 1) CP_WAIT(1);
        else CP_WAIT(0);
        __syncthreads();
        if (c + 2 < NC) load_stage(c + 2);

        const uint32_t sb = smb + (c % 3) * F1_STG;
#pragma unroll
        for (int ks = 0; ks < 4; ks++) {
            uint32_t af[4][4];
#pragma unroll
            for (int mt = 0; mt < 4; mt++) {
                int row = wm + mt * 16 + (lane & 15);
                int ch = ks * 2 + (lane >> 4);
                ldsm4(af[mt], sb + F1_A + soff64(row, ch));
            }
            uint32_t bf[4][2];
#pragma unroll
            for (int p = 0; p < 2; p++) {
                int nrow = wn + p * 16 + ((lane >> 4) & 1) * 8 + (lane & 7);
                int ch = ks * 2 + ((lane >> 3) & 1);
                uint32_t r[4];
                ldsm4(r, sb + F1_B + soff64(nrow, ch));
                bf[p*2][0] = r[0]; bf[p*2][1] = r[1];
                bf[p*2+1][0] = r[2]; bf[p*2+1][1] = r[3];
            }
#pragma unroll
            for (int mt = 0; mt < 4; mt++)
#pragma unroll
                for (int nt = 0; nt < 4; nt++)
                    mma_fp(d[mt][nt], af[mt], bf[nt]);
        }
    }

    const int lr = lane >> 2, lc = (lane & 3) * 2;
#pragma unroll
    for (int mt = 0; mt < 4; mt++) {
        int row = m0 + wm + mt * 16 + lr;
#pragma unroll
        for (int nt = 0; nt < 4; nt++) {
            int col = n0 + wn + nt * 8 + lc;
            float b0 = __ldg(bias + col), b1 = __ldg(bias + col + 1);
            float v0 = (d[mt][nt][0] + b0) * scale, v1 = (d[mt][nt][1] + b1) * scale;
            float v2 = (d[mt][nt][2] + b0) * scale, v3 = (d[mt][nt][3] + b1) * scale;
            if (Cf) {
                *(float2*)&Cf[(size_t)row * N + col] = make_float2(v0, v1);
                *(float2*)&Cf[(size_t)(row + 8) * N + col] = make_float2(v2, v3);
            } else {
                *(uint32_t*)&C16[(size_t)row * N + col] = packh(v1, v0);
                *(uint32_t*)&C16[(size_t)(row + 8) * N + col] = packh(v3, v2);
            }
        }
    }
}

// ============ tensor-core flash attention: kv-chunk 128 per barrier, 3-stage ============
// CTA: 128 q rows of one (b,h); 8 warps x 16 rows. Stage 32KB = K[128][64] + V[128][64].
#define ATS 32768
#define AT_Q (3 * ATS)
#define ATTN_SMEM (3 * ATS + 16384)   // 112 KB
#define NCH2 (NK / 128)   // 8 chunks

__global__ __launch_bounds__(256, 2) void attn_tc(
    const __half* __restrict__ Qp, const __half* __restrict__ Kp,
    const __half* __restrict__ Vp, __half* __restrict__ AO)
{
    extern __shared__ char sm[];
    const uint32_t smb = smem_u32(sm);
    const int t = threadIdx.x, w = t >> 5, lane = t & 31;
    const int q0 = blockIdx.x * 128, h = blockIdx.y, b = blockIdx.z;
    const size_t qbase = ((size_t)(b * NQ + q0)) * QD + h * HD;
    const size_t kbase = ((size_t)(b * NK)) * QD + h * HD;

    auto ld_stage = [&](int c) {
        const uint32_t sb = smb + (c % 3) * ATS;
        const int n0 = c << 7;
#pragma unroll
        for (int j = 0; j < 4; j++) {
            int u = t + j * 256;
            int row = u >> 3, ch = u & 7;
            uint32_t so = soff64(row, ch);
            size_t g = kbase + (size_t)(n0 + row) * QD + ch * 8;
            cpa16(sb + so, Kp + g);
            cpa16(sb + 16384 + so, Vp + g);
        }
        CP_COMMIT();
    };

    // Q load rides in cp group 0
#pragma unroll
    for (int j = 0; j < 4; j++) {
        int u = t + j * 256;
        int row = u >> 3, ch = u & 7;
        cpa16(smb + AT_Q + soff64(row, ch), Qp + qbase + (size_t)row * QD + ch * 8);
    }
    ld_stage(0); ld_stage(1);

    uint32_t qf[4][4];
    float s[8][4];
    float o[8][4];
    float lsum0 = 0.f, lsum1 = 0.f;
#pragma unroll
    for (int i = 0; i < 8; i++)
#pragma unroll
        for (int j = 0; j < 4; j++) o[i][j] = 0.f;

    for (int c = 0; c < NCH2; c++) {
        if (c < NCH2 - 1) CP_WAIT(1);
        else CP_WAIT(0);
        __syncthreads();
        if (c + 2 < NCH2) ld_stage(c + 2);

        if (c == 0) {
#pragma unroll
            for (int ks = 0; ks < 4; ks++) {
                int row = w * 16 + (lane & 15);
                ldsm4(qf[ks], smb + AT_Q + soff64(row, ks * 2 + (lane >> 4)));
            }
        }
        const uint32_t sb = smb + (c % 3) * ATS;

#pragma unroll
        for (int hf = 0; hf < 2; hf++) {
            const int r0 = hf * 64;
            // ---- S = Q K^T over 64 kv (logits in log2 domain) ----
#pragma unroll
            for (int sn = 0; sn < 8; sn++) {
                s[sn][0] = 0.f; s[sn][1] = 0.f; s[sn][2] = 0.f; s[sn][3] = 0.f;
            }
#pragma unroll
            for (int ks = 0; ks < 4; ks++) {
#pragma unroll
                for (int p = 0; p < 4; p++) {
                    int nrow = r0 + p * 16 + ((lane >> 4) & 1) * 8 + (lane & 7);
                    int ch = ks * 2 + ((lane >> 3) & 1);
                    uint32_t kf[4];
                    ldsm4(kf, sb + soff64(nrow, ch));
                    uint32_t b0[2] = {kf[0], kf[1]}, b1[2] = {kf[2], kf[3]};
                    mma_fp(s[2*p],   qf[ks], b0);
                    mma_fp(s[2*p+1], qf[ks], b1);
                }
            }
            // ---- exp2 (poly), pack P fp16, PV mma ----
#pragma unroll
            for (int kk = 0; kk < 4; kk++) {
                float* e0 = s[2*kk];
                float* e1 = s[2*kk+1];
#pragma unroll
                for (int j = 0; j < 4; j++) { e0[j] = fexp2(e0[j]); e1[j] = fexp2(e1[j]); }
                lsum0 += e0[0] + e0[1] + e1[0] + e1[1];
                lsum1 += e0[2] + e0[3] + e1[2] + e1[3];
                uint32_t ph[4];
                ph[0] = packh(e0[1], e0[0]); ph[1] = packh(e0[3], e0[2]);
                ph[2] = packh(e1[1], e1[0]); ph[3] = packh(e1[3], e1[2]);
#pragma unroll
                for (int q = 0; q < 4; q++) {
                    int row = r0 + kk * 16 + (lane & 15);
                    int ch = q * 2 + (lane >> 4);
                    uint32_t vf[4];
                    ldsm4t(vf, sb + 16384 + soff64(row, ch));
                    uint32_t b0[2] = {vf[0], vf[1]}, b1[2] = {vf[2], vf[3]};
                    mma_fp(o[2*q],   ph, b0);
                    mma_fp(o[2*q+1], ph, b1);
                }
            }
        }
    }

    lsum0 += __shfl_xor_sync(0xffffffffu, lsum0, 1);
    lsum0 += __shfl_xor_sync(0xffffffffu, lsum0, 2);
    lsum1 += __shfl_xor_sync(0xffffffffu, lsum1, 1);
    lsum1 += __shfl_xor_sync(0xffffffffu, lsum1, 2);
    const float inv0 = 1.f / lsum0, inv1 = 1.f / lsum1;

    const int row0 = q0 + w * 16 + (lane >> 2);
#pragma unroll
    for (int nt = 0; nt < 8; nt++) {
        int col = h * HD + nt * 8 + (lane & 3) * 2;
        *(uint32_t*)&AO[((size_t)(b * NQ + row0)) * QD + col] =
            packh(o[nt][1] * inv0, o[nt][0] * inv0);
        *(uint32_t*)&AO[((size_t)(b * NQ + row0 + 8)) * QD + col] =
            packh(o[nt][3] * inv1, o[nt][2] * inv1);
    }
}

// ============ kernel_launch ============
extern "C" void kernel_launch(void* const* d_in, const int* in_sizes, int n_in,
                              void* d_out, int out_size)
{
    const float* query = (const float*)d_in[0];
    const float* key   = (const float*)d_in[1];
    const float* value = (const float*)d_in[2];
    const float* Wq = (const float*)d_in[3];  const float* bq = (const float*)d_in[4];
    const float* Wk = (const float*)d_in[5];  const float* bk = (const float*)d_in[6];
    const float* Wv = (const float*)d_in[7];  const float* bv = (const float*)d_in[8];
    const float* Wo = (const float*)d_in[9];  const float* bo = (const float*)d_in[10];
    float* out = (float*)d_out;

    __half *q16,*k16,*v16,*wq16,*wk16,*wv16,*wo16,*Qp,*Kp,*Vp,*ao16;
    cudaGetSymbolAddress((void**)&q16, g_q16);   cudaGetSymbolAddress((void**)&k16, g_k16);
    cudaGetSymbolAddress((void**)&v16, g_v16);
    cudaGetSymbolAddress((void**)&wq16, g_wq16); cudaGetSymbolAddress((void**)&wk16, g_wk16);
    cudaGetSymbolAddress((void**)&wv16, g_wv16); cudaGetSymbolAddress((void**)&wo16, g_wo16);
    cudaGetSymbolAddress((void**)&Qp, g_Qp);     cudaGetSymbolAddress((void**)&Kp, g_Kp);
    cudaGetSymbolAddress((void**)&Vp, g_Vp);     cudaGetSymbolAddress((void**)&ao16, g_AO16);

    cudaFuncSetAttribute(gemm_f16, cudaFuncAttributeMaxDynamicSharedMemorySize, F1_SMEM);
    cudaFuncSetAttribute(attn_tc,  cudaFuncAttributeMaxDynamicSharedMemorySize, ATTN_SMEM);

    const int MQ = BATCH * NQ;   // 16384
    const int MK = BATCH * NK;   // 4096

    // launch 0-1: converts
    conv_in<<<dim3(MQ*QD/4/256, 1, 3), 256>>>(query, key, value);
    wconv_all<<<dim3(QD/32, QD/32, 4), 256>>>(Wq, Wk, Wv, Wo);
    // launches 2-4: projections (fp16 single product; Q scaled by SCALE*log2e)
    gemm_f16<<<dim3(QD/128, MQ/128), 256, F1_SMEM>>>(
        q16, wq16, bq, nullptr, Qp, QSCALE, MQ, QD, QD);
    gemm_f16<<<dim3(QD/128, MK/128), 256, F1_SMEM>>>(
        k16, wk16, bk, nullptr, Kp, 1.0f, MK, QD, KD);
    gemm_f16<<<dim3(QD/128, MK/128), 256, F1_SMEM>>>(
        v16, wv16, bv, nullptr, Vp, 1.0f, MK, QD, KD);
    // launch 5: attention (ncu -s 5 -c 1 captures this)
    attn_tc<<<dim3(NQ/128, NH, BATCH), 256, ATTN_SMEM>>>(Qp, Kp, Vp, ao16);
    // launch 6: O proj -> fp32 d_out
    gemm_f16<<<dim3(QD/128, MQ/128), 256, F1_SMEM>>>(
        ao16, wo16, bo, out, nullptr, 1.0f, MQ, QD, QD);
}

// round 11
// speedup vs baseline: 21.1060x; 1.1648x over previous
#include <cuda_runtime.h>
#include <cuda_fp16.h>
#include <cstdint>

#define BATCH 4
#define NQ    4096
#define NK    1024
#define NH    16
#define HD    64
#define QD    1024
#define KD    768
#define QSCALE 0.1803368801f   // 0.125 * log2(e), folded into Q proj epilogue

// ---------------- helpers ----------------
__device__ __forceinline__ uint32_t smem_u32(const void* p) {
    uint32_t a;
    asm("{ .reg .u64 t; cvta.to.shared.u64 t, %1; cvt.u32.u64 %0, t; }" : "=r"(a) : "l"(p));
    return a;
}
__device__ __forceinline__ void cpa16(uint32_t s, const void* g) {
    asm volatile("cp.async.cg.shared.global [%0], [%1], 16;" :: "r"(s), "l"(g));
}
#define CP_COMMIT() asm volatile("cp.async.commit_group;" ::: "memory")
#define CP_WAIT(n)  asm volatile("cp.async.wait_group %0;" :: "n"(n) : "memory")
__device__ __forceinline__ void ldsm4(uint32_t* r, uint32_t a) {
    asm volatile("ldmatrix.sync.aligned.m8n8.x4.shared.b16 {%0,%1,%2,%3}, [%4];"
        : "=r"(r[0]), "=r"(r[1]), "=r"(r[2]), "=r"(r[3]) : "r"(a));
}
__device__ __forceinline__ void ldsm4t(uint32_t* r, uint32_t a) {
    asm volatile("ldmatrix.sync.aligned.m8n8.x4.trans.shared.b16 {%0,%1,%2,%3}, [%4];"
        : "=r"(r[0]), "=r"(r[1]), "=r"(r[2]), "=r"(r[3]) : "r"(a));
}
__device__ __forceinline__ void mma_fp(float* d, const uint32_t* a, const uint32_t* b) {
    asm volatile("mma.sync.aligned.m16n8k16.row.col.f32.f16.f16.f32 "
        "{%0,%1,%2,%3}, {%4,%5,%6,%7}, {%8,%9}, {%0,%1,%2,%3};"
        : "+f"(d[0]), "+f"(d[1]), "+f"(d[2]), "+f"(d[3])
        : "r"(a[0]), "r"(a[1]), "r"(a[2]), "r"(a[3]), "r"(b[0]), "r"(b[1]));
}
__device__ __forceinline__ uint32_t packh(float hi, float lo) {
    uint32_t r;
    asm("cvt.rn.f16x2.f32 %0, %1, %2;" : "=f"(lo), "=f"(hi) : );  // placeholder (unused form)
    return r;
}
// (real packer)
__device__ __forceinline__ uint32_t packh2(float hi, float lo) {
    uint32_t r;
    asm("cvt.rn.f16x2.f32 %0, %1, %2;" : "=r"(r) : "f"(hi), "f"(lo));
    return r;
}
#undef packh
#define packh packh2
// swizzled offset in [rows][64]halfwords (128B rows, 8 chunks of 16B)
__device__ __forceinline__ uint32_t soff64(int row, int ch) {
    return (uint32_t)(row * 128 + ((ch ^ (row & 7)) << 4));
}
// 2^z via MUFU (warp-wide, rt 8/SMSP — ~63 us chip-wide for all of attention)
__device__ __forceinline__ float fexp2(float z) {
    float r;
    asm("ex2.approx.f32 %0, %1;" : "=f"(r) : "f"(z));
    return r;
}

// ---------------- scratch (all fp16 single) ----------------
#define AL16 __align__(16)
__device__ AL16 __half g_q16[(size_t)BATCH*NQ*QD];
__device__ AL16 __half g_k16[(size_t)BATCH*NK*KD];
__device__ AL16 __half g_v16[(size_t)BATCH*NK*KD];
__device__ AL16 __half g_wq16[(size_t)QD*QD], g_wo16[(size_t)QD*QD];
__device__ AL16 __half g_wk16[(size_t)QD*KD], g_wv16[(size_t)QD*KD];
__device__ AL16 __half g_Qp[(size_t)BATCH*NQ*QD];
__device__ AL16 __half g_Kp[(size_t)BATCH*NK*QD];
__device__ AL16 __half g_Vp[(size_t)BATCH*NK*QD];
__device__ AL16 __half g_AO16[(size_t)BATCH*NQ*QD];

// ============ fused input convert: q/k/v fp32 -> fp16 ============
__global__ __launch_bounds__(256) void conv_in(
    const float* __restrict__ q, const float* __restrict__ k, const float* __restrict__ v)
{
    int z = blockIdx.z;
    const float* x = (z == 0) ? q : (z == 1) ? k : v;
    __half* dst = (z == 0) ? g_q16 : (z == 1) ? g_k16 : g_v16;
    int n4 = (z == 0) ? BATCH*NQ*QD/4 : BATCH*NK*KD/4;
    int i = blockIdx.x * 256 + threadIdx.x;
    if (i >= n4) return;
    float4 val = ((const float4*)x)[i];
    ((uint32_t*)dst)[2*i]   = packh(val.y, val.x);
    ((uint32_t*)dst)[2*i+1] = packh(val.w, val.z);
}

// ============ fused weight transpose+convert: W[K,N] -> [N,K] fp16 ============
__global__ __launch_bounds__(256) void wconv_all(
    const float* __restrict__ Wq, const float* __restrict__ Wk,
    const float* __restrict__ Wv, const float* __restrict__ Wo)
{
    int z = blockIdx.z;
    const float* W; __half* T; int K = QD;
    if (z == 0)      { W = Wq; T = g_wq16; }
    else if (z == 1) { W = Wk; T = g_wk16; K = KD; }
    else if (z == 2) { W = Wv; T = g_wv16; K = KD; }
    else             { W = Wo; T = g_wo16; }
    const int N = QD;
    const int nb = blockIdx.x * 32, kb = blockIdx.y * 32;
    if (kb >= K) return;
    __shared__ float tile[32][33];
    const int tx = threadIdx.x & 31, tg = threadIdx.x >> 5;
#pragma unroll
    for (int r = 0; r < 4; r++) {
        int kk = tg + r * 8;
        tile[kk][tx] = W[(size_t)(kb + kk) * N + nb + tx];
    }
    __syncthreads();
#pragma unroll
    for (int r = 0; r < 4; r++) {
        int n = tg + r * 8;
        T[(size_t)(nb + n) * K + kb + tx] = __float2half_rn(tile[tx][n]);
    }
}

// ============ fp16 GEMM, K-chunk 64, 3-stage pipeline, 1 bar/chunk ============
// C[M,N] = A[M,K] @ B[N,K]^T + bias, *scale. CTA 128x128, 8 warps (64x32 each).
#define F1_A 0
#define F1_B 16384
#define F1_STG 32768
#define F1_SMEM (3 * F1_STG)   // 96 KB

__global__ __launch_bounds__(256, 2) void gemm_f16(
    const __half* __restrict__ A, const __half* __restrict__ B,
    const float* __restrict__ bias, float* __restrict__ Cf,
    __half* __restrict__ C16, float scale, int M, int N, int K)
{
    extern __shared__ char sm[];
    const uint32_t smb = smem_u32(sm);
    const int t = threadIdx.x, wid = t >> 5, lane = t & 31;
    const int m0 = blockIdx.y * 128, n0 = blockIdx.x * 128;
    const int NC = K >> 6;
    const int wm = (wid & 1) * 64, wn = (wid >> 1) * 32;

    auto load_stage = [&](int c) {
        const int kt = c << 6;
        const uint32_t sb = smb + (c % 3) * F1_STG;
#pragma unroll
        for (int j = 0; j < 4; j++) {
            int u = t + j * 256;
            int row = u >> 3, ch = u & 7;
            uint32_t so = soff64(row, ch);
            cpa16(sb + F1_A + so, A + (size_t)(m0 + row) * K + kt + ch * 8);
            cpa16(sb + F1_B + so, B + (size_t)(n0 + row) * K + kt + ch * 8);
        }
        CP_COMMIT();
    };

    float d[4][4][4];
#pragma unroll
    for (int i = 0; i < 4; i++)
#pragma unroll
        for (int j = 0; j < 4; j++)
#pragma unroll
            for (int k = 0; k < 4; k++) d[i][j][k] = 0.f;

    load_stage(0); load_stage(1);

    for (int c = 0; c < NC; c++) {
        if (c < NC - 1) CP_WAIT(1);
        else CP_WAIT(0);
        __syncthreads();
        if (c + 2 < NC) load_stage(c + 2);

        const uint32_t sb = smb + (c % 3) * F1_STG;
#pragma unroll
        for (int ks = 0; ks < 4; ks++) {
            uint32_t af[4][4];
#pragma unroll
            for (int mt = 0; mt < 4; mt++) {
                int row = wm + mt * 16 + (lane & 15);
                int ch = ks * 2 + (lane >> 4);
                ldsm4(af[mt], sb + F1_A + soff64(row, ch));
            }
            uint32_t bf[4][2];
#pragma unroll
            for (int p = 0; p < 2; p++) {
                int nrow = wn + p * 16 + ((lane >> 4) & 1) * 8 + (lane & 7);
                int ch = ks * 2 + ((lane >> 3) & 1);
                uint32_t r[4];
                ldsm4(r, sb + F1_B + soff64(nrow, ch));
                bf[p*2][0] = r[0]; bf[p*2][1] = r[1];
                bf[p*2+1][0] = r[2]; bf[p*2+1][1] = r[3];
            }
#pragma unroll
            for (int mt = 0; mt < 4; mt++)
#pragma unroll
                for (int nt = 0; nt < 4; nt++)
                    mma_fp(d[mt][nt], af[mt], bf[nt]);
        }
    }

    const int lr = lane >> 2, lc = (lane & 3) * 2;
#pragma unroll
    for (int mt = 0; mt < 4; mt++) {
        int row = m0 + wm + mt * 16 + lr;
#pragma unroll
        for (int nt = 0; nt < 4; nt++) {
            int col = n0 + wn + nt * 8 + lc;
            float b0 = __ldg(bias + col), b1 = __ldg(bias + col + 1);
            float v0 = (d[mt][nt][0] + b0) * scale, v1 = (d[mt][nt][1] + b1) * scale;
            float v2 = (d[mt][nt][2] + b0) * scale, v3 = (d[mt][nt][3] + b1) * scale;
            if (Cf) {
                *(float2*)&Cf[(size_t)row * N + col] = make_float2(v0, v1);
                *(float2*)&Cf[(size_t)(row + 8) * N + col] = make_float2(v2, v3);
            } else {
                *(uint32_t*)&C16[(size_t)row * N + col] = packh(v1, v0);
                *(uint32_t*)&C16[(size_t)(row + 8) * N + col] = packh(v3, v2);
            }
        }
    }
}

// ============ tensor-core flash attention: kv-chunk 128 per barrier, 3-stage ============
// CTA: 128 q rows of one (b,h); 8 warps x 16 rows. Stage 32KB = K[128][64] + V[128][64].
#define ATS 32768
#define AT_Q (3 * ATS)
#define ATTN_SMEM (3 * ATS + 16384)   // 112 KB
#define NCH2 (NK / 128)   // 8 chunks

__global__ __launch_bounds__(256, 2) void attn_tc(
    const __half* __restrict__ Qp, const __half* __restrict__ Kp,
    const __half* __restrict__ Vp, __half* __restrict__ AO)
{
    extern __shared__ char sm[];
    const uint32_t smb = smem_u32(sm);
    const int t = threadIdx.x, w = t >> 5, lane = t & 31;
    const int q0 = blockIdx.x * 128, h = blockIdx.y, b = blockIdx.z;
    const size_t qbase = ((size_t)(b * NQ + q0)) * QD + h * HD;
    const size_t kbase = ((size_t)(b * NK)) * QD + h * HD;

    auto ld_stage = [&](int c) {
        const uint32_t sb = smb + (c % 3) * ATS;
        const int n0 = c << 7;
#pragma unroll
        for (int j = 0; j < 4; j++) {
            int u = t + j * 256;
            int row = u >> 3, ch = u & 7;
            uint32_t so = soff64(row, ch);
            size_t g = kbase + (size_t)(n0 + row) * QD + ch * 8;
            cpa16(sb + so, Kp + g);
            cpa16(sb + 16384 + so, Vp + g);
        }
        CP_COMMIT();
    };

    // Q load rides in cp group 0
#pragma unroll
    for (int j = 0; j < 4; j++) {
        int u = t + j * 256;
        int row = u >> 3, ch = u & 7;
        cpa16(smb + AT_Q + soff64(row, ch), Qp + qbase + (size_t)row * QD + ch * 8);
    }
    ld_stage(0); ld_stage(1);

    uint32_t qf[4][4];
    float s[8][4];
    float o[8][4];
    float lsum0 = 0.f, lsum1 = 0.f;
#pragma unroll
    for (int i = 0; i < 8; i++)
#pragma unroll
        for (int j = 0; j < 4; j++) o[i][j] = 0.f;

    for (int c = 0; c < NCH2; c++) {
        if (c < NCH2 - 1) CP_WAIT(1);
        else CP_WAIT(0);
        __syncthreads();
        if (c + 2 < NCH2) ld_stage(c + 2);

        if (c == 0) {
#pragma unroll
            for (int ks = 0; ks < 4; ks++) {
                int row = w * 16 + (lane & 15);
                ldsm4(qf[ks], smb + AT_Q + soff64(row, ks * 2 + (lane >> 4)));
            }
        }
        const uint32_t sb = smb + (c % 3) * ATS;

#pragma unroll
        for (int hf = 0; hf < 2; hf++) {
            const int r0 = hf * 64;
            // ---- S = Q K^T over 64 kv (logits in log2 domain) ----
#pragma unroll
            for (int sn = 0; sn < 8; sn++) {
                s[sn][0] = 0.f; s[sn][1] = 0.f; s[sn][2] = 0.f; s[sn][3] = 0.f;
            }
#pragma unroll
            for (int ks = 0; ks < 4; ks++) {
#pragma unroll
                for (int p = 0; p < 4; p++) {
                    int nrow = r0 + p * 16 + ((lane >> 4) & 1) * 8 + (lane & 7);
                    int ch = ks * 2 + ((lane >> 3) & 1);
                    uint32_t kf[4];
                    ldsm4(kf, sb + soff64(nrow, ch));
                    uint32_t b0[2] = {kf[0], kf[1]}, b1[2] = {kf[2], kf[3]};
                    mma_fp(s[2*p],   qf[ks], b0);
                    mma_fp(s[2*p+1], qf[ks], b1);
                }
            }
            // ---- exp2 (MUFU), pack P fp16, PV mma ----
#pragma unroll
            for (int kk = 0; kk < 4; kk++) {
                float* e0 = s[2*kk];
                float* e1 = s[2*kk+1];
#pragma unroll
                for (int j = 0; j < 4; j++) { e0[j] = fexp2(e0[j]); e1[j] = fexp2(e1[j]); }
                lsum0 += e0[0] + e0[1] + e1[0] + e1[1];
                lsum1 += e0[2] + e0[3] + e1[2] + e1[3];
                uint32_t ph[4];
                ph[0] = packh(e0[1], e0[0]); ph[1] = packh(e0[3], e0[2]);
                ph[2] = packh(e1[1], e1[0]); ph[3] = packh(e1[3], e1[2]);
#pragma unroll
                for (int q = 0; q < 4; q++) {
                    int row = r0 + kk * 16 + (lane & 15);
                    int ch = q * 2 + (lane >> 4);
                    uint32_t vf[4];
                    ldsm4t(vf, sb + 16384 + soff64(row, ch));
                    uint32_t b0[2] = {vf[0], vf[1]}, b1[2] = {vf[2], vf[3]};
                    mma_fp(o[2*q],   ph, b0);
                    mma_fp(o[2*q+1], ph, b1);
                }
            }
        }
    }

    lsum0 += __shfl_xor_sync(0xffffffffu, lsum0, 1);
    lsum0 += __shfl_xor_sync(0xffffffffu, lsum0, 2);
    lsum1 += __shfl_xor_sync(0xffffffffu, lsum1, 1);
    lsum1 += __shfl_xor_sync(0xffffffffu, lsum1, 2);
    const float inv0 = 1.f / lsum0, inv1 = 1.f / lsum1;

    const int row0 = q0 + w * 16 + (lane >> 2);
#pragma unroll
    for (int nt = 0; nt < 8; nt++) {
        int col = h * HD + nt * 8 + (lane & 3) * 2;
        *(uint32_t*)&AO[((size_t)(b * NQ + row0)) * QD + col] =
            packh(o[nt][1] * inv0, o[nt][0] * inv0);
        *(uint32_t*)&AO[((size_t)(b * NQ + row0 + 8)) * QD + col] =
            packh(o[nt][3] * inv1, o[nt][2] * inv1);
    }
}

// ============ kernel_launch ============
extern "C" void kernel_launch(void* const* d_in, const int* in_sizes, int n_in,
                              void* d_out, int out_size)
{
    const float* query = (const float*)d_in[0];
    const float* key   = (const float*)d_in[1];
    const float* value = (const float*)d_in[2];
    const float* Wq = (const float*)d_in[3];  const float* bq = (const float*)d_in[4];
    const float* Wk = (const float*)d_in[5];  const float* bk = (const float*)d_in[6];
    const float* Wv = (const float*)d_in[7];  const float* bv = (const float*)d_in[8];
    const float* Wo = (const float*)d_in[9];  const float* bo = (const float*)d_in[10];
    float* out = (float*)d_out;

    __half *q16,*k16,*v16,*wq16,*wk16,*wv16,*wo16,*Qp,*Kp,*Vp,*ao16;
    cudaGetSymbolAddress((void**)&q16, g_q16);   cudaGetSymbolAddress((void**)&k16, g_k16);
    cudaGetSymbolAddress((void**)&v16, g_v16);
    cudaGetSymbolAddress((void**)&wq16, g_wq16); cudaGetSymbolAddress((void**)&wk16, g_wk16);
    cudaGetSymbolAddress((void**)&wv16, g_wv16); cudaGetSymbolAddress((void**)&wo16, g_wo16);
    cudaGetSymbolAddress((void**)&Qp, g_Qp);     cudaGetSymbolAddress((void**)&Kp, g_Kp);
    cudaGetSymbolAddress((void**)&Vp, g_Vp);     cudaGetSymbolAddress((void**)&ao16, g_AO16);

    cudaFuncSetAttribute(gemm_f16, cudaFuncAttributeMaxDynamicSharedMemorySize, F1_SMEM);
    cudaFuncSetAttribute(attn_tc,  cudaFuncAttributeMaxDynamicSharedMemorySize, ATTN_SMEM);

    const int MQ = BATCH * NQ;   // 16384
    const int MK = BATCH * NK;   // 4096

    // launch 0-1: converts
    conv_in<<<dim3(MQ*QD/4/256, 1, 3), 256>>>(query, key, value);
    wconv_all<<<dim3(QD/32, QD/32, 4), 256>>>(Wq, Wk, Wv, Wo);
    // launches 2-4: projections (fp16 single product; Q scaled by SCALE*log2e)
    gemm_f16<<<dim3(QD/128, MQ/128), 256, F1_SMEM>>>(
        q16, wq16, bq, nullptr, Qp, QSCALE, MQ, QD, QD);
    gemm_f16<<<dim3(QD/128, MK/128), 256, F1_SMEM>>>(
        k16, wk16, bk, nullptr, Kp, 1.0f, MK, QD, KD);
    gemm_f16<<<dim3(QD/128, MK/128), 256, F1_SMEM>>>(
        v16, wv16, bv, nullptr, Vp, 1.0f, MK, QD, KD);
    // launch 5: attention (ncu -s 5 -c 1 captures this)
    attn_tc<<<dim3(NQ/128, NH, BATCH), 256, ATTN_SMEM>>>(Qp, Kp, Vp, ao16);
    // launch 6: O proj -> fp32 d_out
    gemm_f16<<<dim3(QD/128, MQ/128), 256, F1_SMEM>>>(
        ao16, wo16, bo, out, nullptr, 1.0f, MQ, QD, QD);
}

// round 12
// speedup vs baseline: 22.0841x; 1.0463x over previous
#include <cuda_runtime.h>
#include <cuda_fp16.h>
#include <cstdint>

#define BATCH 4
#define NQ    4096
#define NK    1024
#define NH    16
#define HD    64
#define QD    1024
#define KD    768
#define QSCALE 0.1803368801f   // 0.125 * log2(e), folded into Q proj epilogue

// ---------------- helpers ----------------
__device__ __forceinline__ uint32_t smem_u32(const void* p) {
    uint32_t a;
    asm("{ .reg .u64 t; cvta.to.shared.u64 t, %1; cvt.u32.u64 %0, t; }" : "=r"(a) : "l"(p));
    return a;
}
__device__ __forceinline__ void cpa16(uint32_t s, const void* g) {
    asm volatile("cp.async.cg.shared.global [%0], [%1], 16;" :: "r"(s), "l"(g));
}
#define CP_COMMIT() asm volatile("cp.async.commit_group;" ::: "memory")
#define CP_WAIT(n)  asm volatile("cp.async.wait_group %0;" :: "n"(n) : "memory")
__device__ __forceinline__ void ldsm4(uint32_t* r, uint32_t a) {
    asm volatile("ldmatrix.sync.aligned.m8n8.x4.shared.b16 {%0,%1,%2,%3}, [%4];"
        : "=r"(r[0]), "=r"(r[1]), "=r"(r[2]), "=r"(r[3]) : "r"(a));
}
__device__ __forceinline__ void ldsm4t(uint32_t* r, uint32_t a) {
    asm volatile("ldmatrix.sync.aligned.m8n8.x4.trans.shared.b16 {%0,%1,%2,%3}, [%4];"
        : "=r"(r[0]), "=r"(r[1]), "=r"(r[2]), "=r"(r[3]) : "r"(a));
}
__device__ __forceinline__ void mma_fp(float* d, const uint32_t* a, const uint32_t* b) {
    asm volatile("mma.sync.aligned.m16n8k16.row.col.f32.f16.f16.f32 "
        "{%0,%1,%2,%3}, {%4,%5,%6,%7}, {%8,%9}, {%0,%1,%2,%3};"
        : "+f"(d[0]), "+f"(d[1]), "+f"(d[2]), "+f"(d[3])
        : "r"(a[0]), "r"(a[1]), "r"(a[2]), "r"(a[3]), "r"(b[0]), "r"(b[1]));
}
__device__ __forceinline__ uint32_t packh(float hi, float lo) {
    uint32_t r;
    asm("cvt.rn.f16x2.f32 %0, %1, %2;" : "=r"(r) : "f"(hi), "f"(lo));
    return r;
}
// swizzled offset in [rows][64]halfwords (128B rows, 8 chunks of 16B)
__device__ __forceinline__ uint32_t soff64(int row, int ch) {
    return (uint32_t)(row * 128 + ((ch ^ (row & 7)) << 4));
}
// 2^z via MUFU
__device__ __forceinline__ float fexp2(float z) {
    float r;
    asm("ex2.approx.f32 %0, %1;" : "=f"(r) : "f"(z));
    return r;
}

// ---------------- scratch (all fp16 single) ----------------
#define AL16 __align__(16)
__device__ AL16 __half g_q16[(size_t)BATCH*NQ*QD];
__device__ AL16 __half g_k16[(size_t)BATCH*NK*KD];
__device__ AL16 __half g_v16[(size_t)BATCH*NK*KD];
__device__ AL16 __half g_wq16[(size_t)QD*QD], g_wo16[(size_t)QD*QD];
__device__ AL16 __half g_wk16[(size_t)QD*KD], g_wv16[(size_t)QD*KD];
__device__ AL16 __half g_Qp[(size_t)BATCH*NQ*QD];
__device__ AL16 __half g_Kp[(size_t)BATCH*NK*QD];
__device__ AL16 __half g_Vp[(size_t)BATCH*NK*QD];
__device__ AL16 __half g_AO16[(size_t)BATCH*NQ*QD];

// ============ fused input convert: q/k/v fp32 -> fp16 ============
__global__ __launch_bounds__(256) void conv_in(
    const float* __restrict__ q, const float* __restrict__ k, const float* __restrict__ v)
{
    int z = blockIdx.z;
    const float* x = (z == 0) ? q : (z == 1) ? k : v;
    __half* dst = (z == 0) ? g_q16 : (z == 1) ? g_k16 : g_v16;
    int n4 = (z == 0) ? BATCH*NQ*QD/4 : BATCH*NK*KD/4;
    int i = blockIdx.x * 256 + threadIdx.x;
    if (i >= n4) return;
    float4 val = ((const float4*)x)[i];
    ((uint32_t*)dst)[2*i]   = packh(val.y, val.x);
    ((uint32_t*)dst)[2*i+1] = packh(val.w, val.z);
}

// ============ fused weight transpose+convert: W[K,N] -> [N,K] fp16 ============
__global__ __launch_bounds__(256) void wconv_all(
    const float* __restrict__ Wq, const float* __restrict__ Wk,
    const float* __restrict__ Wv, const float* __restrict__ Wo)
{
    int z = blockIdx.z;
    const float* W; __half* T; int K = QD;
    if (z == 0)      { W = Wq; T = g_wq16; }
    else if (z == 1) { W = Wk; T = g_wk16; K = KD; }
    else if (z == 2) { W = Wv; T = g_wv16; K = KD; }
    else             { W = Wo; T = g_wo16; }
    const int N = QD;
    const int nb = blockIdx.x * 32, kb = blockIdx.y * 32;
    if (kb >= K) return;
    __shared__ float tile[32][33];
    const int tx = threadIdx.x & 31, tg = threadIdx.x >> 5;
#pragma unroll
    for (int r = 0; r < 4; r++) {
        int kk = tg + r * 8;
        tile[kk][tx] = W[(size_t)(kb + kk) * N + nb + tx];
    }
    __syncthreads();
#pragma unroll
    for (int r = 0; r < 4; r++) {
        int n = tg + r * 8;
        T[(size_t)(nb + n) * K + kb + tx] = __float2half_rn(tile[tx][n]);
    }
}

// ============ fp16 GEMM body: 128x128 CTA tile, 4 warps (64x64 each), ============
// ============ K-chunk 64, 3-stage cp.async pipeline, 1 bar/chunk     ============
#define F1_A 0
#define F1_B 16384
#define F1_STG 32768
#define F1_SMEM (3 * F1_STG)   // 96 KB

__device__ __forceinline__ void gemm_body(
    const __half* __restrict__ A, const __half* __restrict__ B,
    const float* __restrict__ bias, float* __restrict__ Cf,
    __half* __restrict__ C16, float scale,
    int m0, int n0, int K, int N, uint32_t smb)
{
    const int t = threadIdx.x, wid = t >> 5, lane = t & 31;
    const int NC = K >> 6;
    const int wm = (wid & 1) * 64, wn = (wid >> 1) * 64;

    auto load_stage = [&](int c) {
        const int kt = c << 6;
        const uint32_t sb = smb + (c % 3) * F1_STG;
#pragma unroll
        for (int j = 0; j < 8; j++) {
            int u = t + j * 128;
            int row = u >> 3, ch = u & 7;
            uint32_t so = soff64(row, ch);
            cpa16(sb + F1_A + so, A + (size_t)(m0 + row) * K + kt + ch * 8);
            cpa16(sb + F1_B + so, B + (size_t)(n0 + row) * K + kt + ch * 8);
        }
        CP_COMMIT();
    };

    float d[4][8][4];
#pragma unroll
    for (int i = 0; i < 4; i++)
#pragma unroll
        for (int j = 0; j < 8; j++)
#pragma unroll
            for (int k = 0; k < 4; k++) d[i][j][k] = 0.f;

    load_stage(0); load_stage(1);

    for (int c = 0; c < NC; c++) {
        if (c < NC - 1) CP_WAIT(1);
        else CP_WAIT(0);
        __syncthreads();
        if (c + 2 < NC) load_stage(c + 2);

        const uint32_t sb = smb + (c % 3) * F1_STG;
#pragma unroll
        for (int ks = 0; ks < 4; ks++) {
            uint32_t af[4][4];
#pragma unroll
            for (int mt = 0; mt < 4; mt++) {
                int row = wm + mt * 16 + (lane & 15);
                int ch = ks * 2 + (lane >> 4);
                ldsm4(af[mt], sb + F1_A + soff64(row, ch));
            }
            uint32_t bf[8][2];
#pragma unroll
            for (int p = 0; p < 4; p++) {
                int nrow = wn + p * 16 + ((lane >> 4) & 1) * 8 + (lane & 7);
                int ch = ks * 2 + ((lane >> 3) & 1);
                uint32_t r[4];
                ldsm4(r, sb + F1_B + soff64(nrow, ch));
                bf[p*2][0] = r[0]; bf[p*2][1] = r[1];
                bf[p*2+1][0] = r[2]; bf[p*2+1][1] = r[3];
            }
#pragma unroll
            for (int mt = 0; mt < 4; mt++)
#pragma unroll
                for (int nt = 0; nt < 8; nt++)
                    mma_fp(d[mt][nt], af[mt], bf[nt]);
        }
    }

    const int lr = lane >> 2, lc = (lane & 3) * 2;
#pragma unroll
    for (int mt = 0; mt < 4; mt++) {
        int row = m0 + wm + mt * 16 + lr;
#pragma unroll
        for (int nt = 0; nt < 8; nt++) {
            int col = n0 + wn + nt * 8 + lc;
            float b0 = __ldg(bias + col), b1 = __ldg(bias + col + 1);
            float v0 = (d[mt][nt][0] + b0) * scale, v1 = (d[mt][nt][1] + b1) * scale;
            float v2 = (d[mt][nt][2] + b0) * scale, v3 = (d[mt][nt][3] + b1) * scale;
            if (Cf) {
                *(float2*)&Cf[(size_t)row * N + col] = make_float2(v0, v1);
                *(float2*)&Cf[(size_t)(row + 8) * N + col] = make_float2(v2, v3);
            } else {
                *(uint32_t*)&C16[(size_t)row * N + col] = packh(v1, v0);
                *(uint32_t*)&C16[(size_t)(row + 8) * N + col] = packh(v3, v2);
            }
        }
    }
}

// ============ mega-launch: Q/K/V projections in one grid (1536 CTAs) ============
__global__ __launch_bounds__(128, 2) void gemm_qkv(
    const __half* __restrict__ q16, const __half* __restrict__ k16,
    const __half* __restrict__ v16,
    const __half* __restrict__ wq, const __half* __restrict__ wk,
    const __half* __restrict__ wv,
    const float* __restrict__ bq, const float* __restrict__ bk,
    const float* __restrict__ bv,
    __half* __restrict__ Qp, __half* __restrict__ Kp, __half* __restrict__ Vp)
{
    extern __shared__ char sm[];
    const uint32_t smb = smem_u32(sm);
    const int bid = blockIdx.x;
    const __half *A, *B; const float* bias; __half* C;
    float scale; int K, m0, n0;
    if (bid < 1024) {                      // Q proj: 128x8 tiles, M=16384, K=1024
        A = q16; B = wq; bias = bq; C = Qp; scale = QSCALE; K = QD;
        m0 = (bid >> 3) * 128; n0 = (bid & 7) * 128;
    } else if (bid < 1280) {               // K proj: 32x8 tiles, M=4096, K=768
        int r = bid - 1024;
        A = k16; B = wk; bias = bk; C = Kp; scale = 1.0f; K = KD;
        m0 = (r >> 3) * 128; n0 = (r & 7) * 128;
    } else {                               // V proj
        int r = bid - 1280;
        A = v16; B = wv; bias = bv; C = Vp; scale = 1.0f; K = KD;
        m0 = (r >> 3) * 128; n0 = (r & 7) * 128;
    }
    gemm_body(A, B, bias, nullptr, C, scale, m0, n0, K, QD, smb);
}

// ============ O projection -> fp32 d_out ============
__global__ __launch_bounds__(128, 2) void gemm_o(
    const __half* __restrict__ A, const __half* __restrict__ B,
    const float* __restrict__ bias, float* __restrict__ out)
{
    extern __shared__ char sm[];
    gemm_body(A, B, bias, out, nullptr, 1.0f,
              blockIdx.y * 128, blockIdx.x * 128, QD, QD, smem_u32(sm));
}

// ============ tensor-core flash attention: kv-chunk 128 per barrier, 3-stage ============
#define ATS 32768
#define AT_Q (3 * ATS)
#define ATTN_SMEM (3 * ATS + 16384)   // 112 KB
#define NCH2 (NK / 128)   // 8 chunks

__global__ __launch_bounds__(256, 2) void attn_tc(
    const __half* __restrict__ Qp, const __half* __restrict__ Kp,
    const __half* __restrict__ Vp, __half* __restrict__ AO)
{
    extern __shared__ char sm[];
    const uint32_t smb = smem_u32(sm);
    const int t = threadIdx.x, w = t >> 5, lane = t & 31;
    const int q0 = blockIdx.x * 128, h = blockIdx.y, b = blockIdx.z;
    const size_t qbase = ((size_t)(b * NQ + q0)) * QD + h * HD;
    const size_t kbase = ((size_t)(b * NK)) * QD + h * HD;

    auto ld_stage = [&](int c) {
        const uint32_t sb = smb + (c % 3) * ATS;
        const int n0 = c << 7;
#pragma unroll
        for (int j = 0; j < 4; j++) {
            int u = t + j * 256;
            int row = u >> 3, ch = u & 7;
            uint32_t so = soff64(row, ch);
            size_t g = kbase + (size_t)(n0 + row) * QD + ch * 8;
            cpa16(sb + so, Kp + g);
            cpa16(sb + 16384 + so, Vp + g);
        }
        CP_COMMIT();
    };

    // Q load rides in cp group 0
#pragma unroll
    for (int j = 0; j < 4; j++) {
        int u = t + j * 256;
        int row = u >> 3, ch = u & 7;
        cpa16(smb + AT_Q + soff64(row, ch), Qp + qbase + (size_t)row * QD + ch * 8);
    }
    ld_stage(0); ld_stage(1);

    uint32_t qf[4][4];
    float s[8][4];
    float o[8][4];
    float lsum0 = 0.f, lsum1 = 0.f;
#pragma unroll
    for (int i = 0; i < 8; i++)
#pragma unroll
        for (int j = 0; j < 4; j++) o[i][j] = 0.f;

    for (int c = 0; c < NCH2; c++) {
        if (c < NCH2 - 1) CP_WAIT(1);
        else CP_WAIT(0);
        __syncthreads();
        if (c + 2 < NCH2) ld_stage(c + 2);

        if (c == 0) {
#pragma unroll
            for (int ks = 0; ks < 4; ks++) {
                int row = w * 16 + (lane & 15);
                ldsm4(qf[ks], smb + AT_Q + soff64(row, ks * 2 + (lane >> 4)));
            }
        }
        const uint32_t sb = smb + (c % 3) * ATS;

#pragma unroll
        for (int hf = 0; hf < 2; hf++) {
            const int r0 = hf * 64;
            // ---- S = Q K^T over 64 kv (logits in log2 domain) ----
#pragma unroll
            for (int sn = 0; sn < 8; sn++) {
                s[sn][0] = 0.f; s[sn][1] = 0.f; s[sn][2] = 0.f; s[sn][3] = 0.f;
            }
#pragma unroll
            for (int ks = 0; ks < 4; ks++) {
#pragma unroll
                for (int p = 0; p < 4; p++) {
                    int nrow = r0 + p * 16 + ((lane >> 4) & 1) * 8 + (lane & 7);
                    int ch = ks * 2 + ((lane >> 3) & 1);
                    uint32_t kf[4];
                    ldsm4(kf, sb + soff64(nrow, ch));
                    uint32_t b0[2] = {kf[0], kf[1]}, b1[2] = {kf[2], kf[3]};
                    mma_fp(s[2*p],   qf[ks], b0);
                    mma_fp(s[2*p+1], qf[ks], b1);
                }
            }
            // ---- exp2 (MUFU), pack P fp16, PV mma ----
#pragma unroll
            for (int kk = 0; kk < 4; kk++) {
                float* e0 = s[2*kk];
                float* e1 = s[2*kk+1];
#pragma unroll
                for (int j = 0; j < 4; j++) { e0[j] = fexp2(e0[j]); e1[j] = fexp2(e1[j]); }
                lsum0 += e0[0] + e0[1] + e1[0] + e1[1];
                lsum1 += e0[2] + e0[3] + e1[2] + e1[3];
                uint32_t ph[4];
                ph[0] = packh(e0[1], e0[0]); ph[1] = packh(e0[3], e0[2]);
                ph[2] = packh(e1[1], e1[0]); ph[3] = packh(e1[3], e1[2]);
#pragma unroll
                for (int q = 0; q < 4; q++) {
                    int row = r0 + kk * 16 + (lane & 15);
                    int ch = q * 2 + (lane >> 4);
                    uint32_t vf[4];
                    ldsm4t(vf, sb + 16384 + soff64(row, ch));
                    uint32_t b0[2] = {vf[0], vf[1]}, b1[2] = {vf[2], vf[3]};
                    mma_fp(o[2*q],   ph, b0);
                    mma_fp(o[2*q+1], ph, b1);
                }
            }
        }
    }

    lsum0 += __shfl_xor_sync(0xffffffffu, lsum0, 1);
    lsum0 += __shfl_xor_sync(0xffffffffu, lsum0, 2);
    lsum1 += __shfl_xor_sync(0xffffffffu, lsum1, 1);
    lsum1 += __shfl_xor_sync(0xffffffffu, lsum1, 2);
    const float inv0 = 1.f / lsum0, inv1 = 1.f / lsum1;

    const int row0 = q0 + w * 16 + (lane >> 2);
#pragma unroll
    for (int nt = 0; nt < 8; nt++) {
        int col = h * HD + nt * 8 + (lane & 3) * 2;
        *(uint32_t*)&AO[((size_t)(b * NQ + row0)) * QD + col] =
            packh(o[nt][1] * inv0, o[nt][0] * inv0);
        *(uint32_t*)&AO[((size_t)(b * NQ + row0 + 8)) * QD + col] =
            packh(o[nt][3] * inv1, o[nt][2] * inv1);
    }
}

// ============ kernel_launch ============
extern "C" void kernel_launch(void* const* d_in, const int* in_sizes, int n_in,
                              void* d_out, int out_size)
{
    const float* query = (const float*)d_in[0];
    const float* key   = (const float*)d_in[1];
    const float* value = (const float*)d_in[2];
    const float* Wq = (const float*)d_in[3];  const float* bq = (const float*)d_in[4];
    const float* Wk = (const float*)d_in[5];  const float* bk = (const float*)d_in[6];
    const float* Wv = (const float*)d_in[7];  const float* bv = (const float*)d_in[8];
    const float* Wo = (const float*)d_in[9];  const float* bo = (const float*)d_in[10];
    float* out = (float*)d_out;

    __half *q16,*k16,*v16,*wq16,*wk16,*wv16,*wo16,*Qp,*Kp,*Vp,*ao16;
    cudaGetSymbolAddress((void**)&q16, g_q16);   cudaGetSymbolAddress((void**)&k16, g_k16);
    cudaGetSymbolAddress((void**)&v16, g_v16);
    cudaGetSymbolAddress((void**)&wq16, g_wq16); cudaGetSymbolAddress((void**)&wk16, g_wk16);
    cudaGetSymbolAddress((void**)&wv16, g_wv16); cudaGetSymbolAddress((void**)&wo16, g_wo16);
    cudaGetSymbolAddress((void**)&Qp, g_Qp);     cudaGetSymbolAddress((void**)&Kp, g_Kp);
    cudaGetSymbolAddress((void**)&Vp, g_Vp);     cudaGetSymbolAddress((void**)&ao16, g_AO16);

    cudaFuncSetAttribute(gemm_qkv, cudaFuncAttributeMaxDynamicSharedMemorySize, F1_SMEM);
    cudaFuncSetAttribute(gemm_o,   cudaFuncAttributeMaxDynamicSharedMemorySize, F1_SMEM);
    cudaFuncSetAttribute(attn_tc,  cudaFuncAttributeMaxDynamicSharedMemorySize, ATTN_SMEM);

    const int MQ = BATCH * NQ;   // 16384

    // launch 0-1: converts
    conv_in<<<dim3(MQ*QD/4/256, 1, 3), 256>>>(query, key, value);
    wconv_all<<<dim3(QD/32, QD/32, 4), 256>>>(Wq, Wk, Wv, Wo);
    // launch 2: all three projections in one grid
    gemm_qkv<<<1536, 128, F1_SMEM>>>(q16, k16, v16, wq16, wk16, wv16,
                                     bq, bk, bv, Qp, Kp, Vp);
    // launch 3: attention
    attn_tc<<<dim3(NQ/128, NH, BATCH), 256, ATTN_SMEM>>>(Qp, Kp, Vp, ao16);
    // launch 4: O proj -> fp32 d_out
    gemm_o<<<dim3(QD/128, MQ/128), 128, F1_SMEM>>>(ao16, wo16, bo, out);
}